// round 1
// baseline (speedup 1.0000x reference)
#include <cuda_runtime.h>

#define B_ 8
#define T_ 4096
#define CE 1024
#define HD 64
#define SCALE 0.125f
#define NEGBIG (-1e30f)

// Scratch (device globals: allocation-free per harness rules)
__device__ __align__(16) float g_q[B_ * T_ * HD];
__device__ __align__(16) float g_k[B_ * T_ * HD];
__device__ __align__(16) float g_v[B_ * T_ * HD];
__device__ __align__(16) float g_m[B_ * T_];
__device__ __align__(16) float g_d[B_ * T_];

// Fast FFMA-pipe exp (avoids MUFU rt=8 bottleneck). Args in our use are <= ~10.
// Rel err ~2e-6 on the used range. Returns 0 for x < -87 (covers -inf/NEGBIG).
__device__ __forceinline__ float fast_exp(float x) {
    if (x < -87.0f) return 0.0f;
    float y = x * 1.4426950408889634f;
    float n = rintf(y);
    float f = y - n;
    float p = 1.3333558146e-3f;               // ln2^5/120
    p = fmaf(p, f, 9.6181291076e-3f);         // ln2^4/24
    p = fmaf(p, f, 5.5504108664e-2f);         // ln2^3/6
    p = fmaf(p, f, 2.4022650696e-1f);         // ln2^2/2
    p = fmaf(p, f, 6.9314718056e-1f);         // ln2
    p = fmaf(p, f, 1.0f);
    int e = (int)n;
    return p * __int_as_float((e + 127) << 23);
}

// ---------------------------------------------------------------------------
// Kernel 1: projections.  out[m][n] = sum_c x[m][c] * W[c][n]
// M = B*T = 32768, K = 1024, N = 64.  Tiled: BM=64, BN=64, BK=16, 256 thr,
// 4x4 micro-tile. grid = (512, 3) — blockIdx.y selects {q,k,v}.
// ---------------------------------------------------------------------------
__global__ __launch_bounds__(256) void proj_kernel(
    const float* __restrict__ x,
    const float* __restrict__ Wq, const float* __restrict__ Wk,
    const float* __restrict__ Wv) {
    __shared__ float As[16][68];   // K-major (transposed), padded
    __shared__ float Ws[16][64];

    const float* W = (blockIdx.y == 0) ? Wq : (blockIdx.y == 1) ? Wk : Wv;
    float* Out = (blockIdx.y == 0) ? g_q : (blockIdx.y == 1) ? g_k : g_v;

    int m0 = blockIdx.x * 64;
    int t = threadIdx.x;
    int tr = t >> 4, tc = t & 15;
    int arow = t >> 2, acol = (t & 3) << 2;

    float acc[4][4] = {};
    for (int k0 = 0; k0 < CE; k0 += 16) {
        float4 av = *(const float4*)&x[(size_t)(m0 + arow) * CE + k0 + acol];
        float4 wv = *(const float4*)&W[(size_t)(k0 + tr) * HD + (tc << 2)];
        __syncthreads();
        As[acol + 0][arow] = av.x; As[acol + 1][arow] = av.y;
        As[acol + 2][arow] = av.z; As[acol + 3][arow] = av.w;
        *(float4*)&Ws[tr][tc << 2] = wv;
        __syncthreads();
#pragma unroll
        for (int kk = 0; kk < 16; kk++) {
            float4 a = *(const float4*)&As[kk][tr << 2];
            float4 bv = *(const float4*)&Ws[kk][tc << 2];
            float af[4] = {a.x, a.y, a.z, a.w};
            float bf[4] = {bv.x, bv.y, bv.z, bv.w};
#pragma unroll
            for (int i = 0; i < 4; i++)
#pragma unroll
                for (int j = 0; j < 4; j++)
                    acc[i][j] = fmaf(af[i], bf[j], acc[i][j]);
        }
    }
#pragma unroll
    for (int i = 0; i < 4; i++) {
        *(float4*)&Out[(size_t)(m0 + (tr << 2) + i) * HD + (tc << 2)] =
            make_float4(acc[i][0], acc[i][1], acc[i][2], acc[i][3]);
    }
}

// ---------------------------------------------------------------------------
// Kernel 2: per-KEY-column stats over the query axis (softmax is over axis 1!)
// For each (b, k): m = max_{q>=k} s(q,k), d = sum_{q>=k} exp(s-m), s = q·k/8.
// Block: 256 thr, 128 columns per tile, streams 64-row Q tiles from q=kc..T.
// Each block handles paired column tiles (j, 31-j) for perfect load balance.
// ---------------------------------------------------------------------------
__global__ __launch_bounds__(256) void stats_kernel() {
    __shared__ float Kt[64][128];  // [h][col]
    __shared__ float Qt[64][64];   // [h][q]  (aliased as reduce buffer later)

    int b = blockIdx.y;
    int jp = blockIdx.x;  // 0..15
    int t = threadIdx.x;
    int tr = t >> 4, tc = t & 15;

#pragma unroll 1
    for (int half = 0; half < 2; half++) {
        int kc = (half ? (31 - jp) : jp) << 7;  // column tile base (*128)

        // load K tile transposed
        {
            int col = t >> 1, seg = t & 1;
            const float* src = &g_k[(size_t)(b * T_ + kc + col) * HD + seg * 32];
#pragma unroll
            for (int u = 0; u < 8; u++) {
                float4 v = *(const float4*)&src[u * 4];
                int h0 = seg * 32 + u * 4;
                Kt[h0 + 0][col] = v.x; Kt[h0 + 1][col] = v.y;
                Kt[h0 + 2][col] = v.z; Kt[h0 + 3][col] = v.w;
            }
        }

        float m_run[8], d_run[8];
#pragma unroll
        for (int j = 0; j < 8; j++) { m_run[j] = NEGBIG; d_run[j] = 0.f; }

        int qrow = t >> 2, qseg = t & 3;
        for (int q0 = kc; q0 < T_; q0 += 64) {
            __syncthreads();
            const float* qsrc = &g_q[(size_t)(b * T_ + q0 + qrow) * HD + qseg * 16];
#pragma unroll
            for (int u = 0; u < 4; u++) {
                float4 v = *(const float4*)&qsrc[u * 4];
                int h0 = qseg * 16 + u * 4;
                Qt[h0 + 0][qrow] = v.x; Qt[h0 + 1][qrow] = v.y;
                Qt[h0 + 2][qrow] = v.z; Qt[h0 + 3][qrow] = v.w;
            }
            __syncthreads();

            float acc[4][8] = {};
#pragma unroll 8
            for (int h = 0; h < 64; h++) {
                float4 a = *(const float4*)&Qt[h][tr << 2];
                float4 b0 = *(const float4*)&Kt[h][tc << 3];
                float4 b1 = *(const float4*)&Kt[h][(tc << 3) + 4];
                float af[4] = {a.x, a.y, a.z, a.w};
                float bf[8] = {b0.x, b0.y, b0.z, b0.w, b1.x, b1.y, b1.z, b1.w};
#pragma unroll
                for (int i = 0; i < 4; i++)
#pragma unroll
                    for (int j = 0; j < 8; j++)
                        acc[i][j] = fmaf(af[i], bf[j], acc[i][j]);
            }

            // online (max, sum-exp) update; ~1.25 exps/element
            int qb = q0 + (tr << 2);
#pragma unroll
            for (int j = 0; j < 8; j++) {
                int col = kc + (tc << 3) + j;
                float sv[4];
                float lm = NEGBIG;
#pragma unroll
                for (int i = 0; i < 4; i++) {
                    sv[i] = acc[i][j] * SCALE;
                    if (qb + i >= col) lm = fmaxf(lm, sv[i]);
                }
                if (lm > -8e29f) {
                    float dl = 0.f;
#pragma unroll
                    for (int i = 0; i < 4; i++)
                        if (qb + i >= col) dl += fast_exp(sv[i] - lm);
                    if (lm <= m_run[j]) {
                        d_run[j] += dl * fast_exp(lm - m_run[j]);
                    } else {
                        d_run[j] = d_run[j] * fast_exp(m_run[j] - lm) + dl;
                        m_run[j] = lm;
                    }
                }
            }
        }

        // cross-thread combine: 16 partials per column (alias Qt as buffer)
        __syncthreads();
        float2* red = reinterpret_cast<float2*>(&Qt[0][0]);  // 16*128 float2
#pragma unroll
        for (int j = 0; j < 8; j++)
            red[tr * 128 + (tc << 3) + j] = make_float2(m_run[j], d_run[j]);
        __syncthreads();
        if (t < 128) {
            float m = NEGBIG;
#pragma unroll
            for (int i = 0; i < 16; i++) m = fmaxf(m, red[i * 128 + t].x);
            float d = 0.f;
#pragma unroll
            for (int i = 0; i < 16; i++) {
                float2 r = red[i * 128 + t];
                d += r.y * fast_exp(r.x - m);
            }
            g_m[b * T_ + kc + t] = m;
            g_d[b * T_ + kc + t] = d;
        }
        __syncthreads();
    }
}

// ---------------------------------------------------------------------------
// Kernel 3: output.  out[q][h] = sum_{k<=q} exp(s(q,k)-m[k])/d[k] * v[k][h]
// Flash-style: 64-row Q tile resident; loop key tiles; recompute S; apply
// precomputed column stats; accumulate P@V in registers.
// Paired q-tiles (j, 63-j): every block does exactly 65 key tiles.
// ---------------------------------------------------------------------------
__global__ __launch_bounds__(256) void out_kernel(float* __restrict__ out) {
    __shared__ float Qt[64][64];  // [h][q]
    __shared__ float KP[64][64];  // K tile [h][k], then reused as P tile [q][k]
    __shared__ float Vs[64][64];  // [k][h]

    int b = blockIdx.y;
    int jj = blockIdx.x;  // 0..31
    int t = threadIdx.x;
    int tr = t >> 4, tc = t & 15;
    int lrow = t >> 2, lseg = t & 3;

#pragma unroll 1
    for (int half = 0; half < 2; half++) {
        int qt = half ? (63 - jj) : jj;
        int q0 = qt << 6;

        __syncthreads();
        const float* qsrc = &g_q[(size_t)(b * T_ + q0 + lrow) * HD + lseg * 16];
#pragma unroll
        for (int u = 0; u < 4; u++) {
            float4 v = *(const float4*)&qsrc[u * 4];
            int h0 = lseg * 16 + u * 4;
            Qt[h0 + 0][lrow] = v.x; Qt[h0 + 1][lrow] = v.y;
            Qt[h0 + 2][lrow] = v.z; Qt[h0 + 3][lrow] = v.w;
        }

        float o[4][4] = {};
        for (int kt = 0; kt <= qt; kt++) {
            int k0 = kt << 6;
            __syncthreads();
            // K transposed into KP, V natural into Vs
            const float* ksrc = &g_k[(size_t)(b * T_ + k0 + lrow) * HD + lseg * 16];
#pragma unroll
            for (int u = 0; u < 4; u++) {
                float4 v = *(const float4*)&ksrc[u * 4];
                int h0 = lseg * 16 + u * 4;
                KP[h0 + 0][lrow] = v.x; KP[h0 + 1][lrow] = v.y;
                KP[h0 + 2][lrow] = v.z; KP[h0 + 3][lrow] = v.w;
            }
            const float* vsrc = &g_v[(size_t)(b * T_ + k0 + lrow) * HD + lseg * 16];
#pragma unroll
            for (int u = 0; u < 4; u++)
                *(float4*)&Vs[lrow][lseg * 16 + u * 4] = *(const float4*)&vsrc[u * 4];

            float4 mv = *(const float4*)&g_m[b * T_ + k0 + (tc << 2)];
            float4 dv = *(const float4*)&g_d[b * T_ + k0 + (tc << 2)];
            float mj[4] = {mv.x, mv.y, mv.z, mv.w};
            float idj[4] = {1.f / dv.x, 1.f / dv.y, 1.f / dv.z, 1.f / dv.w};
            __syncthreads();

            // GEMM1: S = Q @ K^T (micro 4x4)
            float s[4][4] = {};
#pragma unroll 8
            for (int h = 0; h < 64; h++) {
                float4 a = *(const float4*)&Qt[h][tr << 2];
                float4 bv = *(const float4*)&KP[h][tc << 2];
                float af[4] = {a.x, a.y, a.z, a.w};
                float bf[4] = {bv.x, bv.y, bv.z, bv.w};
#pragma unroll
                for (int i = 0; i < 4; i++)
#pragma unroll
                    for (int j = 0; j < 4; j++)
                        s[i][j] = fmaf(af[i], bf[j], s[i][j]);
            }
            __syncthreads();  // all reads of K done; KP becomes P

            bool diag = (kt == qt);
#pragma unroll
            for (int i = 0; i < 4; i++) {
                int q = q0 + (tr << 2) + i;
                float p[4];
#pragma unroll
                for (int j = 0; j < 4; j++) {
                    int k = k0 + (tc << 2) + j;
                    float pv = fast_exp(s[i][j] * SCALE - mj[j]) * idj[j];
                    p[j] = (!diag || q >= k) ? pv : 0.f;
                }
                *(float4*)&KP[(tr << 2) + i][tc << 2] =
                    make_float4(p[0], p[1], p[2], p[3]);
            }
            __syncthreads();

            // GEMM2: O += P @ V
#pragma unroll 8
            for (int k = 0; k < 64; k++) {
                float4 bv = *(const float4*)&Vs[k][tc << 2];
                float bf[4] = {bv.x, bv.y, bv.z, bv.w};
#pragma unroll
                for (int i = 0; i < 4; i++) {
                    float a = KP[(tr << 2) + i][k];
#pragma unroll
                    for (int j = 0; j < 4; j++)
                        o[i][j] = fmaf(a, bf[j], o[i][j]);
                }
            }
        }

#pragma unroll
        for (int i = 0; i < 4; i++) {
            *(float4*)&out[(size_t)(b * T_ + q0 + (tr << 2) + i) * HD + (tc << 2)] =
                make_float4(o[i][0], o[i][1], o[i][2], o[i][3]);
        }
    }
}

// ---------------------------------------------------------------------------
// Launch: input order per setup_inputs: x, Wk, Wq, Wv. Output fp32 [8,4096,64].
// ---------------------------------------------------------------------------
extern "C" void kernel_launch(void* const* d_in, const int* in_sizes, int n_in,
                              void* d_out, int out_size) {
    const float* x  = (const float*)d_in[0];
    const float* Wk = (const float*)d_in[1];
    const float* Wq = (const float*)d_in[2];
    const float* Wv = (const float*)d_in[3];
    float* out = (float*)d_out;

    proj_kernel<<<dim3(512, 3), 256>>>(x, Wq, Wk, Wv);
    stats_kernel<<<dim3(16, 8), 256>>>();
    out_kernel<<<dim3(32, 8), 256>>>(out);
}

// round 2
// speedup vs baseline: 1.5470x; 1.5470x over previous
#include <cuda_runtime.h>

#define B_ 8
#define T_ 4096
#define CE 1024
#define HD 64
#define SCALE 0.125f

typedef unsigned long long u64;

// ---- device scratch (allocation-free) ----
__device__ __align__(16) float g_q[B_ * T_ * HD];
__device__ __align__(16) float g_k[B_ * T_ * HD];
__device__ __align__(16) float g_v[B_ * T_ * HD];
__device__ __align__(16) float g_e[(size_t)B_ * T_ * T_];   // exp(scores), causal region only
__device__ __align__(16) float g_dp[B_ * 64 * T_];          // per-(qtile64) column partial sums
__device__ __align__(16) float g_dinv[B_ * T_];

// ---- packed f32x2 helpers (FFMA2: 2x fp32 FMA per issue slot) ----
__device__ __forceinline__ u64 pk2(float x) {
    u64 r; asm("mov.b64 %0,{%1,%1};" : "=l"(r) : "f"(x)); return r;
}
__device__ __forceinline__ void f2(u64& d, u64 a, u64 b) {
    asm("fma.rn.f32x2 %0,%1,%2,%0;" : "+l"(d) : "l"(a), "l"(b));
}
__device__ __forceinline__ float2 up2(u64 v) {
    float2 f; asm("mov.b64 {%0,%1},%2;" : "=f"(f.x), "=f"(f.y) : "l"(v)); return f;
}

// FFMA-pipe exp; args bounded (|x| <~ 25) so no range clamp needed.
__device__ __forceinline__ float fast_exp(float x) {
    float y = x * 1.4426950408889634f;
    float n = rintf(y);
    float f = y - n;
    float p = 1.3333558146e-3f;
    p = fmaf(p, f, 9.6181291076e-3f);
    p = fmaf(p, f, 5.5504108664e-2f);
    p = fmaf(p, f, 2.4022650696e-1f);
    p = fmaf(p, f, 6.9314718056e-1f);
    p = fmaf(p, f, 1.0f);
    return p * __int_as_float(((int)n + 127) << 23);
}

// ---------------------------------------------------------------------------
// Pass 1: fused q/k/v projection. One block: 128 rows x all 192 outputs.
// 384 threads (16 x 24), micro-tile 8x8 packed. x read once (128MB total).
// ---------------------------------------------------------------------------
__global__ __launch_bounds__(384) void proj_kernel(
    const float* __restrict__ x,
    const float* __restrict__ Wq, const float* __restrict__ Wk,
    const float* __restrict__ Wv) {
    __shared__ __align__(16) float As[16][132];   // [k][m], padded
    __shared__ __align__(16) float Ws[16][192];   // [k][n]  (q|k|v cols)

    int t = threadIdx.x;
    int m0 = blockIdx.x << 7;
    int tr = t / 24, tc = t - tr * 24;

    u64 acc[8][4] = {};
    for (int k0 = 0; k0 < CE; k0 += 16) {
        __syncthreads();
        // stage x tile transposed: 512 float4
        {
            int idx = t;
#pragma unroll
            for (int rep = 0; rep < 2; rep++) {
                if (idx < 512) {
                    int m = idx >> 2, kg = (idx & 3) << 2;
                    float4 v = *(const float4*)&x[(size_t)(m0 + m) * CE + k0 + kg];
                    As[kg + 0][m] = v.x; As[kg + 1][m] = v.y;
                    As[kg + 2][m] = v.z; As[kg + 3][m] = v.w;
                }
                idx += 384;
            }
        }
        // stage W slices: 768 float4 (cols 0-63 Wq, 64-127 Wk, 128-191 Wv)
        {
            int idx = t;
#pragma unroll
            for (int rep = 0; rep < 2; rep++) {
                int r = idx / 48, c4 = idx - r * 48;
                const float* W = (c4 < 16) ? Wq : (c4 < 32) ? Wk : Wv;
                int cb = (c4 & 15) << 2;
                *(float4*)&Ws[r][c4 << 2] =
                    *(const float4*)&W[(size_t)(k0 + r) * HD + cb];
                idx += 384;
            }
        }
        __syncthreads();
#pragma unroll
        for (int kk = 0; kk < 16; kk++) {
            float4 a0 = *(const float4*)&As[kk][tr * 8];
            float4 a1 = *(const float4*)&As[kk][tr * 8 + 4];
            ulonglong2 b01 = *(const ulonglong2*)&Ws[kk][tc * 8];
            ulonglong2 b23 = *(const ulonglong2*)&Ws[kk][tc * 8 + 4];
            u64 bb0 = b01.x, bb1 = b01.y, bb2 = b23.x, bb3 = b23.y;
            float av[8] = {a0.x, a0.y, a0.z, a0.w, a1.x, a1.y, a1.z, a1.w};
#pragma unroll
            for (int i = 0; i < 8; i++) {
                u64 aa = pk2(av[i]);
                f2(acc[i][0], aa, bb0); f2(acc[i][1], aa, bb1);
                f2(acc[i][2], aa, bb2); f2(acc[i][3], aa, bb3);
            }
        }
    }
    int cg = tc >> 3;
    float* Out = (cg == 0) ? g_q : (cg == 1) ? g_k : g_v;
    int col = (tc & 7) << 3;
#pragma unroll
    for (int i = 0; i < 8; i++) {
        float2 p0 = up2(acc[i][0]), p1 = up2(acc[i][1]);
        float2 p2 = up2(acc[i][2]), p3 = up2(acc[i][3]);
        float* dst = &Out[(size_t)(m0 + tr * 8 + i) * HD + col];
        *(float4*)dst = make_float4(p0.x, p0.y, p1.x, p1.y);
        *(float4*)(dst + 4) = make_float4(p2.x, p2.y, p3.x, p3.y);
    }
}

// ---------------------------------------------------------------------------
// Pass 2: E = exp(Q.K^T / 8) over causal tiles (64q x 128k), write E to g_e,
// accumulate per-column partial sums into g_dp (deterministic, no atomics).
// grid (kt=32, qt=64, b=8); blocks above the diagonal exit immediately.
// 256 threads (8 x 32), micro 8x4 packed. smem exactly 48KB.
// ---------------------------------------------------------------------------
__global__ __launch_bounds__(256) void score_kernel() {
    __shared__ __align__(16) float Qs[64][64];    // [h][q]
    __shared__ __align__(16) float Ks[64][128];   // [h][k]

    int kt = blockIdx.x, qt = blockIdx.y, b = blockIdx.z;
    if (kt * 128 > qt * 64 + 63) return;
    int q0 = qt << 6, k0 = kt << 7;
    int t = threadIdx.x;

    {   // Q tile transposed
        int q = t >> 2, seg = t & 3;
        const float* src = &g_q[(size_t)(b * T_ + q0 + q) * HD + seg * 16];
#pragma unroll
        for (int u = 0; u < 4; u++) {
            float4 v = *(const float4*)&src[u * 4];
            int h = seg * 16 + u * 4;
            Qs[h + 0][q] = v.x; Qs[h + 1][q] = v.y;
            Qs[h + 2][q] = v.z; Qs[h + 3][q] = v.w;
        }
    }
    {   // K tile transposed
        int k = t >> 1, seg = t & 1;
        const float* src = &g_k[(size_t)(b * T_ + k0 + k) * HD + seg * 32];
#pragma unroll
        for (int u = 0; u < 8; u++) {
            float4 v = *(const float4*)&src[u * 4];
            int h = seg * 32 + u * 4;
            Ks[h + 0][k] = v.x; Ks[h + 1][k] = v.y;
            Ks[h + 2][k] = v.z; Ks[h + 3][k] = v.w;
        }
    }
    __syncthreads();

    int tr = t >> 5, tc = t & 31;   // warp-uniform tr -> broadcast a-loads
    u64 acc[8][2] = {};
#pragma unroll 4
    for (int h = 0; h < 64; h++) {
        float4 a0 = *(const float4*)&Qs[h][tr * 8];
        float4 a1 = *(const float4*)&Qs[h][tr * 8 + 4];
        ulonglong2 bv = *(const ulonglong2*)&Ks[h][tc * 4];
        u64 b0 = bv.x, b1 = bv.y;
        float av[8] = {a0.x, a0.y, a0.z, a0.w, a1.x, a1.y, a1.z, a1.w};
#pragma unroll
        for (int i = 0; i < 8; i++) {
            u64 aa = pk2(av[i]);
            f2(acc[i][0], aa, b0); f2(acc[i][1], aa, b1);
        }
    }

    bool edge = (q0 < k0 + 127);
    float cs0 = 0.f, cs1 = 0.f, cs2 = 0.f, cs3 = 0.f;
    size_t ebase = (size_t)b * T_ * T_ + (size_t)(q0 + tr * 8) * T_ + k0 + tc * 4;
#pragma unroll
    for (int i = 0; i < 8; i++) {
        float2 e0 = up2(acc[i][0]), e1 = up2(acc[i][1]);
        float v0 = fast_exp(e0.x * SCALE);
        float v1 = fast_exp(e0.y * SCALE);
        float v2 = fast_exp(e1.x * SCALE);
        float v3 = fast_exp(e1.y * SCALE);
        if (edge) {
            int q = q0 + tr * 8 + i, kk = k0 + tc * 4;
            if (q < kk + 0) v0 = 0.f;
            if (q < kk + 1) v1 = 0.f;
            if (q < kk + 2) v2 = 0.f;
            if (q < kk + 3) v3 = 0.f;
        }
        *(float4*)&g_e[ebase + (size_t)i * T_] = make_float4(v0, v1, v2, v3);
        cs0 += v0; cs1 += v1; cs2 += v2; cs3 += v3;
    }

    __syncthreads();
    float* buf = &Qs[0][0];   // reuse: 8 x 128 partials
    *(float4*)&buf[tr * 128 + tc * 4] = make_float4(cs0, cs1, cs2, cs3);
    __syncthreads();
    if (t < 128) {
        float s = 0.f;
#pragma unroll
        for (int r = 0; r < 8; r++) s += buf[r * 128 + t];
        g_dp[(size_t)((b << 6) + qt) * T_ + k0 + t] = s;
    }
}

// ---------------------------------------------------------------------------
// Pass 3: d[k] = sum of partials over valid q-tiles; store reciprocal.
// ---------------------------------------------------------------------------
__global__ void dinv_kernel() {
    int i = blockIdx.x * 256 + threadIdx.x;   // 0..32767
    int b = i >> 12, k = i & 4095;
    float s = 0.f;
    for (int qt = (k >> 6); qt < 64; qt++)
        s += g_dp[(size_t)((b << 6) + qt) * T_ + k];
    g_dinv[i] = 1.0f / s;
}

// ---------------------------------------------------------------------------
// Pass 4: O = E @ (V * dinv).  64-row q tiles, k chunks of 64.
// grid (32 paired-qtiles, 8): pair (jj, 63-jj) -> uniform 65 chunks/block.
// 256 threads (16 x 16), micro 4x4 packed. smem 32KB.
// ---------------------------------------------------------------------------
__global__ __launch_bounds__(256) void out_kernel(float* __restrict__ out) {
    __shared__ __align__(16) float Es[64][64];   // [q][k]
    __shared__ __align__(16) float Vs[64][64];   // [k][h] (prescaled by 1/d)

    int jj = blockIdx.x, b = blockIdx.y;
    int t = threadIdx.x;
    int tr = t >> 4, tc = t & 15;

#pragma unroll 1
    for (int half = 0; half < 2; half++) {
        int qt = half ? (63 - jj) : jj;
        int q0 = qt << 6;
        int nk = qt + 1;
        u64 acc[4][2] = {};
        for (int kc = 0; kc < nk; kc++) {
            int k0 = kc << 6;
            __syncthreads();
            {   // E tile (natural layout)
                int q = t >> 2, seg = t & 3;
                const float* src =
                    &g_e[(size_t)b * T_ * T_ + (size_t)(q0 + q) * T_ + k0 + seg * 16];
#pragma unroll
                for (int u = 0; u < 4; u++)
                    *(float4*)&Es[q][seg * 16 + u * 4] = *(const float4*)&src[u * 4];
            }
            {   // V tile prescaled by 1/d
                int k = t >> 2, seg = t & 3;
                float dinv = g_dinv[(b << 12) + k0 + k];
                const float* src = &g_v[(size_t)(b * T_ + k0 + k) * HD + seg * 16];
#pragma unroll
                for (int u = 0; u < 4; u++) {
                    float4 v = *(const float4*)&src[u * 4];
                    v.x *= dinv; v.y *= dinv; v.z *= dinv; v.w *= dinv;
                    *(float4*)&Vs[k][seg * 16 + u * 4] = v;
                }
            }
            __syncthreads();
#pragma unroll 4
            for (int k = 0; k < 64; k++) {
                ulonglong2 bv = *(const ulonglong2*)&Vs[k][tc * 4];
                u64 b0 = bv.x, b1 = bv.y;
#pragma unroll
                for (int i = 0; i < 4; i++) {
                    u64 aa = pk2(Es[tr * 4 + i][k]);
                    f2(acc[i][0], aa, b0); f2(acc[i][1], aa, b1);
                }
            }
        }
#pragma unroll
        for (int i = 0; i < 4; i++) {
            float2 p0 = up2(acc[i][0]), p1 = up2(acc[i][1]);
            *(float4*)&out[(size_t)(b * T_ + q0 + tr * 4 + i) * HD + tc * 4] =
                make_float4(p0.x, p0.y, p1.x, p1.y);
        }
    }
}

// ---------------------------------------------------------------------------
// inputs: x, Wk, Wq, Wv ; output fp32 [8,4096,64]
// ---------------------------------------------------------------------------
extern "C" void kernel_launch(void* const* d_in, const int* in_sizes, int n_in,
                              void* d_out, int out_size) {
    const float* x  = (const float*)d_in[0];
    const float* Wk = (const float*)d_in[1];
    const float* Wq = (const float*)d_in[2];
    const float* Wv = (const float*)d_in[3];
    float* out = (float*)d_out;

    proj_kernel<<<256, 384>>>(x, Wq, Wk, Wv);
    score_kernel<<<dim3(32, 64, 8), 256>>>();
    dinv_kernel<<<128, 256>>>();
    out_kernel<<<dim3(32, 8), 256>>>(out);
}

// round 4
// speedup vs baseline: 1.6955x; 1.0959x over previous
#include <cuda_runtime.h>

#define B_ 8
#define T_ 4096
#define CE 1024
#define HD 64
#define SCALE 0.125f

typedef unsigned long long u64;

// ---- device scratch (allocation-free) ----
__device__ __align__(16) float g_q[B_ * T_ * HD];
__device__ __align__(16) float g_k[B_ * T_ * HD];
__device__ __align__(16) float g_v[B_ * T_ * HD];
__device__ __align__(16) float g_e[(size_t)B_ * T_ * T_];   // exp(scores), causal region
__device__ __align__(16) float g_dp[B_ * 32 * T_];          // per-(128q-tile) column partials
__device__ __align__(16) float g_dinv[B_ * T_];
__device__ __align__(16) float g_op[4 * B_ * T_ * HD];      // k-split output partials

// ---- packed f32x2 helpers ----
__device__ __forceinline__ u64 pk2(float x) {
    u64 r; asm("mov.b64 %0,{%1,%1};" : "=l"(r) : "f"(x)); return r;
}
__device__ __forceinline__ void f2(u64& d, u64 a, u64 b) {
    asm("fma.rn.f32x2 %0,%1,%2,%0;" : "+l"(d) : "l"(a), "l"(b));
}
__device__ __forceinline__ float2 up2(u64 v) {
    float2 f; asm("mov.b64 {%0,%1},%2;" : "=f"(f.x), "=f"(f.y) : "l"(v)); return f;
}

// FFMA-pipe exp; args bounded (|x| <~ 25).
__device__ __forceinline__ float fast_exp(float x) {
    float y = x * 1.4426950408889634f;
    float n = rintf(y);
    float f = y - n;
    float p = 1.3333558146e-3f;
    p = fmaf(p, f, 9.6181291076e-3f);
    p = fmaf(p, f, 5.5504108664e-2f);
    p = fmaf(p, f, 2.4022650696e-1f);
    p = fmaf(p, f, 6.9314718056e-1f);
    p = fmaf(p, f, 1.0f);
    return p * __int_as_float(((int)n + 127) << 23);
}

// ---------------------------------------------------------------------------
// Pass 1: fused q/k/v projection (unchanged; ~balanced FMA/LDS).
// ---------------------------------------------------------------------------
__global__ __launch_bounds__(384) void proj_kernel(
    const float* __restrict__ x,
    const float* __restrict__ Wq, const float* __restrict__ Wk,
    const float* __restrict__ Wv) {
    __shared__ __align__(16) float As[16][132];
    __shared__ __align__(16) float Ws[16][192];

    int t = threadIdx.x;
    int m0 = blockIdx.x << 7;
    int tr = t / 24, tc = t - tr * 24;

    u64 acc[8][4] = {};
    for (int k0 = 0; k0 < CE; k0 += 16) {
        __syncthreads();
        {
            int idx = t;
#pragma unroll
            for (int rep = 0; rep < 2; rep++) {
                if (idx < 512) {
                    int m = idx >> 2, kg = (idx & 3) << 2;
                    float4 v = *(const float4*)&x[(size_t)(m0 + m) * CE + k0 + kg];
                    As[kg + 0][m] = v.x; As[kg + 1][m] = v.y;
                    As[kg + 2][m] = v.z; As[kg + 3][m] = v.w;
                }
                idx += 384;
            }
        }
        {
            int idx = t;
#pragma unroll
            for (int rep = 0; rep < 2; rep++) {
                int r = idx / 48, c4 = idx - r * 48;
                const float* W = (c4 < 16) ? Wq : (c4 < 32) ? Wk : Wv;
                int cb = (c4 & 15) << 2;
                *(float4*)&Ws[r][c4 << 2] =
                    *(const float4*)&W[(size_t)(k0 + r) * HD + cb];
                idx += 384;
            }
        }
        __syncthreads();
#pragma unroll
        for (int kk = 0; kk < 16; kk++) {
            float4 a0 = *(const float4*)&As[kk][tr * 8];
            float4 a1 = *(const float4*)&As[kk][tr * 8 + 4];
            ulonglong2 b01 = *(const ulonglong2*)&Ws[kk][tc * 8];
            ulonglong2 b23 = *(const ulonglong2*)&Ws[kk][tc * 8 + 4];
            u64 bb0 = b01.x, bb1 = b01.y, bb2 = b23.x, bb3 = b23.y;
            float av[8] = {a0.x, a0.y, a0.z, a0.w, a1.x, a1.y, a1.z, a1.w};
#pragma unroll
            for (int i = 0; i < 8; i++) {
                u64 aa = pk2(av[i]);
                f2(acc[i][0], aa, bb0); f2(acc[i][1], aa, bb1);
                f2(acc[i][2], aa, bb2); f2(acc[i][3], aa, bb3);
            }
        }
    }
    int cg = tc >> 3;
    float* Out = (cg == 0) ? g_q : (cg == 1) ? g_k : g_v;
    int col = (tc & 7) << 3;
#pragma unroll
    for (int i = 0; i < 8; i++) {
        float2 p0 = up2(acc[i][0]), p1 = up2(acc[i][1]);
        float2 p2 = up2(acc[i][2]), p3 = up2(acc[i][3]);
        float* dst = &Out[(size_t)(m0 + tr * 8 + i) * HD + col];
        *(float4*)dst = make_float4(p0.x, p0.y, p1.x, p1.y);
        *(float4*)(dst + 4) = make_float4(p2.x, p2.y, p3.x, p3.y);
    }
}

// ---------------------------------------------------------------------------
// Pass 2: E = exp(Q.K^T/8), tile 128q x 128k, 256 thr (16x16), micro 8x8.
// Writes E and per-column partial sums. Dynamic smem 66KB.
// ---------------------------------------------------------------------------
#define QK_PITCH 132
__global__ __launch_bounds__(256) void score_kernel() {
    extern __shared__ __align__(16) float sm[];
    float* Qs = sm;                 // [64 h][132]
    float* Ks = sm + 64 * QK_PITCH; // [64 h][132]

    int kt = blockIdx.x, qt = blockIdx.y, b = blockIdx.z;
    if (kt > qt) return;
    int q0 = qt << 7, k0 = kt << 7;
    int t = threadIdx.x;

#pragma unroll
    for (int u = 0; u < 8; u++) {
        int li = u * 256 + t;          // 0..2047: 128 rows x 16 float4
        int r = li >> 4, fi = li & 15;
        int h = fi << 2;
        float4 v = *(const float4*)&g_q[(size_t)(b * T_ + q0 + r) * HD + h];
        Qs[(h + 0) * QK_PITCH + r] = v.x; Qs[(h + 1) * QK_PITCH + r] = v.y;
        Qs[(h + 2) * QK_PITCH + r] = v.z; Qs[(h + 3) * QK_PITCH + r] = v.w;
        float4 w = *(const float4*)&g_k[(size_t)(b * T_ + k0 + r) * HD + h];
        Ks[(h + 0) * QK_PITCH + r] = w.x; Ks[(h + 1) * QK_PITCH + r] = w.y;
        Ks[(h + 2) * QK_PITCH + r] = w.z; Ks[(h + 3) * QK_PITCH + r] = w.w;
    }
    __syncthreads();

    int tr = t >> 4, tc = t & 15;
    u64 acc[8][4] = {};
#pragma unroll 4
    for (int h = 0; h < 64; h++) {
        float4 a0 = *(const float4*)&Qs[h * QK_PITCH + tr * 8];
        float4 a1 = *(const float4*)&Qs[h * QK_PITCH + tr * 8 + 4];
        ulonglong2 b01 = *(const ulonglong2*)&Ks[h * QK_PITCH + tc * 8];
        ulonglong2 b23 = *(const ulonglong2*)&Ks[h * QK_PITCH + tc * 8 + 4];
        u64 bb0 = b01.x, bb1 = b01.y, bb2 = b23.x, bb3 = b23.y;
        float av[8] = {a0.x, a0.y, a0.z, a0.w, a1.x, a1.y, a1.z, a1.w};
#pragma unroll
        for (int i = 0; i < 8; i++) {
            u64 aa = pk2(av[i]);
            f2(acc[i][0], aa, bb0); f2(acc[i][1], aa, bb1);
            f2(acc[i][2], aa, bb2); f2(acc[i][3], aa, bb3);
        }
    }

    bool diag = (kt == qt);
    float cs[8] = {};
    size_t ebase = (size_t)b * T_ * T_ + (size_t)(q0 + tr * 8) * T_ + k0 + tc * 8;
#pragma unroll
    for (int i = 0; i < 8; i++) {
        float ev[8];
#pragma unroll
        for (int jp = 0; jp < 4; jp++) {
            float2 e = up2(acc[i][jp]);
            ev[jp * 2 + 0] = fast_exp(e.x * SCALE);
            ev[jp * 2 + 1] = fast_exp(e.y * SCALE);
        }
        if (diag) {
            int q = q0 + tr * 8 + i, kk = k0 + tc * 8;
#pragma unroll
            for (int j = 0; j < 8; j++)
                if (q < kk + j) ev[j] = 0.f;
        }
        *(float4*)&g_e[ebase + (size_t)i * T_] =
            make_float4(ev[0], ev[1], ev[2], ev[3]);
        *(float4*)&g_e[ebase + (size_t)i * T_ + 4] =
            make_float4(ev[4], ev[5], ev[6], ev[7]);
#pragma unroll
        for (int j = 0; j < 8; j++) cs[j] += ev[j];
    }

    __syncthreads();
    float* buf = Qs;   // 16 x 128 partials
#pragma unroll
    for (int j = 0; j < 8; j += 4)
        *(float4*)&buf[tr * 128 + tc * 8 + j] =
            make_float4(cs[j], cs[j + 1], cs[j + 2], cs[j + 3]);
    __syncthreads();
    if (t < 128) {
        float s = 0.f;
#pragma unroll
        for (int r = 0; r < 16; r++) s += buf[r * 128 + t];
        g_dp[(size_t)((b << 5) + qt) * T_ + k0 + t] = s;
    }
}

// ---------------------------------------------------------------------------
// Pass 3: d[k] -> reciprocal
// ---------------------------------------------------------------------------
__global__ void dinv_kernel() {
    int i = blockIdx.x * 256 + threadIdx.x;
    int b = i >> 12, k = i & 4095;
    float s = 0.f;
    for (int qt = (k >> 7); qt < 32; qt++)
        s += g_dp[(size_t)((b << 5) + qt) * T_ + k];
    g_dinv[i] = 1.0f / s;
}

// ---------------------------------------------------------------------------
// Pass 4: partial O = E @ (V*dinv) over a k-slice. grid (qt=32, split=4, b=8).
// 128q x 64h tile, 256 thr (16x16), micro 8q x 4h(x2packed). smem 50KB.
// ---------------------------------------------------------------------------
#define E_PITCH 132
#define V_PITCH 68
__global__ __launch_bounds__(256) void out_kernel() {
    extern __shared__ __align__(16) float sm[];
    float* Es = sm;                // [64 k][132 q]
    float* Vs = sm + 64 * E_PITCH; // [64 k][68 h]

    int qt = blockIdx.x, s = blockIdx.y, b = blockIdx.z;
    int q0 = qt << 7;
    int nch = 2 * qt + 2;
    int lo = (s * nch) >> 2, hi = ((s + 1) * nch) >> 2;
    int t = threadIdx.x;
    int tr = t >> 4, tc = t & 15;

    u64 acc[8][2] = {};
    for (int c = lo; c < hi; c++) {
        int k0 = c << 6;
        __syncthreads();
        // stage E transposed: [k][q]  (128 q-rows x 16 float4 of k)
#pragma unroll
        for (int u = 0; u < 8; u++) {
            int li = u * 256 + t;
            int q = li >> 4, fi = li & 15;
            int k = fi << 2;
            float4 v = *(const float4*)
                &g_e[(size_t)b * T_ * T_ + (size_t)(q0 + q) * T_ + k0 + k];
            Es[(k + 0) * E_PITCH + q] = v.x; Es[(k + 1) * E_PITCH + q] = v.y;
            Es[(k + 2) * E_PITCH + q] = v.z; Es[(k + 3) * E_PITCH + q] = v.w;
        }
        // stage V prescaled by dinv (64 k-rows x 16 float4 of h)
#pragma unroll
        for (int u = 0; u < 4; u++) {
            int li = u * 256 + t;          // 0..1023
            int k = li >> 4, fi = li & 15; // k 0..63, fi 0..15
            float dinv = g_dinv[(b << 12) + k0 + k];
            float4 v = *(const float4*)
                &g_v[(size_t)(b * T_ + k0 + k) * HD + (fi << 2)];
            v.x *= dinv; v.y *= dinv; v.z *= dinv; v.w *= dinv;
            *(float4*)&Vs[k * V_PITCH + (fi << 2)] = v;
        }
        __syncthreads();
#pragma unroll 4
        for (int k = 0; k < 64; k++) {
            float4 a0 = *(const float4*)&Es[k * E_PITCH + tr * 8];
            float4 a1 = *(const float4*)&Es[k * E_PITCH + tr * 8 + 4];
            ulonglong2 bv = *(const ulonglong2*)&Vs[k * V_PITCH + tc * 4];
            u64 b0 = bv.x, b1 = bv.y;
            float av[8] = {a0.x, a0.y, a0.z, a0.w, a1.x, a1.y, a1.z, a1.w};
#pragma unroll
            for (int i = 0; i < 8; i++) {
                u64 aa = pk2(av[i]);
                f2(acc[i][0], aa, b0); f2(acc[i][1], aa, b1);
            }
        }
    }
#pragma unroll
    for (int i = 0; i < 8; i++) {
        float2 p0 = up2(acc[i][0]), p1 = up2(acc[i][1]);
        *(float4*)&g_op[(size_t)(((s * B_ + b) * T_) + q0 + tr * 8 + i) * HD + tc * 4] =
            make_float4(p0.x, p0.y, p1.x, p1.y);
    }
}

// ---------------------------------------------------------------------------
// Pass 5: out = sum of 4 split partials (deterministic)
// ---------------------------------------------------------------------------
__global__ void reduce_kernel(float* __restrict__ out) {
    const int N4 = B_ * T_ * HD / 4;  // 524288
    int i = blockIdx.x * 256 + threadIdx.x;
    const float4* p = (const float4*)g_op;
    float4 a = p[i], b = p[i + N4], c = p[i + 2 * N4], d = p[i + 3 * N4];
    ((float4*)out)[i] = make_float4(a.x + b.x + c.x + d.x,
                                    a.y + b.y + c.y + d.y,
                                    a.z + b.z + c.z + d.z,
                                    a.w + b.w + c.w + d.w);
}

// ---------------------------------------------------------------------------
// inputs: x, Wk, Wq, Wv ; output fp32 [8,4096,64]
// ---------------------------------------------------------------------------
extern "C" void kernel_launch(void* const* d_in, const int* in_sizes, int n_in,
                              void* d_out, int out_size) {
    const float* x  = (const float*)d_in[0];
    const float* Wk = (const float*)d_in[1];
    const float* Wq = (const float*)d_in[2];
    const float* Wv = (const float*)d_in[3];
    float* out = (float*)d_out;

    // idempotent, not a stream op: safe under graph capture, no static guard
    cudaFuncSetAttribute(score_kernel,
        cudaFuncAttributeMaxDynamicSharedMemorySize, 2 * 64 * QK_PITCH * 4);
    cudaFuncSetAttribute(out_kernel,
        cudaFuncAttributeMaxDynamicSharedMemorySize,
        (64 * E_PITCH + 64 * V_PITCH) * 4);

    proj_kernel<<<256, 384>>>(x, Wq, Wk, Wv);
    score_kernel<<<dim3(32, 32, 8), 256, 2 * 64 * QK_PITCH * 4>>>();
    dinv_kernel<<<128, 256>>>();
    out_kernel<<<dim3(32, 4, 8), 256, (64 * E_PITCH + 64 * V_PITCH) * 4>>>();
    reduce_kernel<<<2048, 256>>>(out);
}

// round 7
// speedup vs baseline: 1.8438x; 1.0875x over previous
#include <cuda_runtime.h>
#include <cuda_bf16.h>
#include <cstdint>

#define B_ 8
#define T_ 4096
#define CE 1024
#define HD 64
#define SCALE 0.125f

typedef unsigned long long u64;
typedef unsigned int u32;

// ---- device scratch (allocation-free) ----
__device__ __align__(16) float g_q[B_ * T_ * HD];
__device__ __align__(16) float g_k[B_ * T_ * HD];
__device__ __align__(16) float g_v[B_ * T_ * HD];
__device__ __align__(16) __nv_bfloat16 g_qh[B_ * T_ * HD];
__device__ __align__(16) __nv_bfloat16 g_ql[B_ * T_ * HD];
__device__ __align__(16) __nv_bfloat16 g_kh[B_ * T_ * HD];
__device__ __align__(16) __nv_bfloat16 g_kl[B_ * T_ * HD];
__device__ __align__(16) float g_e[(size_t)B_ * T_ * T_];
__device__ __align__(16) float g_dp[B_ * 32 * T_];
__device__ __align__(16) float g_dinv[B_ * T_];
__device__ __align__(16) float g_op[4 * B_ * T_ * HD];

// ---- packed f32x2 helpers ----
__device__ __forceinline__ u64 pk2(float x) {
    u64 r; asm("mov.b64 %0,{%1,%1};" : "=l"(r) : "f"(x)); return r;
}
__device__ __forceinline__ void f2(u64& d, u64 a, u64 b) {
    asm("fma.rn.f32x2 %0,%1,%2,%0;" : "+l"(d) : "l"(a), "l"(b));
}
__device__ __forceinline__ float2 up2(u64 v) {
    float2 f; asm("mov.b64 {%0,%1},%2;" : "=f"(f.x), "=f"(f.y) : "l"(v)); return f;
}

__device__ __forceinline__ float fast_exp(float x) {
    float y = x * 1.4426950408889634f;
    float n = rintf(y);
    float f = y - n;
    float p = 1.3333558146e-3f;
    p = fmaf(p, f, 9.6181291076e-3f);
    p = fmaf(p, f, 5.5504108664e-2f);
    p = fmaf(p, f, 2.4022650696e-1f);
    p = fmaf(p, f, 6.9314718056e-1f);
    p = fmaf(p, f, 1.0f);
    return p * __int_as_float(((int)n + 127) << 23);
}

// ---- warp MMA helpers (arch-portable: sm_80+) ----
__device__ __forceinline__ u32 s2u(const void* p) {
    u32 a;
    asm("{ .reg .u64 t; cvta.to.shared.u64 t, %1; cvt.u32.u64 %0, t; }"
        : "=r"(a) : "l"(p));
    return a;
}
__device__ __forceinline__ void ldsm4(u32* r, u32 addr) {
    asm volatile("ldmatrix.sync.aligned.m8n8.x4.shared.b16 {%0,%1,%2,%3}, [%4];"
                 : "=r"(r[0]), "=r"(r[1]), "=r"(r[2]), "=r"(r[3]) : "r"(addr));
}
__device__ __forceinline__ void mma16816(float* d, const u32* a, const u32* b) {
    asm volatile(
        "mma.sync.aligned.m16n8k16.row.col.f32.bf16.bf16.f32 "
        "{%0,%1,%2,%3}, {%4,%5,%6,%7}, {%8,%9}, {%0,%1,%2,%3};"
        : "+f"(d[0]), "+f"(d[1]), "+f"(d[2]), "+f"(d[3])
        : "r"(a[0]), "r"(a[1]), "r"(a[2]), "r"(a[3]), "r"(b[0]), "r"(b[1]));
}

// ---------------------------------------------------------------------------
// Pass 1: fused q/k/v projection (proven)
// ---------------------------------------------------------------------------
__global__ __launch_bounds__(384) void proj_kernel(
    const float* __restrict__ x,
    const float* __restrict__ Wq, const float* __restrict__ Wk,
    const float* __restrict__ Wv) {
    __shared__ __align__(16) float As[16][132];
    __shared__ __align__(16) float Ws[16][192];

    int t = threadIdx.x;
    int m0 = blockIdx.x << 7;
    int tr = t / 24, tc = t - tr * 24;

    u64 acc[8][4] = {};
    for (int k0 = 0; k0 < CE; k0 += 16) {
        __syncthreads();
        {
            int idx = t;
#pragma unroll
            for (int rep = 0; rep < 2; rep++) {
                if (idx < 512) {
                    int m = idx >> 2, kg = (idx & 3) << 2;
                    float4 v = *(const float4*)&x[(size_t)(m0 + m) * CE + k0 + kg];
                    As[kg + 0][m] = v.x; As[kg + 1][m] = v.y;
                    As[kg + 2][m] = v.z; As[kg + 3][m] = v.w;
                }
                idx += 384;
            }
        }
        {
            int idx = t;
#pragma unroll
            for (int rep = 0; rep < 2; rep++) {
                int r = idx / 48, c4 = idx - r * 48;
                const float* W = (c4 < 16) ? Wq : (c4 < 32) ? Wk : Wv;
                int cb = (c4 & 15) << 2;
                *(float4*)&Ws[r][c4 << 2] =
                    *(const float4*)&W[(size_t)(k0 + r) * HD + cb];
                idx += 384;
            }
        }
        __syncthreads();
#pragma unroll
        for (int kk = 0; kk < 16; kk++) {
            float4 a0 = *(const float4*)&As[kk][tr * 8];
            float4 a1 = *(const float4*)&As[kk][tr * 8 + 4];
            ulonglong2 b01 = *(const ulonglong2*)&Ws[kk][tc * 8];
            ulonglong2 b23 = *(const ulonglong2*)&Ws[kk][tc * 8 + 4];
            u64 bb0 = b01.x, bb1 = b01.y, bb2 = b23.x, bb3 = b23.y;
            float av[8] = {a0.x, a0.y, a0.z, a0.w, a1.x, a1.y, a1.z, a1.w};
#pragma unroll
            for (int i = 0; i < 8; i++) {
                u64 aa = pk2(av[i]);
                f2(acc[i][0], aa, bb0); f2(acc[i][1], aa, bb1);
                f2(acc[i][2], aa, bb2); f2(acc[i][3], aa, bb3);
            }
        }
    }
    int cg = tc >> 3;
    float* Out = (cg == 0) ? g_q : (cg == 1) ? g_k : g_v;
    int col = (tc & 7) << 3;
#pragma unroll
    for (int i = 0; i < 8; i++) {
        float2 p0 = up2(acc[i][0]), p1 = up2(acc[i][1]);
        float2 p2 = up2(acc[i][2]), p3 = up2(acc[i][3]);
        float* dst = &Out[(size_t)(m0 + tr * 8 + i) * HD + col];
        *(float4*)dst = make_float4(p0.x, p0.y, p1.x, p1.y);
        *(float4*)(dst + 4) = make_float4(p2.x, p2.y, p3.x, p3.y);
    }
}

// ---------------------------------------------------------------------------
// Pass 1b: split q (pre-scaled by 1/8) and k into bf16 hi/lo
// ---------------------------------------------------------------------------
__global__ __launch_bounds__(256) void split_kernel() {
    int i = blockIdx.x * 256 + threadIdx.x;   // float4-groups
    bool isq = (i < 524288);
    int j = isq ? i : i - 524288;
    const float* src = isq ? g_q : g_k;
    float4 v = *(const float4*)&src[(size_t)j * 4];
    if (isq) { v.x *= SCALE; v.y *= SCALE; v.z *= SCALE; v.w *= SCALE; }
    __nv_bfloat16 h0 = __float2bfloat16(v.x), h1 = __float2bfloat16(v.y);
    __nv_bfloat16 h2 = __float2bfloat16(v.z), h3 = __float2bfloat16(v.w);
    __nv_bfloat16 l0 = __float2bfloat16(v.x - __bfloat162float(h0));
    __nv_bfloat16 l1 = __float2bfloat16(v.y - __bfloat162float(h1));
    __nv_bfloat16 l2 = __float2bfloat16(v.z - __bfloat162float(h2));
    __nv_bfloat16 l3 = __float2bfloat16(v.w - __bfloat162float(h3));
    ushort4 hh = make_ushort4(__bfloat16_as_ushort(h0), __bfloat16_as_ushort(h1),
                              __bfloat16_as_ushort(h2), __bfloat16_as_ushort(h3));
    ushort4 ll = make_ushort4(__bfloat16_as_ushort(l0), __bfloat16_as_ushort(l1),
                              __bfloat16_as_ushort(l2), __bfloat16_as_ushort(l3));
    *(ushort4*)&(isq ? g_qh : g_kh)[(size_t)j * 4] = hh;
    *(ushort4*)&(isq ? g_ql : g_kl)[(size_t)j * 4] = ll;
}

// ---------------------------------------------------------------------------
// Pass 2: score via mma.sync bf16x3. 128q x 128k per CTA, 8 warps (4q x 2k).
// B (K tile) is [n][k] row-major == col-major B -> NON-trans ldmatrix.
// ---------------------------------------------------------------------------
#define OQH 0
#define OQL (128 * 144)
#define OKH (2 * 128 * 144)
#define OKL (3 * 128 * 144)
#define OBUF (4 * 128 * 144)        // float[4][128]
#define SMM_TOTAL (OBUF + 4 * 128 * 4)

__global__ __launch_bounds__(256) void score_mma_kernel() {
    extern __shared__ __align__(16) char smem[];
    int kt = blockIdx.x, qt = blockIdx.y, b = blockIdx.z;
    if (kt > qt) return;
    int q0 = qt << 7, k0 = kt << 7;
    int t = threadIdx.x, wid = t >> 5, lane = t & 31;

    // stage 4 tiles: 512 rows of 128B, pitch 144B
    {
        const __nv_bfloat16* gsrc[4] = {
            g_qh + (size_t)(b * T_ + q0) * HD, g_ql + (size_t)(b * T_ + q0) * HD,
            g_kh + (size_t)(b * T_ + k0) * HD, g_kl + (size_t)(b * T_ + k0) * HD};
        const int obase[4] = {OQH, OQL, OKH, OKL};
#pragma unroll
        for (int rep = 0; rep < 2; rep++) {
            int li = rep * 256 + t;
            int a = li >> 7, row = li & 127;
            const uint4* s = (const uint4*)(gsrc[a] + (size_t)row * HD);
            uint4* d = (uint4*)(smem + obase[a] + row * 144);
#pragma unroll
            for (int c = 0; c < 8; c++) d[c] = s[c];
        }
    }
    __syncthreads();

    int qw = wid >> 1, kw = wid & 1;
    u32 sb = s2u(smem);
    float acc[2][8][4] = {};

    const int abase[3] = {OQH, OQH, OQL};
    const int bbase[3] = {OKH, OKL, OKH};
#pragma unroll 1
    for (int p = 0; p < 3; p++) {
        u32 sa = sb + abase[p], sk = bbase[p] + sb;
#pragma unroll
        for (int kk = 0; kk < 4; kk++) {
            u32 afr[2][4];
#pragma unroll
            for (int tq = 0; tq < 2; tq++)
                ldsm4(afr[tq], sa +
                      (u32)((qw * 32 + tq * 16 + (lane & 15)) * 144 +
                            (kk * 16 + ((lane >> 4) << 3)) * 2));
            u32 bfr[4][4];
#pragma unroll
            for (int ng = 0; ng < 4; ng++)
                ldsm4(bfr[ng], sk +
                      (u32)((kw * 64 + ng * 16 + (lane & 7) +
                             ((lane & 16) ? 8 : 0)) * 144 +
                            (kk * 16 + ((lane & 8) ? 8 : 0)) * 2));
#pragma unroll
            for (int tq = 0; tq < 2; tq++)
#pragma unroll
                for (int ng = 0; ng < 4; ng++) {
                    mma16816(acc[tq][ng * 2 + 0], afr[tq], bfr[ng] + 0);
                    mma16816(acc[tq][ng * 2 + 1], afr[tq], bfr[ng] + 2);
                }
        }
    }

    // epilogue: exp + causal mask + E stores + column partial sums
    int g = lane >> 2, tp = (lane & 3) << 1;
    bool diag = (kt == qt);
    float cs[8][2] = {};
#pragma unroll
    for (int tq = 0; tq < 2; tq++) {
        int qrA = q0 + qw * 32 + tq * 16 + g;
        int qrB = qrA + 8;
#pragma unroll
        for (int nt = 0; nt < 8; nt++) {
            int kcol = k0 + kw * 64 + nt * 8 + tp;
            float e0 = fast_exp(acc[tq][nt][0]);
            float e1 = fast_exp(acc[tq][nt][1]);
            float e2 = fast_exp(acc[tq][nt][2]);
            float e3 = fast_exp(acc[tq][nt][3]);
            if (diag) {
                if (qrA < kcol) e0 = 0.f;
                if (qrA < kcol + 1) e1 = 0.f;
                if (qrB < kcol) e2 = 0.f;
                if (qrB < kcol + 1) e3 = 0.f;
            }
            *(float2*)&g_e[((size_t)(b * T_ + qrA)) * T_ + kcol] = make_float2(e0, e1);
            *(float2*)&g_e[((size_t)(b * T_ + qrB)) * T_ + kcol] = make_float2(e2, e3);
            cs[nt][0] += e0 + e2;
            cs[nt][1] += e1 + e3;
        }
    }
    // reduce over g (lanes differing in bits 2..4)
#pragma unroll
    for (int nt = 0; nt < 8; nt++)
#pragma unroll
        for (int j = 0; j < 2; j++) {
            float v = cs[nt][j];
            v += __shfl_xor_sync(0xffffffffu, v, 4);
            v += __shfl_xor_sync(0xffffffffu, v, 8);
            v += __shfl_xor_sync(0xffffffffu, v, 16);
            cs[nt][j] = v;
        }
    float* buf = (float*)(smem + OBUF);
    if (lane < 4) {
#pragma unroll
        for (int nt = 0; nt < 8; nt++) {
            buf[qw * 128 + kw * 64 + nt * 8 + ((lane & 3) << 1) + 0] = cs[nt][0];
            buf[qw * 128 + kw * 64 + nt * 8 + ((lane & 3) << 1) + 1] = cs[nt][1];
        }
    }
    __syncthreads();
    if (t < 128) {
        float s = buf[t] + buf[128 + t] + buf[256 + t] + buf[384 + t];
        g_dp[(size_t)((b << 5) + qt) * T_ + k0 + t] = s;
    }
}

// ---------------------------------------------------------------------------
// Pass 3: d[k] -> reciprocal
// ---------------------------------------------------------------------------
__global__ void dinv_kernel() {
    int i = blockIdx.x * 256 + threadIdx.x;
    int b = i >> 12, k = i & 4095;
    float s = 0.f;
    for (int qt = (k >> 7); qt < 32; qt++)
        s += g_dp[(size_t)((b << 5) + qt) * T_ + k];
    g_dinv[i] = 1.0f / s;
}

// ---------------------------------------------------------------------------
// Pass 4: partial O = E @ (V*dinv) (proven R4 version)
// ---------------------------------------------------------------------------
#define E_PITCH 132
#define V_PITCH 68
__global__ __launch_bounds__(256) void out_kernel() {
    extern __shared__ __align__(16) float sm[];
    float* Es = sm;
    float* Vs = sm + 64 * E_PITCH;

    int qt = blockIdx.x, s = blockIdx.y, b = blockIdx.z;
    int q0 = qt << 7;
    int nch = 2 * qt + 2;
    int lo = (s * nch) >> 2, hi = ((s + 1) * nch) >> 2;
    int t = threadIdx.x;
    int tr = t >> 4, tc = t & 15;

    u64 acc[8][2] = {};
    for (int c = lo; c < hi; c++) {
        int k0 = c << 6;
        __syncthreads();
#pragma unroll
        for (int u = 0; u < 8; u++) {
            int li = u * 256 + t;
            int q = li >> 4, fi = li & 15;
            int k = fi << 2;
            float4 v = *(const float4*)
                &g_e[(size_t)b * T_ * T_ + (size_t)(q0 + q) * T_ + k0 + k];
            Es[(k + 0) * E_PITCH + q] = v.x; Es[(k + 1) * E_PITCH + q] = v.y;
            Es[(k + 2) * E_PITCH + q] = v.z; Es[(k + 3) * E_PITCH + q] = v.w;
        }
#pragma unroll
        for (int u = 0; u < 4; u++) {
            int li = u * 256 + t;
            int k = li >> 4, fi = li & 15;
            float dinv = g_dinv[(b << 12) + k0 + k];
            float4 v = *(const float4*)
                &g_v[(size_t)(b * T_ + k0 + k) * HD + (fi << 2)];
            v.x *= dinv; v.y *= dinv; v.z *= dinv; v.w *= dinv;
            *(float4*)&Vs[k * V_PITCH + (fi << 2)] = v;
        }
        __syncthreads();
#pragma unroll 4
        for (int k = 0; k < 64; k++) {
            float4 a0 = *(const float4*)&Es[k * E_PITCH + tr * 8];
            float4 a1 = *(const float4*)&Es[k * E_PITCH + tr * 8 + 4];
            ulonglong2 bv = *(const ulonglong2*)&Vs[k * V_PITCH + tc * 4];
            u64 b0 = bv.x, b1 = bv.y;
            float av[8] = {a0.x, a0.y, a0.z, a0.w, a1.x, a1.y, a1.z, a1.w};
#pragma unroll
            for (int i = 0; i < 8; i++) {
                u64 aa = pk2(av[i]);
                f2(acc[i][0], aa, b0); f2(acc[i][1], aa, b1);
            }
        }
    }
#pragma unroll
    for (int i = 0; i < 8; i++) {
        float2 p0 = up2(acc[i][0]), p1 = up2(acc[i][1]);
        *(float4*)&g_op[(size_t)(((s * B_ + b) * T_) + q0 + tr * 8 + i) * HD + tc * 4] =
            make_float4(p0.x, p0.y, p1.x, p1.y);
    }
}

// ---------------------------------------------------------------------------
// Pass 5: sum 4 split partials
// ---------------------------------------------------------------------------
__global__ void reduce_kernel(float* __restrict__ out) {
    const int N4 = B_ * T_ * HD / 4;
    int i = blockIdx.x * 256 + threadIdx.x;
    const float4* p = (const float4*)g_op;
    float4 a = p[i], b = p[i + N4], c = p[i + 2 * N4], d = p[i + 3 * N4];
    ((float4*)out)[i] = make_float4(a.x + b.x + c.x + d.x,
                                    a.y + b.y + c.y + d.y,
                                    a.z + b.z + c.z + d.z,
                                    a.w + b.w + c.w + d.w);
}

// ---------------------------------------------------------------------------
// inputs: x, Wk, Wq, Wv ; output fp32 [8,4096,64]
// ---------------------------------------------------------------------------
extern "C" void kernel_launch(void* const* d_in, const int* in_sizes, int n_in,
                              void* d_out, int out_size) {
    const float* x  = (const float*)d_in[0];
    const float* Wk = (const float*)d_in[1];
    const float* Wq = (const float*)d_in[2];
    const float* Wv = (const float*)d_in[3];
    float* out = (float*)d_out;

    cudaFuncSetAttribute(score_mma_kernel,
        cudaFuncAttributeMaxDynamicSharedMemorySize, SMM_TOTAL);
    cudaFuncSetAttribute(out_kernel,
        cudaFuncAttributeMaxDynamicSharedMemorySize,
        (64 * E_PITCH + 64 * V_PITCH) * 4);

    proj_kernel<<<256, 384>>>(x, Wq, Wk, Wv);
    split_kernel<<<4096, 256>>>();
    score_mma_kernel<<<dim3(32, 32, 8), 256, SMM_TOTAL>>>();
    dinv_kernel<<<128, 256>>>();
    out_kernel<<<dim3(32, 4, 8), 256, (64 * E_PITCH + 64 * V_PITCH) * 4>>>();
    reduce_kernel<<<2048, 256>>>(out);
}

// round 9
// speedup vs baseline: 2.2002x; 1.1933x over previous
#include <cuda_runtime.h>
#include <cuda_bf16.h>
#include <cstdint>

#define B_ 8
#define T_ 4096
#define CE 1024
#define HD 64
#define SCALE 0.125f

typedef unsigned long long u64;
typedef unsigned int u32;

// ---- device scratch (allocation-free) ----
__device__ __align__(16) float g_q[B_ * T_ * HD];
__device__ __align__(16) float g_k[B_ * T_ * HD];
__device__ __align__(16) float g_v[B_ * T_ * HD];
__device__ __align__(16) __nv_bfloat16 g_qh[B_ * T_ * HD];
__device__ __align__(16) __nv_bfloat16 g_ql[B_ * T_ * HD];
__device__ __align__(16) __nv_bfloat16 g_kh[B_ * T_ * HD];
__device__ __align__(16) __nv_bfloat16 g_kl[B_ * T_ * HD];
__device__ __align__(16) __nv_bfloat16 g_eh[(size_t)B_ * T_ * T_];  // E hi
__device__ __align__(16) __nv_bfloat16 g_el[(size_t)B_ * T_ * T_];  // E lo
__device__ __align__(16) __nv_bfloat16 g_vth[B_ * HD * T_];         // (V*dinv)^T hi
__device__ __align__(16) __nv_bfloat16 g_vtl[B_ * HD * T_];         // (V*dinv)^T lo
__device__ __align__(16) float g_dp[B_ * 32 * T_];
__device__ __align__(16) float g_dinv[B_ * T_];
__device__ __align__(16) float g_op[4 * B_ * T_ * HD];

// ---- packed f32x2 helpers ----
__device__ __forceinline__ u64 pk2(float x) {
    u64 r; asm("mov.b64 %0,{%1,%1};" : "=l"(r) : "f"(x)); return r;
}
__device__ __forceinline__ void f2(u64& d, u64 a, u64 b) {
    asm("fma.rn.f32x2 %0,%1,%2,%0;" : "+l"(d) : "l"(a), "l"(b));
}
__device__ __forceinline__ float2 up2(u64 v) {
    float2 f; asm("mov.b64 {%0,%1},%2;" : "=f"(f.x), "=f"(f.y) : "l"(v)); return f;
}

__device__ __forceinline__ float fast_exp(float x) {
    float y = x * 1.4426950408889634f;
    float n = rintf(y);
    float f = y - n;
    float p = 1.3333558146e-3f;
    p = fmaf(p, f, 9.6181291076e-3f);
    p = fmaf(p, f, 5.5504108664e-2f);
    p = fmaf(p, f, 2.4022650696e-1f);
    p = fmaf(p, f, 6.9314718056e-1f);
    p = fmaf(p, f, 1.0f);
    return p * __int_as_float(((int)n + 127) << 23);
}

// ---- warp MMA helpers ----
__device__ __forceinline__ u32 s2u(const void* p) {
    u32 a;
    asm("{ .reg .u64 t; cvta.to.shared.u64 t, %1; cvt.u32.u64 %0, t; }"
        : "=r"(a) : "l"(p));
    return a;
}
__device__ __forceinline__ void ldsm4(u32* r, u32 addr) {
    asm volatile("ldmatrix.sync.aligned.m8n8.x4.shared.b16 {%0,%1,%2,%3}, [%4];"
                 : "=r"(r[0]), "=r"(r[1]), "=r"(r[2]), "=r"(r[3]) : "r"(addr));
}
__device__ __forceinline__ void mma16816(float* d, const u32* a, const u32* b) {
    asm volatile(
        "mma.sync.aligned.m16n8k16.row.col.f32.bf16.bf16.f32 "
        "{%0,%1,%2,%3}, {%4,%5,%6,%7}, {%8,%9}, {%0,%1,%2,%3};"
        : "+f"(d[0]), "+f"(d[1]), "+f"(d[2]), "+f"(d[3])
        : "r"(a[0]), "r"(a[1]), "r"(a[2]), "r"(a[3]), "r"(b[0]), "r"(b[1]));
}

// ---------------------------------------------------------------------------
// Pass 1: fused q/k/v projection (proven FFMA2)
// ---------------------------------------------------------------------------
__global__ __launch_bounds__(384) void proj_kernel(
    const float* __restrict__ x,
    const float* __restrict__ Wq, const float* __restrict__ Wk,
    const float* __restrict__ Wv) {
    __shared__ __align__(16) float As[16][132];
    __shared__ __align__(16) float Ws[16][192];

    int t = threadIdx.x;
    int m0 = blockIdx.x << 7;
    int tr = t / 24, tc = t - tr * 24;

    u64 acc[8][4] = {};
    for (int k0 = 0; k0 < CE; k0 += 16) {
        __syncthreads();
        {
            int idx = t;
#pragma unroll
            for (int rep = 0; rep < 2; rep++) {
                if (idx < 512) {
                    int m = idx >> 2, kg = (idx & 3) << 2;
                    float4 v = *(const float4*)&x[(size_t)(m0 + m) * CE + k0 + kg];
                    As[kg + 0][m] = v.x; As[kg + 1][m] = v.y;
                    As[kg + 2][m] = v.z; As[kg + 3][m] = v.w;
                }
                idx += 384;
            }
        }
        {
            int idx = t;
#pragma unroll
            for (int rep = 0; rep < 2; rep++) {
                int r = idx / 48, c4 = idx - r * 48;
                const float* W = (c4 < 16) ? Wq : (c4 < 32) ? Wk : Wv;
                int cb = (c4 & 15) << 2;
                *(float4*)&Ws[r][c4 << 2] =
                    *(const float4*)&W[(size_t)(k0 + r) * HD + cb];
                idx += 384;
            }
        }
        __syncthreads();
#pragma unroll
        for (int kk = 0; kk < 16; kk++) {
            float4 a0 = *(const float4*)&As[kk][tr * 8];
            float4 a1 = *(const float4*)&As[kk][tr * 8 + 4];
            ulonglong2 b01 = *(const ulonglong2*)&Ws[kk][tc * 8];
            ulonglong2 b23 = *(const ulonglong2*)&Ws[kk][tc * 8 + 4];
            u64 bb0 = b01.x, bb1 = b01.y, bb2 = b23.x, bb3 = b23.y;
            float av[8] = {a0.x, a0.y, a0.z, a0.w, a1.x, a1.y, a1.z, a1.w};
#pragma unroll
            for (int i = 0; i < 8; i++) {
                u64 aa = pk2(av[i]);
                f2(acc[i][0], aa, bb0); f2(acc[i][1], aa, bb1);
                f2(acc[i][2], aa, bb2); f2(acc[i][3], aa, bb3);
            }
        }
    }
    int cg = tc >> 3;
    float* Out = (cg == 0) ? g_q : (cg == 1) ? g_k : g_v;
    int col = (tc & 7) << 3;
#pragma unroll
    for (int i = 0; i < 8; i++) {
        float2 p0 = up2(acc[i][0]), p1 = up2(acc[i][1]);
        float2 p2 = up2(acc[i][2]), p3 = up2(acc[i][3]);
        float* dst = &Out[(size_t)(m0 + tr * 8 + i) * HD + col];
        *(float4*)dst = make_float4(p0.x, p0.y, p1.x, p1.y);
        *(float4*)(dst + 4) = make_float4(p2.x, p2.y, p3.x, p3.y);
    }
}

// ---------------------------------------------------------------------------
// Pass 1b: split q (pre-scaled by 1/8) and k into bf16 hi/lo
// ---------------------------------------------------------------------------
__global__ __launch_bounds__(256) void split_kernel() {
    int i = blockIdx.x * 256 + threadIdx.x;
    bool isq = (i < 524288);
    int j = isq ? i : i - 524288;
    const float* src = isq ? g_q : g_k;
    float4 v = *(const float4*)&src[(size_t)j * 4];
    if (isq) { v.x *= SCALE; v.y *= SCALE; v.z *= SCALE; v.w *= SCALE; }
    __nv_bfloat16 h0 = __float2bfloat16(v.x), h1 = __float2bfloat16(v.y);
    __nv_bfloat16 h2 = __float2bfloat16(v.z), h3 = __float2bfloat16(v.w);
    __nv_bfloat16 l0 = __float2bfloat16(v.x - __bfloat162float(h0));
    __nv_bfloat16 l1 = __float2bfloat16(v.y - __bfloat162float(h1));
    __nv_bfloat16 l2 = __float2bfloat16(v.z - __bfloat162float(h2));
    __nv_bfloat16 l3 = __float2bfloat16(v.w - __bfloat162float(h3));
    ushort4 hh = make_ushort4(__bfloat16_as_ushort(h0), __bfloat16_as_ushort(h1),
                              __bfloat16_as_ushort(h2), __bfloat16_as_ushort(h3));
    ushort4 ll = make_ushort4(__bfloat16_as_ushort(l0), __bfloat16_as_ushort(l1),
                              __bfloat16_as_ushort(l2), __bfloat16_as_ushort(l3));
    *(ushort4*)&(isq ? g_qh : g_kh)[(size_t)j * 4] = hh;
    *(ushort4*)&(isq ? g_ql : g_kl)[(size_t)j * 4] = ll;
}

// ---------------------------------------------------------------------------
// Pass 2: score via mma.sync bf16x3; E stored as bf16 hi+lo planes.
// ---------------------------------------------------------------------------
#define OQH 0
#define OQL (128 * 144)
#define OKH (2 * 128 * 144)
#define OKL (3 * 128 * 144)
#define OBUF (4 * 128 * 144)
#define SMM_TOTAL (OBUF + 4 * 128 * 4)

__global__ __launch_bounds__(256) void score_mma_kernel() {
    extern __shared__ __align__(16) char smem[];
    int kt = blockIdx.x, qt = blockIdx.y, b = blockIdx.z;
    if (kt > qt) return;
    int q0 = qt << 7, k0 = kt << 7;
    int t = threadIdx.x, wid = t >> 5, lane = t & 31;

    {
        const __nv_bfloat16* gsrc[4] = {
            g_qh + (size_t)(b * T_ + q0) * HD, g_ql + (size_t)(b * T_ + q0) * HD,
            g_kh + (size_t)(b * T_ + k0) * HD, g_kl + (size_t)(b * T_ + k0) * HD};
        const int obase[4] = {OQH, OQL, OKH, OKL};
#pragma unroll
        for (int rep = 0; rep < 2; rep++) {
            int li = rep * 256 + t;
            int a = li >> 7, row = li & 127;
            const uint4* s = (const uint4*)(gsrc[a] + (size_t)row * HD);
            uint4* d = (uint4*)(smem + obase[a] + row * 144);
#pragma unroll
            for (int c = 0; c < 8; c++) d[c] = s[c];
        }
    }
    __syncthreads();

    int qw = wid >> 1, kw = wid & 1;
    u32 sb = s2u(smem);
    float acc[2][8][4] = {};

    const int abase[3] = {OQH, OQH, OQL};
    const int bbase[3] = {OKH, OKL, OKH};
#pragma unroll 1
    for (int p = 0; p < 3; p++) {
        u32 sa = sb + abase[p], sk = bbase[p] + sb;
#pragma unroll
        for (int kk = 0; kk < 4; kk++) {
            u32 afr[2][4];
#pragma unroll
            for (int tq = 0; tq < 2; tq++)
                ldsm4(afr[tq], sa +
                      (u32)((qw * 32 + tq * 16 + (lane & 15)) * 144 +
                            (kk * 16 + ((lane >> 4) << 3)) * 2));
            u32 bfr[4][4];
#pragma unroll
            for (int ng = 0; ng < 4; ng++)
                ldsm4(bfr[ng], sk +
                      (u32)((kw * 64 + ng * 16 + (lane & 7) +
                             ((lane & 16) ? 8 : 0)) * 144 +
                            (kk * 16 + ((lane & 8) ? 8 : 0)) * 2));
#pragma unroll
            for (int tq = 0; tq < 2; tq++)
#pragma unroll
                for (int ng = 0; ng < 4; ng++) {
                    mma16816(acc[tq][ng * 2 + 0], afr[tq], bfr[ng] + 0);
                    mma16816(acc[tq][ng * 2 + 1], afr[tq], bfr[ng] + 2);
                }
        }
    }

    // epilogue: exp -> E hi/lo bf16 stores + fp32 column sums
    int g = lane >> 2, tp = (lane & 3) << 1;
    bool diag = (kt == qt);
    float cs[8][2] = {};
#pragma unroll
    for (int tq = 0; tq < 2; tq++) {
        int qrA = q0 + qw * 32 + tq * 16 + g;
        int qrB = qrA + 8;
#pragma unroll
        for (int nt = 0; nt < 8; nt++) {
            int kcol = k0 + kw * 64 + nt * 8 + tp;
            float e0 = fast_exp(acc[tq][nt][0]);
            float e1 = fast_exp(acc[tq][nt][1]);
            float e2 = fast_exp(acc[tq][nt][2]);
            float e3 = fast_exp(acc[tq][nt][3]);
            if (diag) {
                if (qrA < kcol) e0 = 0.f;
                if (qrA < kcol + 1) e1 = 0.f;
                if (qrB < kcol) e2 = 0.f;
                if (qrB < kcol + 1) e3 = 0.f;
            }
            __nv_bfloat162 hA = __floats2bfloat162_rn(e0, e1);
            __nv_bfloat162 hB = __floats2bfloat162_rn(e2, e3);
            __nv_bfloat162 lA = __floats2bfloat162_rn(
                e0 - __bfloat162float(hA.x), e1 - __bfloat162float(hA.y));
            __nv_bfloat162 lB = __floats2bfloat162_rn(
                e2 - __bfloat162float(hB.x), e3 - __bfloat162float(hB.y));
            size_t offA = ((size_t)(b * T_ + qrA)) * T_ + kcol;
            size_t offB = ((size_t)(b * T_ + qrB)) * T_ + kcol;
            *(__nv_bfloat162*)&g_eh[offA] = hA;
            *(__nv_bfloat162*)&g_eh[offB] = hB;
            *(__nv_bfloat162*)&g_el[offA] = lA;
            *(__nv_bfloat162*)&g_el[offB] = lB;
            cs[nt][0] += e0 + e2;
            cs[nt][1] += e1 + e3;
        }
    }
#pragma unroll
    for (int nt = 0; nt < 8; nt++)
#pragma unroll
        for (int j = 0; j < 2; j++) {
            float v = cs[nt][j];
            v += __shfl_xor_sync(0xffffffffu, v, 4);
            v += __shfl_xor_sync(0xffffffffu, v, 8);
            v += __shfl_xor_sync(0xffffffffu, v, 16);
            cs[nt][j] = v;
        }
    float* buf = (float*)(smem + OBUF);
    if (lane < 4) {
#pragma unroll
        for (int nt = 0; nt < 8; nt++) {
            buf[qw * 128 + kw * 64 + nt * 8 + ((lane & 3) << 1) + 0] = cs[nt][0];
            buf[qw * 128 + kw * 64 + nt * 8 + ((lane & 3) << 1) + 1] = cs[nt][1];
        }
    }
    __syncthreads();
    if (t < 128) {
        float s = buf[t] + buf[128 + t] + buf[256 + t] + buf[384 + t];
        g_dp[(size_t)((b << 5) + qt) * T_ + k0 + t] = s;
    }
}

// ---------------------------------------------------------------------------
// Pass 3: d[k] -> reciprocal
// ---------------------------------------------------------------------------
__global__ void dinv_kernel() {
    int i = blockIdx.x * 256 + threadIdx.x;
    int b = i >> 12, k = i & 4095;
    float s = 0.f;
    for (int qt = (k >> 7); qt < 32; qt++)
        s += g_dp[(size_t)((b << 5) + qt) * T_ + k];
    g_dinv[i] = 1.0f / s;
}

// ---------------------------------------------------------------------------
// Pass 3b: Vt = (V*dinv)^T in bf16 hi/lo, [b][h][k] layout
// ---------------------------------------------------------------------------
__global__ __launch_bounds__(256) void vprep_kernel() {
    __shared__ __align__(16) float Vt[64][68];
    int k0 = blockIdx.x << 6, b = blockIdx.y;
    int t = threadIdx.x;
    {
        int k = t >> 2, hseg = (t & 3) << 4;
        float dinv = g_dinv[(b << 12) + k0 + k];
        const float* src = &g_v[(size_t)(b * T_ + k0 + k) * HD + hseg];
#pragma unroll
        for (int u = 0; u < 4; u++) {
            float4 v = *(const float4*)&src[u * 4];
            Vt[hseg + u * 4 + 0][k] = v.x * dinv;
            Vt[hseg + u * 4 + 1][k] = v.y * dinv;
            Vt[hseg + u * 4 + 2][k] = v.z * dinv;
            Vt[hseg + u * 4 + 3][k] = v.w * dinv;
        }
    }
    __syncthreads();
    {
        int h = t >> 2, kseg = (t & 3) << 4;
        ushort4 hh[4], ll[4];
#pragma unroll
        for (int u = 0; u < 4; u++) {
            unsigned short hv[4], lv[4];
#pragma unroll
            for (int e = 0; e < 4; e++) {
                float v = Vt[h][kseg + u * 4 + e];
                __nv_bfloat16 hb = __float2bfloat16(v);
                __nv_bfloat16 lb = __float2bfloat16(v - __bfloat162float(hb));
                hv[e] = __bfloat16_as_ushort(hb);
                lv[e] = __bfloat16_as_ushort(lb);
            }
            hh[u] = make_ushort4(hv[0], hv[1], hv[2], hv[3]);
            ll[u] = make_ushort4(lv[0], lv[1], lv[2], lv[3]);
        }
        size_t dst = (size_t)(b * HD + h) * T_ + k0 + kseg;
#pragma unroll
        for (int u = 0; u < 4; u++) {
            *(ushort4*)&g_vth[dst + u * 4] = hh[u];
            *(ushort4*)&g_vtl[dst + u * 4] = ll[u];
        }
    }
}

// ---------------------------------------------------------------------------
// Pass 4: out via mma.sync 3-pass: O = Eh@Vh + Eh@Vl + El@Vh
// ---------------------------------------------------------------------------
#define OEH 0
#define OEL (128 * 144)
#define OVH (2 * 128 * 144)
#define OVL (OVH + 64 * 144)
#define SMO_TOTAL (OVL + 64 * 144)

__global__ __launch_bounds__(256) void out_mma_kernel() {
    extern __shared__ __align__(16) char smem[];
    int qt = blockIdx.x, s = blockIdx.y, b = blockIdx.z;
    int q0 = qt << 7;
    int nch = 2 * qt + 2;
    int lo = (s * nch) >> 2, hi = ((s + 1) * nch) >> 2;
    int t = threadIdx.x, wid = t >> 5, lane = t & 31;
    int qw = wid >> 1, hw = wid & 1;
    u32 sb = s2u(smem);

    float acc[2][4][4] = {};
    for (int c = lo; c < hi; c++) {
        int k0 = c << 6;
        __syncthreads();
        // stage Eh/El chunks: 128 q-rows x 64 k bf16 each
#pragma unroll
        for (int rep = 0; rep < 4; rep++) {
            int li = rep * 256 + t;          // 0..1023 = 128 rows x 8 uint4
            int row = li >> 3, c16 = li & 7;
            size_t gsrc = ((size_t)(b * T_ + q0 + row)) * T_ + k0 + c16 * 8;
            *(uint4*)(smem + OEH + row * 144 + c16 * 16) =
                *(const uint4*)&g_eh[gsrc];
            *(uint4*)(smem + OEL + row * 144 + c16 * 16) =
                *(const uint4*)&g_el[gsrc];
        }
        // stage Vth/Vtl chunks: 64 h-rows x 64 k bf16 each
#pragma unroll
        for (int rep = 0; rep < 2; rep++) {
            int li = rep * 256 + t;          // 0..511 = 64 rows x 8 uint4
            int row = li >> 3, c16 = li & 7;
            size_t gsrc = (size_t)(b * HD + row) * T_ + k0 + c16 * 8;
            *(uint4*)(smem + OVH + row * 144 + c16 * 16) =
                *(const uint4*)&g_vth[gsrc];
            *(uint4*)(smem + OVL + row * 144 + c16 * 16) =
                *(const uint4*)&g_vtl[gsrc];
        }
        __syncthreads();

#pragma unroll
        for (int kk = 0; kk < 4; kk++) {
            u32 ah[2][4], al[2][4];
#pragma unroll
            for (int tq = 0; tq < 2; tq++) {
                u32 aoff = (u32)((qw * 32 + tq * 16 + (lane & 15)) * 144 +
                                 (kk * 16 + ((lane >> 4) << 3)) * 2);
                ldsm4(ah[tq], sb + OEH + aoff);
                ldsm4(al[tq], sb + OEL + aoff);
            }
            u32 bh[2][4], bl[2][4];
#pragma unroll
            for (int ng = 0; ng < 2; ng++) {
                u32 roff = (u32)((hw * 32 + ng * 16 + (lane & 7) +
                                  ((lane & 16) ? 8 : 0)) * 144 +
                                 (kk * 16 + ((lane & 8) ? 8 : 0)) * 2);
                ldsm4(bh[ng], sb + OVH + roff);
                ldsm4(bl[ng], sb + OVL + roff);
            }
#pragma unroll
            for (int tq = 0; tq < 2; tq++)
#pragma unroll
                for (int nt = 0; nt < 4; nt++) {
                    int ng = nt >> 1, hf = (nt & 1) << 1;
                    mma16816(acc[tq][nt], ah[tq], bh[ng] + hf);
                    mma16816(acc[tq][nt], ah[tq], bl[ng] + hf);
                    mma16816(acc[tq][nt], al[tq], bh[ng] + hf);
                }
        }
    }

    int g = lane >> 2, tp = (lane & 3) << 1;
#pragma unroll
    for (int tq = 0; tq < 2; tq++) {
        int qrA = q0 + qw * 32 + tq * 16 + g;
#pragma unroll
        for (int nt = 0; nt < 4; nt++) {
            int h = hw * 32 + nt * 8 + tp;
            size_t base = (size_t)((s * B_ + b) * T_);
            *(float2*)&g_op[(base + qrA) * HD + h] =
                make_float2(acc[tq][nt][0], acc[tq][nt][1]);
            *(float2*)&g_op[(base + qrA + 8) * HD + h] =
                make_float2(acc[tq][nt][2], acc[tq][nt][3]);
        }
    }
}

// ---------------------------------------------------------------------------
// Pass 5: sum 4 split partials
// ---------------------------------------------------------------------------
__global__ void reduce_kernel(float* __restrict__ out) {
    const int N4 = B_ * T_ * HD / 4;
    int i = blockIdx.x * 256 + threadIdx.x;
    const float4* p = (const float4*)g_op;
    float4 a = p[i], b = p[i + N4], c = p[i + 2 * N4], d = p[i + 3 * N4];
    ((float4*)out)[i] = make_float4(a.x + b.x + c.x + d.x,
                                    a.y + b.y + c.y + d.y,
                                    a.z + b.z + c.z + d.z,
                                    a.w + b.w + c.w + d.w);
}

// ---------------------------------------------------------------------------
// inputs: x, Wk, Wq, Wv ; output fp32 [8,4096,64]
// ---------------------------------------------------------------------------
extern "C" void kernel_launch(void* const* d_in, const int* in_sizes, int n_in,
                              void* d_out, int out_size) {
    const float* x  = (const float*)d_in[0];
    const float* Wk = (const float*)d_in[1];
    const float* Wq = (const float*)d_in[2];
    const float* Wv = (const float*)d_in[3];
    float* out = (float*)d_out;

    cudaFuncSetAttribute(score_mma_kernel,
        cudaFuncAttributeMaxDynamicSharedMemorySize, SMM_TOTAL);
    cudaFuncSetAttribute(out_mma_kernel,
        cudaFuncAttributeMaxDynamicSharedMemorySize, SMO_TOTAL);

    proj_kernel<<<256, 384>>>(x, Wq, Wk, Wv);
    split_kernel<<<4096, 256>>>();
    score_mma_kernel<<<dim3(32, 32, 8), 256, SMM_TOTAL>>>();
    dinv_kernel<<<128, 256>>>();
    vprep_kernel<<<dim3(64, 8), 256>>>();
    out_mma_kernel<<<dim3(32, 4, 8), 256, SMO_TOTAL>>>();
    reduce_kernel<<<2048, 256>>>(out);
}

// round 10
// speedup vs baseline: 2.9445x; 1.3383x over previous
#include <cuda_runtime.h>
#include <cuda_bf16.h>
#include <cstdint>

#define B_ 8
#define T_ 4096
#define CE 1024
#define HD 64
#define SCALE 0.125f

typedef unsigned long long u64;
typedef unsigned int u32;

// ---- device scratch (allocation-free) ----
__device__ __align__(16) float g_v[B_ * T_ * HD];
__device__ __align__(16) __nv_bfloat16 g_xh[B_ * T_ * CE];
__device__ __align__(16) __nv_bfloat16 g_xl[B_ * T_ * CE];
__device__ __align__(16) __nv_bfloat16 g_wth[3 * HD * CE];  // W^T hi [n][k]
__device__ __align__(16) __nv_bfloat16 g_wtl[3 * HD * CE];  // W^T lo
__device__ __align__(16) __nv_bfloat16 g_qh[B_ * T_ * HD];
__device__ __align__(16) __nv_bfloat16 g_ql[B_ * T_ * HD];
__device__ __align__(16) __nv_bfloat16 g_kh[B_ * T_ * HD];
__device__ __align__(16) __nv_bfloat16 g_kl[B_ * T_ * HD];
__device__ __align__(16) __nv_bfloat16 g_eh[(size_t)B_ * T_ * T_];
__device__ __align__(16) __nv_bfloat16 g_el[(size_t)B_ * T_ * T_];
__device__ __align__(16) __nv_bfloat16 g_vth[B_ * HD * T_];
__device__ __align__(16) __nv_bfloat16 g_vtl[B_ * HD * T_];
__device__ __align__(16) float g_dp[B_ * 32 * T_];
__device__ __align__(16) float g_dinv[B_ * T_];
__device__ __align__(16) float g_op[4 * B_ * T_ * HD];

__device__ __forceinline__ float fast_exp(float x) {
    float y = x * 1.4426950408889634f;
    float n = rintf(y);
    float f = y - n;
    float p = 1.3333558146e-3f;
    p = fmaf(p, f, 9.6181291076e-3f);
    p = fmaf(p, f, 5.5504108664e-2f);
    p = fmaf(p, f, 2.4022650696e-1f);
    p = fmaf(p, f, 6.9314718056e-1f);
    p = fmaf(p, f, 1.0f);
    return p * __int_as_float(((int)n + 127) << 23);
}

// ---- warp MMA helpers ----
__device__ __forceinline__ u32 s2u(const void* p) {
    u32 a;
    asm("{ .reg .u64 t; cvta.to.shared.u64 t, %1; cvt.u32.u64 %0, t; }"
        : "=r"(a) : "l"(p));
    return a;
}
__device__ __forceinline__ void ldsm4(u32* r, u32 addr) {
    asm volatile("ldmatrix.sync.aligned.m8n8.x4.shared.b16 {%0,%1,%2,%3}, [%4];"
                 : "=r"(r[0]), "=r"(r[1]), "=r"(r[2]), "=r"(r[3]) : "r"(addr));
}
__device__ __forceinline__ void mma16816(float* d, const u32* a, const u32* b) {
    asm volatile(
        "mma.sync.aligned.m16n8k16.row.col.f32.bf16.bf16.f32 "
        "{%0,%1,%2,%3}, {%4,%5,%6,%7}, {%8,%9}, {%0,%1,%2,%3};"
        : "+f"(d[0]), "+f"(d[1]), "+f"(d[2]), "+f"(d[3])
        : "r"(a[0]), "r"(a[1]), "r"(a[2]), "r"(a[3]), "r"(b[0]), "r"(b[1]));
}
__device__ __forceinline__ void bfsplit(float v, __nv_bfloat16& h, __nv_bfloat16& l) {
    h = __float2bfloat16(v);
    l = __float2bfloat16(v - __bfloat162float(h));
}

// ---------------------------------------------------------------------------
// Pass 0a: split x into bf16 hi/lo planes
// ---------------------------------------------------------------------------
__global__ __launch_bounds__(256) void xsplit_kernel(const float* __restrict__ x) {
    size_t i = (size_t)blockIdx.x * 256 + threadIdx.x;   // float4 groups
    float4 v = *(const float4*)&x[i * 4];
    __nv_bfloat16 h0, h1, h2, h3, l0, l1, l2, l3;
    bfsplit(v.x, h0, l0); bfsplit(v.y, h1, l1);
    bfsplit(v.z, h2, l2); bfsplit(v.w, h3, l3);
    *(ushort4*)&g_xh[i * 4] =
        make_ushort4(__bfloat16_as_ushort(h0), __bfloat16_as_ushort(h1),
                     __bfloat16_as_ushort(h2), __bfloat16_as_ushort(h3));
    *(ushort4*)&g_xl[i * 4] =
        make_ushort4(__bfloat16_as_ushort(l0), __bfloat16_as_ushort(l1),
                     __bfloat16_as_ushort(l2), __bfloat16_as_ushort(l3));
}

// ---------------------------------------------------------------------------
// Pass 0b: transpose+split W into [n=192][k=1024] bf16 hi/lo
// ---------------------------------------------------------------------------
__global__ __launch_bounds__(256) void wsplit_kernel(
    const float* __restrict__ Wq, const float* __restrict__ Wk,
    const float* __restrict__ Wv) {
    int i = blockIdx.x * 256 + threadIdx.x;   // 0..196607
    int n = i >> 10, k = i & 1023;
    const float* W = (n < 64) ? Wq : (n < 128) ? Wk : Wv;
    float v = W[k * HD + (n & 63)];
    __nv_bfloat16 h, l;
    bfsplit(v, h, l);
    g_wth[i] = h;
    g_wtl[i] = l;
}

// ---------------------------------------------------------------------------
// Pass 1: proj via mma.sync bf16x3: {q,k,v} = x @ W.
// Tile 128m x 64n, K=1024 in 64-chunks. grid (256 mtiles, 3 = q/k/v).
// Epilogue: q (scaled 1/8) and k written as bf16 hi/lo; v written fp32.
// ---------------------------------------------------------------------------
#define PXH 0
#define PXL (128 * 144)
#define PWH (2 * 128 * 144)
#define PWL (PWH + 64 * 144)
#define SMP_TOTAL (PWL + 64 * 144)    // 55296

__global__ __launch_bounds__(256) void proj_mma_kernel() {
    extern __shared__ __align__(16) char smem[];
    int m0 = blockIdx.x << 7, ntile = blockIdx.y;
    int t = threadIdx.x, wid = t >> 5, lane = t & 31;
    int qw = wid >> 1, hw = wid & 1;
    u32 sb = s2u(smem);

    float acc[2][4][4] = {};
#pragma unroll 1
    for (int kc = 0; kc < 16; kc++) {
        int k0 = kc << 6;
        __syncthreads();
        // stage x hi/lo chunk: 128 rows x 64 k
#pragma unroll
        for (int rep = 0; rep < 4; rep++) {
            int li = rep * 256 + t;
            int row = li >> 3, c16 = li & 7;
            size_t gsrc = (size_t)(m0 + row) * CE + k0 + c16 * 8;
            *(uint4*)(smem + PXH + row * 144 + c16 * 16) =
                *(const uint4*)&g_xh[gsrc];
            *(uint4*)(smem + PXL + row * 144 + c16 * 16) =
                *(const uint4*)&g_xl[gsrc];
        }
        // stage W^T hi/lo chunk: 64 n-rows x 64 k
#pragma unroll
        for (int rep = 0; rep < 2; rep++) {
            int li = rep * 256 + t;
            int row = li >> 3, c16 = li & 7;
            size_t gsrc = (size_t)(ntile * 64 + row) * CE + k0 + c16 * 8;
            *(uint4*)(smem + PWH + row * 144 + c16 * 16) =
                *(const uint4*)&g_wth[gsrc];
            *(uint4*)(smem + PWL + row * 144 + c16 * 16) =
                *(const uint4*)&g_wtl[gsrc];
        }
        __syncthreads();

#pragma unroll
        for (int kk = 0; kk < 4; kk++) {
            u32 ah[2][4], al[2][4];
#pragma unroll
            for (int tq = 0; tq < 2; tq++) {
                u32 aoff = (u32)((qw * 32 + tq * 16 + (lane & 15)) * 144 +
                                 (kk * 16 + ((lane >> 4) << 3)) * 2);
                ldsm4(ah[tq], sb + PXH + aoff);
                ldsm4(al[tq], sb + PXL + aoff);
            }
            u32 bh[2][4], bl[2][4];
#pragma unroll
            for (int ng = 0; ng < 2; ng++) {
                u32 roff = (u32)((hw * 32 + ng * 16 + (lane & 7) +
                                  ((lane & 16) ? 8 : 0)) * 144 +
                                 (kk * 16 + ((lane & 8) ? 8 : 0)) * 2);
                ldsm4(bh[ng], sb + PWH + roff);
                ldsm4(bl[ng], sb + PWL + roff);
            }
#pragma unroll
            for (int tq = 0; tq < 2; tq++)
#pragma unroll
                for (int nt = 0; nt < 4; nt++) {
                    int ng = nt >> 1, hf = (nt & 1) << 1;
                    mma16816(acc[tq][nt], ah[tq], bh[ng] + hf);
                    mma16816(acc[tq][nt], ah[tq], bl[ng] + hf);
                    mma16816(acc[tq][nt], al[tq], bh[ng] + hf);
                }
        }
    }

    int g = lane >> 2, tp = (lane & 3) << 1;
#pragma unroll
    for (int tq = 0; tq < 2; tq++) {
        int mA = m0 + qw * 32 + tq * 16 + g;
        int mB = mA + 8;
#pragma unroll
        for (int nt = 0; nt < 4; nt++) {
            int h = hw * 32 + nt * 8 + tp;
            float v0 = acc[tq][nt][0], v1 = acc[tq][nt][1];
            float v2 = acc[tq][nt][2], v3 = acc[tq][nt][3];
            if (ntile == 2) {
                *(float2*)&g_v[(size_t)mA * HD + h] = make_float2(v0, v1);
                *(float2*)&g_v[(size_t)mB * HD + h] = make_float2(v2, v3);
            } else {
                if (ntile == 0) {
                    v0 *= SCALE; v1 *= SCALE; v2 *= SCALE; v3 *= SCALE;
                }
                __nv_bfloat16* gh = (ntile == 0) ? g_qh : g_kh;
                __nv_bfloat16* gl = (ntile == 0) ? g_ql : g_kl;
                __nv_bfloat162 hA = __floats2bfloat162_rn(v0, v1);
                __nv_bfloat162 hB = __floats2bfloat162_rn(v2, v3);
                __nv_bfloat162 lA = __floats2bfloat162_rn(
                    v0 - __bfloat162float(hA.x), v1 - __bfloat162float(hA.y));
                __nv_bfloat162 lB = __floats2bfloat162_rn(
                    v2 - __bfloat162float(hB.x), v3 - __bfloat162float(hB.y));
                *(__nv_bfloat162*)&gh[(size_t)mA * HD + h] = hA;
                *(__nv_bfloat162*)&gh[(size_t)mB * HD + h] = hB;
                *(__nv_bfloat162*)&gl[(size_t)mA * HD + h] = lA;
                *(__nv_bfloat162*)&gl[(size_t)mB * HD + h] = lB;
            }
        }
    }
}

// ---------------------------------------------------------------------------
// Pass 2: score via mma.sync bf16x3; E stored as bf16 hi+lo planes.
// ---------------------------------------------------------------------------
#define OQH 0
#define OQL (128 * 144)
#define OKH (2 * 128 * 144)
#define OKL (3 * 128 * 144)
#define OBUF (4 * 128 * 144)
#define SMM_TOTAL (OBUF + 4 * 128 * 4)

__global__ __launch_bounds__(256) void score_mma_kernel() {
    extern __shared__ __align__(16) char smem[];
    int kt = blockIdx.x, qt = blockIdx.y, b = blockIdx.z;
    if (kt > qt) return;
    int q0 = qt << 7, k0 = kt << 7;
    int t = threadIdx.x, wid = t >> 5, lane = t & 31;

    {
        const __nv_bfloat16* gsrc[4] = {
            g_qh + (size_t)(b * T_ + q0) * HD, g_ql + (size_t)(b * T_ + q0) * HD,
            g_kh + (size_t)(b * T_ + k0) * HD, g_kl + (size_t)(b * T_ + k0) * HD};
        const int obase[4] = {OQH, OQL, OKH, OKL};
#pragma unroll
        for (int rep = 0; rep < 2; rep++) {
            int li = rep * 256 + t;
            int a = li >> 7, row = li & 127;
            const uint4* s = (const uint4*)(gsrc[a] + (size_t)row * HD);
            uint4* d = (uint4*)(smem + obase[a] + row * 144);
#pragma unroll
            for (int c = 0; c < 8; c++) d[c] = s[c];
        }
    }
    __syncthreads();

    int qw = wid >> 1, kw = wid & 1;
    u32 sb = s2u(smem);
    float acc[2][8][4] = {};

    const int abase[3] = {OQH, OQH, OQL};
    const int bbase[3] = {OKH, OKL, OKH};
#pragma unroll 1
    for (int p = 0; p < 3; p++) {
        u32 sa = sb + abase[p], sk = bbase[p] + sb;
#pragma unroll
        for (int kk = 0; kk < 4; kk++) {
            u32 afr[2][4];
#pragma unroll
            for (int tq = 0; tq < 2; tq++)
                ldsm4(afr[tq], sa +
                      (u32)((qw * 32 + tq * 16 + (lane & 15)) * 144 +
                            (kk * 16 + ((lane >> 4) << 3)) * 2));
            u32 bfr[4][4];
#pragma unroll
            for (int ng = 0; ng < 4; ng++)
                ldsm4(bfr[ng], sk +
                      (u32)((kw * 64 + ng * 16 + (lane & 7) +
                             ((lane & 16) ? 8 : 0)) * 144 +
                            (kk * 16 + ((lane & 8) ? 8 : 0)) * 2));
#pragma unroll
            for (int tq = 0; tq < 2; tq++)
#pragma unroll
                for (int ng = 0; ng < 4; ng++) {
                    mma16816(acc[tq][ng * 2 + 0], afr[tq], bfr[ng] + 0);
                    mma16816(acc[tq][ng * 2 + 1], afr[tq], bfr[ng] + 2);
                }
        }
    }

    int g = lane >> 2, tp = (lane & 3) << 1;
    bool diag = (kt == qt);
    float cs[8][2] = {};
#pragma unroll
    for (int tq = 0; tq < 2; tq++) {
        int qrA = q0 + qw * 32 + tq * 16 + g;
        int qrB = qrA + 8;
#pragma unroll
        for (int nt = 0; nt < 8; nt++) {
            int kcol = k0 + kw * 64 + nt * 8 + tp;
            float e0 = fast_exp(acc[tq][nt][0]);
            float e1 = fast_exp(acc[tq][nt][1]);
            float e2 = fast_exp(acc[tq][nt][2]);
            float e3 = fast_exp(acc[tq][nt][3]);
            if (diag) {
                if (qrA < kcol) e0 = 0.f;
                if (qrA < kcol + 1) e1 = 0.f;
                if (qrB < kcol) e2 = 0.f;
                if (qrB < kcol + 1) e3 = 0.f;
            }
            __nv_bfloat162 hA = __floats2bfloat162_rn(e0, e1);
            __nv_bfloat162 hB = __floats2bfloat162_rn(e2, e3);
            __nv_bfloat162 lA = __floats2bfloat162_rn(
                e0 - __bfloat162float(hA.x), e1 - __bfloat162float(hA.y));
            __nv_bfloat162 lB = __floats2bfloat162_rn(
                e2 - __bfloat162float(hB.x), e3 - __bfloat162float(hB.y));
            size_t offA = ((size_t)(b * T_ + qrA)) * T_ + kcol;
            size_t offB = ((size_t)(b * T_ + qrB)) * T_ + kcol;
            *(__nv_bfloat162*)&g_eh[offA] = hA;
            *(__nv_bfloat162*)&g_eh[offB] = hB;
            *(__nv_bfloat162*)&g_el[offA] = lA;
            *(__nv_bfloat162*)&g_el[offB] = lB;
            cs[nt][0] += e0 + e2;
            cs[nt][1] += e1 + e3;
        }
    }
#pragma unroll
    for (int nt = 0; nt < 8; nt++)
#pragma unroll
        for (int j = 0; j < 2; j++) {
            float v = cs[nt][j];
            v += __shfl_xor_sync(0xffffffffu, v, 4);
            v += __shfl_xor_sync(0xffffffffu, v, 8);
            v += __shfl_xor_sync(0xffffffffu, v, 16);
            cs[nt][j] = v;
        }
    float* buf = (float*)(smem + OBUF);
    if (lane < 4) {
#pragma unroll
        for (int nt = 0; nt < 8; nt++) {
            buf[qw * 128 + kw * 64 + nt * 8 + ((lane & 3) << 1) + 0] = cs[nt][0];
            buf[qw * 128 + kw * 64 + nt * 8 + ((lane & 3) << 1) + 1] = cs[nt][1];
        }
    }
    __syncthreads();
    if (t < 128) {
        float s = buf[t] + buf[128 + t] + buf[256 + t] + buf[384 + t];
        g_dp[(size_t)((b << 5) + qt) * T_ + k0 + t] = s;
    }
}

// ---------------------------------------------------------------------------
// Pass 3: d[k] -> reciprocal
// ---------------------------------------------------------------------------
__global__ void dinv_kernel() {
    int i = blockIdx.x * 256 + threadIdx.x;
    int b = i >> 12, k = i & 4095;
    float s = 0.f;
    for (int qt = (k >> 7); qt < 32; qt++)
        s += g_dp[(size_t)((b << 5) + qt) * T_ + k];
    g_dinv[i] = 1.0f / s;
}

// ---------------------------------------------------------------------------
// Pass 3b: Vt = (V*dinv)^T in bf16 hi/lo, [b][h][k] layout
// ---------------------------------------------------------------------------
__global__ __launch_bounds__(256) void vprep_kernel() {
    __shared__ __align__(16) float Vt[64][68];
    int k0 = blockIdx.x << 6, b = blockIdx.y;
    int t = threadIdx.x;
    {
        int k = t >> 2, hseg = (t & 3) << 4;
        float dinv = g_dinv[(b << 12) + k0 + k];
        const float* src = &g_v[(size_t)(b * T_ + k0 + k) * HD + hseg];
#pragma unroll
        for (int u = 0; u < 4; u++) {
            float4 v = *(const float4*)&src[u * 4];
            Vt[hseg + u * 4 + 0][k] = v.x * dinv;
            Vt[hseg + u * 4 + 1][k] = v.y * dinv;
            Vt[hseg + u * 4 + 2][k] = v.z * dinv;
            Vt[hseg + u * 4 + 3][k] = v.w * dinv;
        }
    }
    __syncthreads();
    {
        int h = t >> 2, kseg = (t & 3) << 4;
        ushort4 hh[4], ll[4];
#pragma unroll
        for (int u = 0; u < 4; u++) {
            unsigned short hv[4], lv[4];
#pragma unroll
            for (int e = 0; e < 4; e++) {
                float v = Vt[h][kseg + u * 4 + e];
                __nv_bfloat16 hb, lb;
                bfsplit(v, hb, lb);
                hv[e] = __bfloat16_as_ushort(hb);
                lv[e] = __bfloat16_as_ushort(lb);
            }
            hh[u] = make_ushort4(hv[0], hv[1], hv[2], hv[3]);
            ll[u] = make_ushort4(lv[0], lv[1], lv[2], lv[3]);
        }
        size_t dst = (size_t)(b * HD + h) * T_ + k0 + kseg;
#pragma unroll
        for (int u = 0; u < 4; u++) {
            *(ushort4*)&g_vth[dst + u * 4] = hh[u];
            *(ushort4*)&g_vtl[dst + u * 4] = ll[u];
        }
    }
}

// ---------------------------------------------------------------------------
// Pass 4: out via mma.sync 3-pass: O = Eh@Vh + Eh@Vl + El@Vh
// ---------------------------------------------------------------------------
#define OEH 0
#define OEL (128 * 144)
#define OVH (2 * 128 * 144)
#define OVL (OVH + 64 * 144)
#define SMO_TOTAL (OVL + 64 * 144)

__global__ __launch_bounds__(256) void out_mma_kernel() {
    extern __shared__ __align__(16) char smem[];
    int qt = blockIdx.x, s = blockIdx.y, b = blockIdx.z;
    int q0 = qt << 7;
    int nch = 2 * qt + 2;
    int lo = (s * nch) >> 2, hi = ((s + 1) * nch) >> 2;
    int t = threadIdx.x, wid = t >> 5, lane = t & 31;
    int qw = wid >> 1, hw = wid & 1;
    u32 sb = s2u(smem);

    float acc[2][4][4] = {};
    for (int c = lo; c < hi; c++) {
        int k0 = c << 6;
        __syncthreads();
#pragma unroll
        for (int rep = 0; rep < 4; rep++) {
            int li = rep * 256 + t;
            int row = li >> 3, c16 = li & 7;
            size_t gsrc = ((size_t)(b * T_ + q0 + row)) * T_ + k0 + c16 * 8;
            *(uint4*)(smem + OEH + row * 144 + c16 * 16) =
                *(const uint4*)&g_eh[gsrc];
            *(uint4*)(smem + OEL + row * 144 + c16 * 16) =
                *(const uint4*)&g_el[gsrc];
        }
#pragma unroll
        for (int rep = 0; rep < 2; rep++) {
            int li = rep * 256 + t;
            int row = li >> 3, c16 = li & 7;
            size_t gsrc = (size_t)(b * HD + row) * T_ + k0 + c16 * 8;
            *(uint4*)(smem + OVH + row * 144 + c16 * 16) =
                *(const uint4*)&g_vth[gsrc];
            *(uint4*)(smem + OVL + row * 144 + c16 * 16) =
                *(const uint4*)&g_vtl[gsrc];
        }
        __syncthreads();

#pragma unroll
        for (int kk = 0; kk < 4; kk++) {
            u32 ah[2][4], al[2][4];
#pragma unroll
            for (int tq = 0; tq < 2; tq++) {
                u32 aoff = (u32)((qw * 32 + tq * 16 + (lane & 15)) * 144 +
                                 (kk * 16 + ((lane >> 4) << 3)) * 2);
                ldsm4(ah[tq], sb + OEH + aoff);
                ldsm4(al[tq], sb + OEL + aoff);
            }
            u32 bh[2][4], bl[2][4];
#pragma unroll
            for (int ng = 0; ng < 2; ng++) {
                u32 roff = (u32)((hw * 32 + ng * 16 + (lane & 7) +
                                  ((lane & 16) ? 8 : 0)) * 144 +
                                 (kk * 16 + ((lane & 8) ? 8 : 0)) * 2);
                ldsm4(bh[ng], sb + OVH + roff);
                ldsm4(bl[ng], sb + OVL + roff);
            }
#pragma unroll
            for (int tq = 0; tq < 2; tq++)
#pragma unroll
                for (int nt = 0; nt < 4; nt++) {
                    int ng = nt >> 1, hf = (nt & 1) << 1;
                    mma16816(acc[tq][nt], ah[tq], bh[ng] + hf);
                    mma16816(acc[tq][nt], ah[tq], bl[ng] + hf);
                    mma16816(acc[tq][nt], al[tq], bh[ng] + hf);
                }
        }
    }

    int g = lane >> 2, tp = (lane & 3) << 1;
#pragma unroll
    for (int tq = 0; tq < 2; tq++) {
        int qrA = q0 + qw * 32 + tq * 16 + g;
#pragma unroll
        for (int nt = 0; nt < 4; nt++) {
            int h = hw * 32 + nt * 8 + tp;
            size_t base = (size_t)((s * B_ + b) * T_);
            *(float2*)&g_op[(base + qrA) * HD + h] =
                make_float2(acc[tq][nt][0], acc[tq][nt][1]);
            *(float2*)&g_op[(base + qrA + 8) * HD + h] =
                make_float2(acc[tq][nt][2], acc[tq][nt][3]);
        }
    }
}

// ---------------------------------------------------------------------------
// Pass 5: sum 4 split partials
// ---------------------------------------------------------------------------
__global__ void reduce_kernel(float* __restrict__ out) {
    const int N4 = B_ * T_ * HD / 4;
    int i = blockIdx.x * 256 + threadIdx.x;
    const float4* p = (const float4*)g_op;
    float4 a = p[i], b = p[i + N4], c = p[i + 2 * N4], d = p[i + 3 * N4];
    ((float4*)out)[i] = make_float4(a.x + b.x + c.x + d.x,
                                    a.y + b.y + c.y + d.y,
                                    a.z + b.z + c.z + d.z,
                                    a.w + b.w + c.w + d.w);
}

// ---------------------------------------------------------------------------
// inputs: x, Wk, Wq, Wv ; output fp32 [8,4096,64]
// ---------------------------------------------------------------------------
extern "C" void kernel_launch(void* const* d_in, const int* in_sizes, int n_in,
                              void* d_out, int out_size) {
    const float* x  = (const float*)d_in[0];
    const float* Wk = (const float*)d_in[1];
    const float* Wq = (const float*)d_in[2];
    const float* Wv = (const float*)d_in[3];
    float* out = (float*)d_out;

    cudaFuncSetAttribute(proj_mma_kernel,
        cudaFuncAttributeMaxDynamicSharedMemorySize, SMP_TOTAL);
    cudaFuncSetAttribute(score_mma_kernel,
        cudaFuncAttributeMaxDynamicSharedMemorySize, SMM_TOTAL);
    cudaFuncSetAttribute(out_mma_kernel,
        cudaFuncAttributeMaxDynamicSharedMemorySize, SMO_TOTAL);

    xsplit_kernel<<<32768, 256>>>(x);
    wsplit_kernel<<<768, 256>>>(Wq, Wk, Wv);
    proj_mma_kernel<<<dim3(256, 3), 256, SMP_TOTAL>>>();
    score_mma_kernel<<<dim3(32, 32, 8), 256, SMM_TOTAL>>>();
    dinv_kernel<<<128, 256>>>();
    vprep_kernel<<<dim3(64, 8), 256>>>();
    out_mma_kernel<<<dim3(32, 4, 8), 256, SMO_TOTAL>>>();
    reduce_kernel<<<2048, 256>>>(out);
}

// round 11
// speedup vs baseline: 3.5658x; 1.2110x over previous
#include <cuda_runtime.h>
#include <cuda_bf16.h>
#include <cstdint>

#define B_ 8
#define T_ 4096
#define CE 1024
#define HD 64
#define SCALE 0.125f

typedef unsigned long long u64;
typedef unsigned int u32;

// ---- device scratch (allocation-free) ----
__device__ __align__(16) float g_v[B_ * T_ * HD];
__device__ __align__(16) __nv_bfloat16 g_wth[3 * HD * CE];  // W^T hi [n][k]
__device__ __align__(16) __nv_bfloat16 g_wtl[3 * HD * CE];  // W^T lo
__device__ __align__(16) __nv_bfloat16 g_qh[B_ * T_ * HD];
__device__ __align__(16) __nv_bfloat16 g_ql[B_ * T_ * HD];
__device__ __align__(16) __nv_bfloat16 g_kh[B_ * T_ * HD];
__device__ __align__(16) __nv_bfloat16 g_kl[B_ * T_ * HD];
__device__ __align__(16) __nv_bfloat16 g_eh[(size_t)B_ * T_ * T_];
__device__ __align__(16) __nv_bfloat16 g_el[(size_t)B_ * T_ * T_];
__device__ __align__(16) __nv_bfloat16 g_vth[B_ * HD * T_];
__device__ __align__(16) __nv_bfloat16 g_vtl[B_ * HD * T_];
__device__ __align__(16) float g_dp[B_ * 32 * T_];
__device__ __align__(16) float g_dinv[B_ * T_];
__device__ __align__(16) float g_op[4 * B_ * T_ * HD];

__device__ __forceinline__ float fast_exp(float x) {
    float y = x * 1.4426950408889634f;
    float n = rintf(y);
    float f = y - n;
    float p = 1.3333558146e-3f;
    p = fmaf(p, f, 9.6181291076e-3f);
    p = fmaf(p, f, 5.5504108664e-2f);
    p = fmaf(p, f, 2.4022650696e-1f);
    p = fmaf(p, f, 6.9314718056e-1f);
    p = fmaf(p, f, 1.0f);
    return p * __int_as_float(((int)n + 127) << 23);
}

// ---- warp MMA helpers ----
__device__ __forceinline__ u32 s2u(const void* p) {
    u32 a;
    asm("{ .reg .u64 t; cvta.to.shared.u64 t, %1; cvt.u32.u64 %0, t; }"
        : "=r"(a) : "l"(p));
    return a;
}
__device__ __forceinline__ void ldsm4(u32* r, u32 addr) {
    asm volatile("ldmatrix.sync.aligned.m8n8.x4.shared.b16 {%0,%1,%2,%3}, [%4];"
                 : "=r"(r[0]), "=r"(r[1]), "=r"(r[2]), "=r"(r[3]) : "r"(addr));
}
__device__ __forceinline__ void mma16816(float* d, const u32* a, const u32* b) {
    asm volatile(
        "mma.sync.aligned.m16n8k16.row.col.f32.bf16.bf16.f32 "
        "{%0,%1,%2,%3}, {%4,%5,%6,%7}, {%8,%9}, {%0,%1,%2,%3};"
        : "+f"(d[0]), "+f"(d[1]), "+f"(d[2]), "+f"(d[3])
        : "r"(a[0]), "r"(a[1]), "r"(a[2]), "r"(a[3]), "r"(b[0]), "r"(b[1]));
}
__device__ __forceinline__ void bfsplit(float v, __nv_bfloat16& h, __nv_bfloat16& l) {
    h = __float2bfloat16(v);
    l = __float2bfloat16(v - __bfloat162float(h));
}

// ---------------------------------------------------------------------------
// Pass 0: transpose+split W into [n=192][k=1024] bf16 hi/lo
// ---------------------------------------------------------------------------
__global__ __launch_bounds__(256) void wsplit_kernel(
    const float* __restrict__ Wq, const float* __restrict__ Wk,
    const float* __restrict__ Wv) {
    int i = blockIdx.x * 256 + threadIdx.x;
    int n = i >> 10, k = i & 1023;
    const float* W = (n < 64) ? Wq : (n < 128) ? Wk : Wv;
    float v = W[k * HD + (n & 63)];
    __nv_bfloat16 h, l;
    bfsplit(v, h, l);
    g_wth[i] = h;
    g_wtl[i] = l;
}

// ---------------------------------------------------------------------------
// Pass 1: proj via mma.sync bf16x3 with FUSED x fp32->bf16 hi/lo staging.
// grid (3 ntiles, 256 mtiles) so q/k/v of one m-tile share x via L2.
// ---------------------------------------------------------------------------
#define PXH 0
#define PXL (128 * 144)
#define PWH (2 * 128 * 144)
#define PWL (PWH + 64 * 144)
#define SMP_TOTAL (PWL + 64 * 144)

__global__ __launch_bounds__(256) void proj_mma_kernel(const float* __restrict__ x) {
    extern __shared__ __align__(16) char smem[];
    int ntile = blockIdx.x, m0 = blockIdx.y << 7;
    int t = threadIdx.x, wid = t >> 5, lane = t & 31;
    int qw = wid >> 1, hw = wid & 1;
    u32 sb = s2u(smem);

    float acc[2][4][4] = {};
#pragma unroll 1
    for (int kc = 0; kc < 16; kc++) {
        int k0 = kc << 6;
        __syncthreads();
        // stage x chunk with inline fp32 -> bf16 hi/lo split
#pragma unroll
        for (int rep = 0; rep < 8; rep++) {
            int li = rep * 256 + t;          // 0..2047: 128 rows x 16 float4
            int row = li >> 4, c4 = li & 15;
            float4 v = *(const float4*)&x[(size_t)(m0 + row) * CE + k0 + c4 * 4];
            __nv_bfloat16 h0, h1, h2, h3, l0, l1, l2, l3;
            bfsplit(v.x, h0, l0); bfsplit(v.y, h1, l1);
            bfsplit(v.z, h2, l2); bfsplit(v.w, h3, l3);
            *(ushort4*)(smem + PXH + row * 144 + c4 * 8) =
                make_ushort4(__bfloat16_as_ushort(h0), __bfloat16_as_ushort(h1),
                             __bfloat16_as_ushort(h2), __bfloat16_as_ushort(h3));
            *(ushort4*)(smem + PXL + row * 144 + c4 * 8) =
                make_ushort4(__bfloat16_as_ushort(l0), __bfloat16_as_ushort(l1),
                             __bfloat16_as_ushort(l2), __bfloat16_as_ushort(l3));
        }
        // stage W^T hi/lo chunk: 64 n-rows x 64 k
#pragma unroll
        for (int rep = 0; rep < 2; rep++) {
            int li = rep * 256 + t;
            int row = li >> 3, c16 = li & 7;
            size_t gsrc = (size_t)(ntile * 64 + row) * CE + k0 + c16 * 8;
            *(uint4*)(smem + PWH + row * 144 + c16 * 16) =
                *(const uint4*)&g_wth[gsrc];
            *(uint4*)(smem + PWL + row * 144 + c16 * 16) =
                *(const uint4*)&g_wtl[gsrc];
        }
        __syncthreads();

#pragma unroll
        for (int kk = 0; kk < 4; kk++) {
            u32 ah[2][4], al[2][4];
#pragma unroll
            for (int tq = 0; tq < 2; tq++) {
                u32 aoff = (u32)((qw * 32 + tq * 16 + (lane & 15)) * 144 +
                                 (kk * 16 + ((lane >> 4) << 3)) * 2);
                ldsm4(ah[tq], sb + PXH + aoff);
                ldsm4(al[tq], sb + PXL + aoff);
            }
            u32 bh[2][4], bl[2][4];
#pragma unroll
            for (int ng = 0; ng < 2; ng++) {
                u32 roff = (u32)((hw * 32 + ng * 16 + (lane & 7) +
                                  ((lane & 16) ? 8 : 0)) * 144 +
                                 (kk * 16 + ((lane & 8) ? 8 : 0)) * 2);
                ldsm4(bh[ng], sb + PWH + roff);
                ldsm4(bl[ng], sb + PWL + roff);
            }
#pragma unroll
            for (int tq = 0; tq < 2; tq++)
#pragma unroll
                for (int nt = 0; nt < 4; nt++) {
                    int ng = nt >> 1, hf = (nt & 1) << 1;
                    mma16816(acc[tq][nt], ah[tq], bh[ng] + hf);
                    mma16816(acc[tq][nt], ah[tq], bl[ng] + hf);
                    mma16816(acc[tq][nt], al[tq], bh[ng] + hf);
                }
        }
    }

    int g = lane >> 2, tp = (lane & 3) << 1;
#pragma unroll
    for (int tq = 0; tq < 2; tq++) {
        int mA = m0 + qw * 32 + tq * 16 + g;
        int mB = mA + 8;
#pragma unroll
        for (int nt = 0; nt < 4; nt++) {
            int h = hw * 32 + nt * 8 + tp;
            float v0 = acc[tq][nt][0], v1 = acc[tq][nt][1];
            float v2 = acc[tq][nt][2], v3 = acc[tq][nt][3];
            if (ntile == 2) {
                *(float2*)&g_v[(size_t)mA * HD + h] = make_float2(v0, v1);
                *(float2*)&g_v[(size_t)mB * HD + h] = make_float2(v2, v3);
            } else {
                if (ntile == 0) {
                    v0 *= SCALE; v1 *= SCALE; v2 *= SCALE; v3 *= SCALE;
                }
                __nv_bfloat16* gh = (ntile == 0) ? g_qh : g_kh;
                __nv_bfloat16* gl = (ntile == 0) ? g_ql : g_kl;
                __nv_bfloat162 hA = __floats2bfloat162_rn(v0, v1);
                __nv_bfloat162 hB = __floats2bfloat162_rn(v2, v3);
                __nv_bfloat162 lA = __floats2bfloat162_rn(
                    v0 - __bfloat162float(hA.x), v1 - __bfloat162float(hA.y));
                __nv_bfloat162 lB = __floats2bfloat162_rn(
                    v2 - __bfloat162float(hB.x), v3 - __bfloat162float(hB.y));
                *(__nv_bfloat162*)&gh[(size_t)mA * HD + h] = hA;
                *(__nv_bfloat162*)&gh[(size_t)mB * HD + h] = hB;
                *(__nv_bfloat162*)&gl[(size_t)mA * HD + h] = lA;
                *(__nv_bfloat162*)&gl[(size_t)mB * HD + h] = lB;
            }
        }
    }
}

// ---------------------------------------------------------------------------
// Pass 2: score. Fragment-shared 3-combo mainloop (12 ldsm / 48 mma per kk),
// smem-staged coalesced E stores, triangular grid (528, 8).
// ---------------------------------------------------------------------------
#define OQH 0
#define OQL (128 * 144)
#define OKH (2 * 128 * 144)
#define OKL (3 * 128 * 144)
#define OBUF (4 * 128 * 144)
#define SMM_TOTAL (OBUF + 4 * 128 * 4)
#define EPITCH 272                      // 136 bf16 per row

__global__ __launch_bounds__(256) void score_mma_kernel() {
    extern __shared__ __align__(16) char smem[];
    int b = blockIdx.y;
    int ti = blockIdx.x;
    int qt = (int)((sqrtf(8.f * (float)ti + 1.f) - 1.f) * 0.5f);
    while ((qt + 1) * (qt + 2) / 2 <= ti) qt++;
    while (qt * (qt + 1) / 2 > ti) qt--;
    int kt = ti - qt * (qt + 1) / 2;
    int q0 = qt << 7, k0 = kt << 7;
    int t = threadIdx.x, wid = t >> 5, lane = t & 31;

    {
        const __nv_bfloat16* gsrc[4] = {
            g_qh + (size_t)(b * T_ + q0) * HD, g_ql + (size_t)(b * T_ + q0) * HD,
            g_kh + (size_t)(b * T_ + k0) * HD, g_kl + (size_t)(b * T_ + k0) * HD};
        const int obase[4] = {OQH, OQL, OKH, OKL};
#pragma unroll
        for (int rep = 0; rep < 2; rep++) {
            int li = rep * 256 + t;
            int a = li >> 7, row = li & 127;
            const uint4* s = (const uint4*)(gsrc[a] + (size_t)row * HD);
            uint4* d = (uint4*)(smem + obase[a] + row * 144);
#pragma unroll
            for (int c = 0; c < 8; c++) d[c] = s[c];
        }
    }
    __syncthreads();

    int qw = wid >> 1, kw = wid & 1;
    u32 sb = s2u(smem);
    float acc[2][8][4] = {};

#pragma unroll
    for (int kk = 0; kk < 4; kk++) {
        u32 ah[2][4], al[2][4];
#pragma unroll
        for (int tq = 0; tq < 2; tq++) {
            u32 aoff = (u32)((qw * 32 + tq * 16 + (lane & 15)) * 144 +
                             (kk * 16 + ((lane >> 4) << 3)) * 2);
            ldsm4(ah[tq], sb + OQH + aoff);
            ldsm4(al[tq], sb + OQL + aoff);
        }
        u32 bh[4][4], bl[4][4];
#pragma unroll
        for (int ng = 0; ng < 4; ng++) {
            u32 roff = (u32)((kw * 64 + ng * 16 + (lane & 7) +
                              ((lane & 16) ? 8 : 0)) * 144 +
                             (kk * 16 + ((lane & 8) ? 8 : 0)) * 2);
            ldsm4(bh[ng], sb + OKH + roff);
            ldsm4(bl[ng], sb + OKL + roff);
        }
#pragma unroll
        for (int tq = 0; tq < 2; tq++)
#pragma unroll
            for (int ng = 0; ng < 4; ng++)
#pragma unroll
                for (int hf = 0; hf < 2; hf++) {
                    float* d = acc[tq][ng * 2 + hf];
                    mma16816(d, ah[tq], bh[ng] + hf * 2);
                    mma16816(d, ah[tq], bl[ng] + hf * 2);
                    mma16816(d, al[tq], bh[ng] + hf * 2);
                }
    }

    // all staging reads done -> reuse staging smem for E tile
    __syncthreads();

    char* ehs = smem;                    // 128 x EPITCH (hi)
    char* els = smem + 128 * EPITCH;     // 128 x EPITCH (lo)
    int g = lane >> 2, tp = (lane & 3) << 1;
    bool diag = (kt == qt);
    float cs[8][2] = {};
#pragma unroll
    for (int tq = 0; tq < 2; tq++) {
        int rA = qw * 32 + tq * 16 + g;
        int rB = rA + 8;
#pragma unroll
        for (int nt = 0; nt < 8; nt++) {
            int col = kw * 64 + nt * 8 + tp;
            float e0 = fast_exp(acc[tq][nt][0]);
            float e1 = fast_exp(acc[tq][nt][1]);
            float e2 = fast_exp(acc[tq][nt][2]);
            float e3 = fast_exp(acc[tq][nt][3]);
            if (diag) {
                if (q0 + rA < k0 + col) e0 = 0.f;
                if (q0 + rA < k0 + col + 1) e1 = 0.f;
                if (q0 + rB < k0 + col) e2 = 0.f;
                if (q0 + rB < k0 + col + 1) e3 = 0.f;
            }
            __nv_bfloat162 hA = __floats2bfloat162_rn(e0, e1);
            __nv_bfloat162 hB = __floats2bfloat162_rn(e2, e3);
            __nv_bfloat162 lA = __floats2bfloat162_rn(
                e0 - __bfloat162float(hA.x), e1 - __bfloat162float(hA.y));
            __nv_bfloat162 lB = __floats2bfloat162_rn(
                e2 - __bfloat162float(hB.x), e3 - __bfloat162float(hB.y));
            *(__nv_bfloat162*)(ehs + rA * EPITCH + col * 2) = hA;
            *(__nv_bfloat162*)(ehs + rB * EPITCH + col * 2) = hB;
            *(__nv_bfloat162*)(els + rA * EPITCH + col * 2) = lA;
            *(__nv_bfloat162*)(els + rB * EPITCH + col * 2) = lB;
            cs[nt][0] += e0 + e2;
            cs[nt][1] += e1 + e3;
        }
    }
#pragma unroll
    for (int nt = 0; nt < 8; nt++)
#pragma unroll
        for (int j = 0; j < 2; j++) {
            float v = cs[nt][j];
            v += __shfl_xor_sync(0xffffffffu, v, 4);
            v += __shfl_xor_sync(0xffffffffu, v, 8);
            v += __shfl_xor_sync(0xffffffffu, v, 16);
            cs[nt][j] = v;
        }
    float* buf = (float*)(smem + OBUF);
    if (lane < 4) {
#pragma unroll
        for (int nt = 0; nt < 8; nt++) {
            buf[qw * 128 + kw * 64 + nt * 8 + ((lane & 3) << 1) + 0] = cs[nt][0];
            buf[qw * 128 + kw * 64 + nt * 8 + ((lane & 3) << 1) + 1] = cs[nt][1];
        }
    }
    __syncthreads();

    // coalesced E copy-out (128B rows) + dp
    size_t gbase = (size_t)b * T_ * T_ + (size_t)q0 * T_ + k0;
#pragma unroll
    for (int rep = 0; rep < 8; rep++) {
        int li = rep * 256 + t;
        int row = li >> 4, c16 = li & 15;
        size_t goff = gbase + (size_t)row * T_ + c16 * 8;
        *(uint4*)&g_eh[goff] = *(const uint4*)(ehs + row * EPITCH + c16 * 16);
        *(uint4*)&g_el[goff] = *(const uint4*)(els + row * EPITCH + c16 * 16);
    }
    if (t < 128) {
        float s = buf[t] + buf[128 + t] + buf[256 + t] + buf[384 + t];
        g_dp[(size_t)((b << 5) + qt) * T_ + k0 + t] = s;
    }
}

// ---------------------------------------------------------------------------
// Pass 3: d[k] -> reciprocal
// ---------------------------------------------------------------------------
__global__ void dinv_kernel() {
    int i = blockIdx.x * 256 + threadIdx.x;
    int b = i >> 12, k = i & 4095;
    float s = 0.f;
    for (int qt = (k >> 7); qt < 32; qt++)
        s += g_dp[(size_t)((b << 5) + qt) * T_ + k];
    g_dinv[i] = 1.0f / s;
}

// ---------------------------------------------------------------------------
// Pass 3b: Vt = (V*dinv)^T in bf16 hi/lo, [b][h][k] layout
// ---------------------------------------------------------------------------
__global__ __launch_bounds__(256) void vprep_kernel() {
    __shared__ __align__(16) float Vt[64][68];
    int k0 = blockIdx.x << 6, b = blockIdx.y;
    int t = threadIdx.x;
    {
        int k = t >> 2, hseg = (t & 3) << 4;
        float dinv = g_dinv[(b << 12) + k0 + k];
        const float* src = &g_v[(size_t)(b * T_ + k0 + k) * HD + hseg];
#pragma unroll
        for (int u = 0; u < 4; u++) {
            float4 v = *(const float4*)&src[u * 4];
            Vt[hseg + u * 4 + 0][k] = v.x * dinv;
            Vt[hseg + u * 4 + 1][k] = v.y * dinv;
            Vt[hseg + u * 4 + 2][k] = v.z * dinv;
            Vt[hseg + u * 4 + 3][k] = v.w * dinv;
        }
    }
    __syncthreads();
    {
        int h = t >> 2, kseg = (t & 3) << 4;
        ushort4 hh[4], ll[4];
#pragma unroll
        for (int u = 0; u < 4; u++) {
            unsigned short hv[4], lv[4];
#pragma unroll
            for (int e = 0; e < 4; e++) {
                float v = Vt[h][kseg + u * 4 + e];
                __nv_bfloat16 hb, lb;
                bfsplit(v, hb, lb);
                hv[e] = __bfloat16_as_ushort(hb);
                lv[e] = __bfloat16_as_ushort(lb);
            }
            hh[u] = make_ushort4(hv[0], hv[1], hv[2], hv[3]);
            ll[u] = make_ushort4(lv[0], lv[1], lv[2], lv[3]);
        }
        size_t dst = (size_t)(b * HD + h) * T_ + k0 + kseg;
#pragma unroll
        for (int u = 0; u < 4; u++) {
            *(ushort4*)&g_vth[dst + u * 4] = hh[u];
            *(ushort4*)&g_vtl[dst + u * 4] = ll[u];
        }
    }
}

// ---------------------------------------------------------------------------
// Pass 4: out via mma.sync 3-pass: O = Eh@Vh + Eh@Vl + El@Vh
// ---------------------------------------------------------------------------
#define OEH 0
#define OEL (128 * 144)
#define OVH (2 * 128 * 144)
#define OVL (OVH + 64 * 144)
#define SMO_TOTAL (OVL + 64 * 144)

__global__ __launch_bounds__(256) void out_mma_kernel() {
    extern __shared__ __align__(16) char smem[];
    int qt = blockIdx.x, s = blockIdx.y, b = blockIdx.z;
    int q0 = qt << 7;
    int nch = 2 * qt + 2;
    int lo = (s * nch) >> 2, hi = ((s + 1) * nch) >> 2;
    int t = threadIdx.x, wid = t >> 5, lane = t & 31;
    int qw = wid >> 1, hw = wid & 1;
    u32 sb = s2u(smem);

    float acc[2][4][4] = {};
    for (int c = lo; c < hi; c++) {
        int k0 = c << 6;
        __syncthreads();
#pragma unroll
        for (int rep = 0; rep < 4; rep++) {
            int li = rep * 256 + t;
            int row = li >> 3, c16 = li & 7;
            size_t gsrc = ((size_t)(b * T_ + q0 + row)) * T_ + k0 + c16 * 8;
            *(uint4*)(smem + OEH + row * 144 + c16 * 16) =
                *(const uint4*)&g_eh[gsrc];
            *(uint4*)(smem + OEL + row * 144 + c16 * 16) =
                *(const uint4*)&g_el[gsrc];
        }
#pragma unroll
        for (int rep = 0; rep < 2; rep++) {
            int li = rep * 256 + t;
            int row = li >> 3, c16 = li & 7;
            size_t gsrc = (size_t)(b * HD + row) * T_ + k0 + c16 * 8;
            *(uint4*)(smem + OVH + row * 144 + c16 * 16) =
                *(const uint4*)&g_vth[gsrc];
            *(uint4*)(smem + OVL + row * 144 + c16 * 16) =
                *(const uint4*)&g_vtl[gsrc];
        }
        __syncthreads();

#pragma unroll
        for (int kk = 0; kk < 4; kk++) {
            u32 ah[2][4], al[2][4];
#pragma unroll
            for (int tq = 0; tq < 2; tq++) {
                u32 aoff = (u32)((qw * 32 + tq * 16 + (lane & 15)) * 144 +
                                 (kk * 16 + ((lane >> 4) << 3)) * 2);
                ldsm4(ah[tq], sb + OEH + aoff);
                ldsm4(al[tq], sb + OEL + aoff);
            }
            u32 bh[2][4], bl[2][4];
#pragma unroll
            for (int ng = 0; ng < 2; ng++) {
                u32 roff = (u32)((hw * 32 + ng * 16 + (lane & 7) +
                                  ((lane & 16) ? 8 : 0)) * 144 +
                                 (kk * 16 + ((lane & 8) ? 8 : 0)) * 2);
                ldsm4(bh[ng], sb + OVH + roff);
                ldsm4(bl[ng], sb + OVL + roff);
            }
#pragma unroll
            for (int tq = 0; tq < 2; tq++)
#pragma unroll
                for (int nt = 0; nt < 4; nt++) {
                    int ng = nt >> 1, hf = (nt & 1) << 1;
                    mma16816(acc[tq][nt], ah[tq], bh[ng] + hf);
                    mma16816(acc[tq][nt], ah[tq], bl[ng] + hf);
                    mma16816(acc[tq][nt], al[tq], bh[ng] + hf);
                }
        }
    }

    int g = lane >> 2, tp = (lane & 3) << 1;
#pragma unroll
    for (int tq = 0; tq < 2; tq++) {
        int qrA = q0 + qw * 32 + tq * 16 + g;
#pragma unroll
        for (int nt = 0; nt < 4; nt++) {
            int h = hw * 32 + nt * 8 + tp;
            size_t base = (size_t)((s * B_ + b) * T_);
            *(float2*)&g_op[(base + qrA) * HD + h] =
                make_float2(acc[tq][nt][0], acc[tq][nt][1]);
            *(float2*)&g_op[(base + qrA + 8) * HD + h] =
                make_float2(acc[tq][nt][2], acc[tq][nt][3]);
        }
    }
}

// ---------------------------------------------------------------------------
// Pass 5: sum 4 split partials
// ---------------------------------------------------------------------------
__global__ void reduce_kernel(float* __restrict__ out) {
    const int N4 = B_ * T_ * HD / 4;
    int i = blockIdx.x * 256 + threadIdx.x;
    const float4* p = (const float4*)g_op;
    float4 a = p[i], b = p[i + N4], c = p[i + 2 * N4], d = p[i + 3 * N4];
    ((float4*)out)[i] = make_float4(a.x + b.x + c.x + d.x,
                                    a.y + b.y + c.y + d.y,
                                    a.z + b.z + c.z + d.z,
                                    a.w + b.w + c.w + d.w);
}

// ---------------------------------------------------------------------------
// inputs: x, Wk, Wq, Wv ; output fp32 [8,4096,64]
// ---------------------------------------------------------------------------
extern "C" void kernel_launch(void* const* d_in, const int* in_sizes, int n_in,
                              void* d_out, int out_size) {
    const float* x  = (const float*)d_in[0];
    const float* Wk = (const float*)d_in[1];
    const float* Wq = (const float*)d_in[2];
    const float* Wv = (const float*)d_in[3];
    float* out = (float*)d_out;

    cudaFuncSetAttribute(proj_mma_kernel,
        cudaFuncAttributeMaxDynamicSharedMemorySize, SMP_TOTAL);
    cudaFuncSetAttribute(score_mma_kernel,
        cudaFuncAttributeMaxDynamicSharedMemorySize, SMM_TOTAL);
    cudaFuncSetAttribute(out_mma_kernel,
        cudaFuncAttributeMaxDynamicSharedMemorySize, SMO_TOTAL);

    wsplit_kernel<<<768, 256>>>(Wq, Wk, Wv);
    proj_mma_kernel<<<dim3(3, 256), 256, SMP_TOTAL>>>(x);
    score_mma_kernel<<<dim3(528, 8), 256, SMM_TOTAL>>>();
    dinv_kernel<<<128, 256>>>();
    vprep_kernel<<<dim3(64, 8), 256>>>();
    out_mma_kernel<<<dim3(32, 4, 8), 256, SMO_TOTAL>>>();
    reduce_kernel<<<2048, 256>>>(out);
}

// round 12
// speedup vs baseline: 3.8949x; 1.0923x over previous
#include <cuda_runtime.h>
#include <cuda_bf16.h>
#include <cuda_fp16.h>
#include <cstdint>

#define B_ 8
#define T_ 4096
#define CE 1024
#define HD 64
#define SCALE 0.125f

typedef unsigned long long u64;
typedef unsigned int u32;

// ---- device scratch (allocation-free) ----
__device__ __align__(16) float g_v[B_ * T_ * HD];
__device__ __align__(16) __nv_bfloat16 g_wth[3 * HD * CE];  // W^T hi [n][k]
__device__ __align__(16) __nv_bfloat16 g_wtl[3 * HD * CE];  // W^T lo
__device__ __align__(16) __nv_bfloat16 g_qh[B_ * T_ * HD];
__device__ __align__(16) __nv_bfloat16 g_ql[B_ * T_ * HD];
__device__ __align__(16) __nv_bfloat16 g_kh[B_ * T_ * HD];
__device__ __align__(16) __nv_bfloat16 g_kl[B_ * T_ * HD];
__device__ __align__(16) __half g_ef[(size_t)B_ * T_ * T_];  // E fp16
__device__ __align__(16) __half g_vth[B_ * HD * T_];         // (V*dinv)^T hi fp16
__device__ __align__(16) __half g_vtl[B_ * HD * T_];         // (V*dinv)^T lo fp16
__device__ __align__(16) float g_dp[B_ * 32 * T_];
__device__ __align__(16) float g_dinv[B_ * T_];
__device__ __align__(16) float g_op[4 * B_ * T_ * HD];

__device__ __forceinline__ float fast_exp(float x) {
    float y = x * 1.4426950408889634f;
    float n = rintf(y);
    float f = y - n;
    float p = 1.3333558146e-3f;
    p = fmaf(p, f, 9.6181291076e-3f);
    p = fmaf(p, f, 5.5504108664e-2f);
    p = fmaf(p, f, 2.4022650696e-1f);
    p = fmaf(p, f, 6.9314718056e-1f);
    p = fmaf(p, f, 1.0f);
    return p * __int_as_float(((int)n + 127) << 23);
}

// ---- warp MMA helpers ----
__device__ __forceinline__ u32 s2u(const void* p) {
    u32 a;
    asm("{ .reg .u64 t; cvta.to.shared.u64 t, %1; cvt.u32.u64 %0, t; }"
        : "=r"(a) : "l"(p));
    return a;
}
__device__ __forceinline__ void ldsm4(u32* r, u32 addr) {
    asm volatile("ldmatrix.sync.aligned.m8n8.x4.shared.b16 {%0,%1,%2,%3}, [%4];"
                 : "=r"(r[0]), "=r"(r[1]), "=r"(r[2]), "=r"(r[3]) : "r"(addr));
}
__device__ __forceinline__ void mma16816(float* d, const u32* a, const u32* b) {
    asm volatile(
        "mma.sync.aligned.m16n8k16.row.col.f32.bf16.bf16.f32 "
        "{%0,%1,%2,%3}, {%4,%5,%6,%7}, {%8,%9}, {%0,%1,%2,%3};"
        : "+f"(d[0]), "+f"(d[1]), "+f"(d[2]), "+f"(d[3])
        : "r"(a[0]), "r"(a[1]), "r"(a[2]), "r"(a[3]), "r"(b[0]), "r"(b[1]));
}
__device__ __forceinline__ void mma16816h(float* d, const u32* a, const u32* b) {
    asm volatile(
        "mma.sync.aligned.m16n8k16.row.col.f32.f16.f16.f32 "
        "{%0,%1,%2,%3}, {%4,%5,%6,%7}, {%8,%9}, {%0,%1,%2,%3};"
        : "+f"(d[0]), "+f"(d[1]), "+f"(d[2]), "+f"(d[3])
        : "r"(a[0]), "r"(a[1]), "r"(a[2]), "r"(a[3]), "r"(b[0]), "r"(b[1]));
}
__device__ __forceinline__ void bfsplit(float v, __nv_bfloat16& h, __nv_bfloat16& l) {
    h = __float2bfloat16(v);
    l = __float2bfloat16(v - __bfloat162float(h));
}

// ---------------------------------------------------------------------------
// Pass 0: transpose+split W into [n=192][k=1024] bf16 hi/lo
// ---------------------------------------------------------------------------
__global__ __launch_bounds__(256) void wsplit_kernel(
    const float* __restrict__ Wq, const float* __restrict__ Wk,
    const float* __restrict__ Wv) {
    int i = blockIdx.x * 256 + threadIdx.x;
    int n = i >> 10, k = i & 1023;
    const float* W = (n < 64) ? Wq : (n < 128) ? Wk : Wv;
    float v = W[k * HD + (n & 63)];
    __nv_bfloat16 h, l;
    bfsplit(v, h, l);
    g_wth[i] = h;
    g_wtl[i] = l;
}

// ---------------------------------------------------------------------------
// Pass 1: proj via mma.sync bf16x3 with fused x fp32->bf16 hi/lo staging.
// ---------------------------------------------------------------------------
#define PXH 0
#define PXL (128 * 144)
#define PWH (2 * 128 * 144)
#define PWL (PWH + 64 * 144)
#define SMP_TOTAL (PWL + 64 * 144)

__global__ __launch_bounds__(256) void proj_mma_kernel(const float* __restrict__ x) {
    extern __shared__ __align__(16) char smem[];
    int ntile = blockIdx.x, m0 = blockIdx.y << 7;
    int t = threadIdx.x, wid = t >> 5, lane = t & 31;
    int qw = wid >> 1, hw = wid & 1;
    u32 sb = s2u(smem);

    float acc[2][4][4] = {};
#pragma unroll 1
    for (int kc = 0; kc < 16; kc++) {
        int k0 = kc << 6;
        __syncthreads();
#pragma unroll
        for (int rep = 0; rep < 8; rep++) {
            int li = rep * 256 + t;
            int row = li >> 4, c4 = li & 15;
            float4 v = *(const float4*)&x[(size_t)(m0 + row) * CE + k0 + c4 * 4];
            __nv_bfloat16 h0, h1, h2, h3, l0, l1, l2, l3;
            bfsplit(v.x, h0, l0); bfsplit(v.y, h1, l1);
            bfsplit(v.z, h2, l2); bfsplit(v.w, h3, l3);
            *(ushort4*)(smem + PXH + row * 144 + c4 * 8) =
                make_ushort4(__bfloat16_as_ushort(h0), __bfloat16_as_ushort(h1),
                             __bfloat16_as_ushort(h2), __bfloat16_as_ushort(h3));
            *(ushort4*)(smem + PXL + row * 144 + c4 * 8) =
                make_ushort4(__bfloat16_as_ushort(l0), __bfloat16_as_ushort(l1),
                             __bfloat16_as_ushort(l2), __bfloat16_as_ushort(l3));
        }
#pragma unroll
        for (int rep = 0; rep < 2; rep++) {
            int li = rep * 256 + t;
            int row = li >> 3, c16 = li & 7;
            size_t gsrc = (size_t)(ntile * 64 + row) * CE + k0 + c16 * 8;
            *(uint4*)(smem + PWH + row * 144 + c16 * 16) =
                *(const uint4*)&g_wth[gsrc];
            *(uint4*)(smem + PWL + row * 144 + c16 * 16) =
                *(const uint4*)&g_wtl[gsrc];
        }
        __syncthreads();

#pragma unroll
        for (int kk = 0; kk < 4; kk++) {
            u32 ah[2][4], al[2][4];
#pragma unroll
            for (int tq = 0; tq < 2; tq++) {
                u32 aoff = (u32)((qw * 32 + tq * 16 + (lane & 15)) * 144 +
                                 (kk * 16 + ((lane >> 4) << 3)) * 2);
                ldsm4(ah[tq], sb + PXH + aoff);
                ldsm4(al[tq], sb + PXL + aoff);
            }
            u32 bh[2][4], bl[2][4];
#pragma unroll
            for (int ng = 0; ng < 2; ng++) {
                u32 roff = (u32)((hw * 32 + ng * 16 + (lane & 7) +
                                  ((lane & 16) ? 8 : 0)) * 144 +
                                 (kk * 16 + ((lane & 8) ? 8 : 0)) * 2);
                ldsm4(bh[ng], sb + PWH + roff);
                ldsm4(bl[ng], sb + PWL + roff);
            }
#pragma unroll
            for (int tq = 0; tq < 2; tq++)
#pragma unroll
                for (int nt = 0; nt < 4; nt++) {
                    int ng = nt >> 1, hf = (nt & 1) << 1;
                    mma16816(acc[tq][nt], ah[tq], bh[ng] + hf);
                    mma16816(acc[tq][nt], ah[tq], bl[ng] + hf);
                    mma16816(acc[tq][nt], al[tq], bh[ng] + hf);
                }
        }
    }

    int g = lane >> 2, tp = (lane & 3) << 1;
#pragma unroll
    for (int tq = 0; tq < 2; tq++) {
        int mA = m0 + qw * 32 + tq * 16 + g;
        int mB = mA + 8;
#pragma unroll
        for (int nt = 0; nt < 4; nt++) {
            int h = hw * 32 + nt * 8 + tp;
            float v0 = acc[tq][nt][0], v1 = acc[tq][nt][1];
            float v2 = acc[tq][nt][2], v3 = acc[tq][nt][3];
            if (ntile == 2) {
                *(float2*)&g_v[(size_t)mA * HD + h] = make_float2(v0, v1);
                *(float2*)&g_v[(size_t)mB * HD + h] = make_float2(v2, v3);
            } else {
                if (ntile == 0) {
                    v0 *= SCALE; v1 *= SCALE; v2 *= SCALE; v3 *= SCALE;
                }
                __nv_bfloat16* gh = (ntile == 0) ? g_qh : g_kh;
                __nv_bfloat16* gl = (ntile == 0) ? g_ql : g_kl;
                __nv_bfloat162 hA = __floats2bfloat162_rn(v0, v1);
                __nv_bfloat162 hB = __floats2bfloat162_rn(v2, v3);
                __nv_bfloat162 lA = __floats2bfloat162_rn(
                    v0 - __bfloat162float(hA.x), v1 - __bfloat162float(hA.y));
                __nv_bfloat162 lB = __floats2bfloat162_rn(
                    v2 - __bfloat162float(hB.x), v3 - __bfloat162float(hB.y));
                *(__nv_bfloat162*)&gh[(size_t)mA * HD + h] = hA;
                *(__nv_bfloat162*)&gh[(size_t)mB * HD + h] = hB;
                *(__nv_bfloat162*)&gl[(size_t)mA * HD + h] = lA;
                *(__nv_bfloat162*)&gl[(size_t)mB * HD + h] = lB;
            }
        }
    }
}

// ---------------------------------------------------------------------------
// Pass 2: score (bf16x3 mainloop). E stored as ONE fp16 plane; d sums use
// the fp16-rounded values (consistent-d). Coalesced smem-staged E stores.
// ---------------------------------------------------------------------------
#define OQH 0
#define OQL (128 * 144)
#define OKH (2 * 128 * 144)
#define OKL (3 * 128 * 144)
#define OBUF (4 * 128 * 144)
#define SMM_TOTAL (OBUF + 4 * 128 * 4)
#define EPITCH 272

__global__ __launch_bounds__(256) void score_mma_kernel() {
    extern __shared__ __align__(16) char smem[];
    int b = blockIdx.y;
    int ti = blockIdx.x;
    int qt = (int)((sqrtf(8.f * (float)ti + 1.f) - 1.f) * 0.5f);
    while ((qt + 1) * (qt + 2) / 2 <= ti) qt++;
    while (qt * (qt + 1) / 2 > ti) qt--;
    int kt = ti - qt * (qt + 1) / 2;
    int q0 = qt << 7, k0 = kt << 7;
    int t = threadIdx.x, wid = t >> 5, lane = t & 31;

    {
        const __nv_bfloat16* gsrc[4] = {
            g_qh + (size_t)(b * T_ + q0) * HD, g_ql + (size_t)(b * T_ + q0) * HD,
            g_kh + (size_t)(b * T_ + k0) * HD, g_kl + (size_t)(b * T_ + k0) * HD};
        const int obase[4] = {OQH, OQL, OKH, OKL};
#pragma unroll
        for (int rep = 0; rep < 2; rep++) {
            int li = rep * 256 + t;
            int a = li >> 7, row = li & 127;
            const uint4* s = (const uint4*)(gsrc[a] + (size_t)row * HD);
            uint4* d = (uint4*)(smem + obase[a] + row * 144);
#pragma unroll
            for (int c = 0; c < 8; c++) d[c] = s[c];
        }
    }
    __syncthreads();

    int qw = wid >> 1, kw = wid & 1;
    u32 sb = s2u(smem);
    float acc[2][8][4] = {};

#pragma unroll
    for (int kk = 0; kk < 4; kk++) {
        u32 ah[2][4], al[2][4];
#pragma unroll
        for (int tq = 0; tq < 2; tq++) {
            u32 aoff = (u32)((qw * 32 + tq * 16 + (lane & 15)) * 144 +
                             (kk * 16 + ((lane >> 4) << 3)) * 2);
            ldsm4(ah[tq], sb + OQH + aoff);
            ldsm4(al[tq], sb + OQL + aoff);
        }
        u32 bh[4][4], bl[4][4];
#pragma unroll
        for (int ng = 0; ng < 4; ng++) {
            u32 roff = (u32)((kw * 64 + ng * 16 + (lane & 7) +
                              ((lane & 16) ? 8 : 0)) * 144 +
                             (kk * 16 + ((lane & 8) ? 8 : 0)) * 2);
            ldsm4(bh[ng], sb + OKH + roff);
            ldsm4(bl[ng], sb + OKL + roff);
        }
#pragma unroll
        for (int tq = 0; tq < 2; tq++)
#pragma unroll
            for (int ng = 0; ng < 4; ng++)
#pragma unroll
                for (int hf = 0; hf < 2; hf++) {
                    float* d = acc[tq][ng * 2 + hf];
                    mma16816(d, ah[tq], bh[ng] + hf * 2);
                    mma16816(d, ah[tq], bl[ng] + hf * 2);
                    mma16816(d, al[tq], bh[ng] + hf * 2);
                }
    }

    __syncthreads();   // staging reads done; reuse smem for E tile

    char* efs = smem;                    // 128 x EPITCH (fp16 plane)
    int g = lane >> 2, tp = (lane & 3) << 1;
    bool diag = (kt == qt);
    float cs[8][2] = {};
#pragma unroll
    for (int tq = 0; tq < 2; tq++) {
        int rA = qw * 32 + tq * 16 + g;
        int rB = rA + 8;
#pragma unroll
        for (int nt = 0; nt < 8; nt++) {
            int col = kw * 64 + nt * 8 + tp;
            float e0 = fast_exp(acc[tq][nt][0]);
            float e1 = fast_exp(acc[tq][nt][1]);
            float e2 = fast_exp(acc[tq][nt][2]);
            float e3 = fast_exp(acc[tq][nt][3]);
            if (diag) {
                if (q0 + rA < k0 + col) e0 = 0.f;
                if (q0 + rA < k0 + col + 1) e1 = 0.f;
                if (q0 + rB < k0 + col) e2 = 0.f;
                if (q0 + rB < k0 + col + 1) e3 = 0.f;
            }
            __half2 hA = __floats2half2_rn(e0, e1);
            __half2 hB = __floats2half2_rn(e2, e3);
            *(__half2*)(efs + rA * EPITCH + col * 2) = hA;
            *(__half2*)(efs + rB * EPITCH + col * 2) = hB;
            cs[nt][0] += __half2float(hA.x) + __half2float(hB.x);
            cs[nt][1] += __half2float(hA.y) + __half2float(hB.y);
        }
    }
#pragma unroll
    for (int nt = 0; nt < 8; nt++)
#pragma unroll
        for (int j = 0; j < 2; j++) {
            float v = cs[nt][j];
            v += __shfl_xor_sync(0xffffffffu, v, 4);
            v += __shfl_xor_sync(0xffffffffu, v, 8);
            v += __shfl_xor_sync(0xffffffffu, v, 16);
            cs[nt][j] = v;
        }
    float* buf = (float*)(smem + OBUF);
    if (lane < 4) {
#pragma unroll
        for (int nt = 0; nt < 8; nt++) {
            buf[qw * 128 + kw * 64 + nt * 8 + ((lane & 3) << 1) + 0] = cs[nt][0];
            buf[qw * 128 + kw * 64 + nt * 8 + ((lane & 3) << 1) + 1] = cs[nt][1];
        }
    }
    __syncthreads();

    // coalesced E copy-out (256B rows)
    size_t gbase = (size_t)b * T_ * T_ + (size_t)q0 * T_ + k0;
#pragma unroll
    for (int rep = 0; rep < 8; rep++) {
        int li = rep * 256 + t;
        int row = li >> 4, c16 = li & 15;
        *(uint4*)&g_ef[gbase + (size_t)row * T_ + c16 * 8] =
            *(const uint4*)(efs + row * EPITCH + c16 * 16);
    }
    if (t < 128) {
        float s = buf[t] + buf[128 + t] + buf[256 + t] + buf[384 + t];
        g_dp[(size_t)((b << 5) + qt) * T_ + k0 + t] = s;
    }
}

// ---------------------------------------------------------------------------
// Pass 3: d[k] -> reciprocal
// ---------------------------------------------------------------------------
__global__ void dinv_kernel() {
    int i = blockIdx.x * 256 + threadIdx.x;
    int b = i >> 12, k = i & 4095;
    float s = 0.f;
    for (int qt = (k >> 7); qt < 32; qt++)
        s += g_dp[(size_t)((b << 5) + qt) * T_ + k];
    g_dinv[i] = 1.0f / s;
}

// ---------------------------------------------------------------------------
// Pass 3b: Vt = (V*dinv)^T in fp16 hi/lo, [b][h][k] layout
// ---------------------------------------------------------------------------
__global__ __launch_bounds__(256) void vprep_kernel() {
    __shared__ __align__(16) float Vt[64][68];
    int k0 = blockIdx.x << 6, b = blockIdx.y;
    int t = threadIdx.x;
    {
        int k = t >> 2, hseg = (t & 3) << 4;
        float dinv = g_dinv[(b << 12) + k0 + k];
        const float* src = &g_v[(size_t)(b * T_ + k0 + k) * HD + hseg];
#pragma unroll
        for (int u = 0; u < 4; u++) {
            float4 v = *(const float4*)&src[u * 4];
            Vt[hseg + u * 4 + 0][k] = v.x * dinv;
            Vt[hseg + u * 4 + 1][k] = v.y * dinv;
            Vt[hseg + u * 4 + 2][k] = v.z * dinv;
            Vt[hseg + u * 4 + 3][k] = v.w * dinv;
        }
    }
    __syncthreads();
    {
        int h = t >> 2, kseg = (t & 3) << 4;
        ushort4 hh[4], ll[4];
#pragma unroll
        for (int u = 0; u < 4; u++) {
            unsigned short hv[4], lv[4];
#pragma unroll
            for (int e = 0; e < 4; e++) {
                float v = Vt[h][kseg + u * 4 + e];
                __half hb = __float2half_rn(v);
                __half lb = __float2half_rn(v - __half2float(hb));
                hv[e] = __half_as_ushort(hb);
                lv[e] = __half_as_ushort(lb);
            }
            hh[u] = make_ushort4(hv[0], hv[1], hv[2], hv[3]);
            ll[u] = make_ushort4(lv[0], lv[1], lv[2], lv[3]);
        }
        size_t dst = (size_t)(b * HD + h) * T_ + k0 + kseg;
#pragma unroll
        for (int u = 0; u < 4; u++) {
            *(ushort4*)&g_vth[dst + u * 4] = hh[u];
            *(ushort4*)&g_vtl[dst + u * 4] = ll[u];
        }
    }
}

// ---------------------------------------------------------------------------
// Pass 4: out via f16 mma 2-pass: O = Ef@Vh + Ef@Vl
// ---------------------------------------------------------------------------
#define OEF 0
#define OVH (128 * 144)
#define OVL (OVH + 64 * 144)
#define SMO_TOTAL (OVL + 64 * 144)

__global__ __launch_bounds__(256) void out_mma_kernel() {
    extern __shared__ __align__(16) char smem[];
    int qt = blockIdx.x, s = blockIdx.y, b = blockIdx.z;
    int q0 = qt << 7;
    int nch = 2 * qt + 2;
    int lo = (s * nch) >> 2, hi = ((s + 1) * nch) >> 2;
    int t = threadIdx.x, wid = t >> 5, lane = t & 31;
    int qw = wid >> 1, hw = wid & 1;
    u32 sb = s2u(smem);

    float acc[2][4][4] = {};
    for (int c = lo; c < hi; c++) {
        int k0 = c << 6;
        __syncthreads();
#pragma unroll
        for (int rep = 0; rep < 4; rep++) {
            int li = rep * 256 + t;
            int row = li >> 3, c16 = li & 7;
            *(uint4*)(smem + OEF + row * 144 + c16 * 16) = *(const uint4*)
                &g_ef[((size_t)(b * T_ + q0 + row)) * T_ + k0 + c16 * 8];
        }
#pragma unroll
        for (int rep = 0; rep < 2; rep++) {
            int li = rep * 256 + t;
            int row = li >> 3, c16 = li & 7;
            size_t gsrc = (size_t)(b * HD + row) * T_ + k0 + c16 * 8;
            *(uint4*)(smem + OVH + row * 144 + c16 * 16) =
                *(const uint4*)&g_vth[gsrc];
            *(uint4*)(smem + OVL + row * 144 + c16 * 16) =
                *(const uint4*)&g_vtl[gsrc];
        }
        __syncthreads();

#pragma unroll
        for (int kk = 0; kk < 4; kk++) {
            u32 af[2][4];
#pragma unroll
            for (int tq = 0; tq < 2; tq++) {
                u32 aoff = (u32)((qw * 32 + tq * 16 + (lane & 15)) * 144 +
                                 (kk * 16 + ((lane >> 4) << 3)) * 2);
                ldsm4(af[tq], sb + OEF + aoff);
            }
            u32 bh[2][4], bl[2][4];
#pragma unroll
            for (int ng = 0; ng < 2; ng++) {
                u32 roff = (u32)((hw * 32 + ng * 16 + (lane & 7) +
                                  ((lane & 16) ? 8 : 0)) * 144 +
                                 (kk * 16 + ((lane & 8) ? 8 : 0)) * 2);
                ldsm4(bh[ng], sb + OVH + roff);
                ldsm4(bl[ng], sb + OVL + roff);
            }
#pragma unroll
            for (int tq = 0; tq < 2; tq++)
#pragma unroll
                for (int nt = 0; nt < 4; nt++) {
                    int ng = nt >> 1, hf = (nt & 1) << 1;
                    mma16816h(acc[tq][nt], af[tq], bh[ng] + hf);
                    mma16816h(acc[tq][nt], af[tq], bl[ng] + hf);
                }
        }
    }

    int g = lane >> 2, tp = (lane & 3) << 1;
#pragma unroll
    for (int tq = 0; tq < 2; tq++) {
        int qrA = q0 + qw * 32 + tq * 16 + g;
#pragma unroll
        for (int nt = 0; nt < 4; nt++) {
            int h = hw * 32 + nt * 8 + tp;
            size_t base = (size_t)((s * B_ + b) * T_);
            *(float2*)&g_op[(base + qrA) * HD + h] =
                make_float2(acc[tq][nt][0], acc[tq][nt][1]);
            *(float2*)&g_op[(base + qrA + 8) * HD + h] =
                make_float2(acc[tq][nt][2], acc[tq][nt][3]);
        }
    }
}

// ---------------------------------------------------------------------------
// Pass 5: sum 4 split partials
// ---------------------------------------------------------------------------
__global__ void reduce_kernel(float* __restrict__ out) {
    const int N4 = B_ * T_ * HD / 4;
    int i = blockIdx.x * 256 + threadIdx.x;
    const float4* p = (const float4*)g_op;
    float4 a = p[i], b = p[i + N4], c = p[i + 2 * N4], d = p[i + 3 * N4];
    ((float4*)out)[i] = make_float4(a.x + b.x + c.x + d.x,
                                    a.y + b.y + c.y + d.y,
                                    a.z + b.z + c.z + d.z,
                                    a.w + b.w + c.w + d.w);
}

// ---------------------------------------------------------------------------
// inputs: x, Wk, Wq, Wv ; output fp32 [8,4096,64]
// ---------------------------------------------------------------------------
extern "C" void kernel_launch(void* const* d_in, const int* in_sizes, int n_in,
                              void* d_out, int out_size) {
    const float* x  = (const float*)d_in[0];
    const float* Wk = (const float*)d_in[1];
    const float* Wq = (const float*)d_in[2];
    const float* Wv = (const float*)d_in[3];
    float* out = (float*)d_out;

    cudaFuncSetAttribute(proj_mma_kernel,
        cudaFuncAttributeMaxDynamicSharedMemorySize, SMP_TOTAL);
    cudaFuncSetAttribute(score_mma_kernel,
        cudaFuncAttributeMaxDynamicSharedMemorySize, SMM_TOTAL);
    cudaFuncSetAttribute(out_mma_kernel,
        cudaFuncAttributeMaxDynamicSharedMemorySize, SMO_TOTAL);

    wsplit_kernel<<<768, 256>>>(Wq, Wk, Wv);
    proj_mma_kernel<<<dim3(3, 256), 256, SMP_TOTAL>>>(x);
    score_mma_kernel<<<dim3(528, 8), 256, SMM_TOTAL>>>();
    dinv_kernel<<<128, 256>>>();
    vprep_kernel<<<dim3(64, 8), 256>>>();
    out_mma_kernel<<<dim3(32, 4, 8), 256, SMO_TOTAL>>>();
    reduce_kernel<<<2048, 256>>>(out);
}

// round 13
// speedup vs baseline: 4.5670x; 1.1726x over previous
#include <cuda_runtime.h>
#include <cuda_bf16.h>
#include <cuda_fp16.h>
#include <cstdint>

#define B_ 8
#define T_ 4096
#define CE 1024
#define HD 64
#define SCALE 0.125f

typedef unsigned long long u64;
typedef unsigned int u32;

// ---- device scratch (allocation-free) ----
__device__ __align__(16) float g_v[B_ * T_ * HD];
__device__ __align__(16) __nv_bfloat16 g_wth[3 * HD * CE];  // W^T hi [n][k]
__device__ __align__(16) __nv_bfloat16 g_wtl[3 * HD * CE];  // W^T lo
__device__ __align__(16) __half g_qh2[B_ * T_ * HD];        // q/8 fp16 hi
__device__ __align__(16) __half g_ql2[B_ * T_ * HD];        // q/8 fp16 lo
__device__ __align__(16) __half g_kf[B_ * T_ * HD];         // k fp16 single
__device__ __align__(16) __half g_ef[(size_t)B_ * T_ * T_]; // E fp16
__device__ __align__(16) __half g_vtf[B_ * HD * T_];        // (V*dinv)^T fp16
__device__ __align__(16) float g_dp[B_ * 32 * T_];
__device__ __align__(16) float g_dinv[B_ * T_];
__device__ __align__(16) float g_op[4 * B_ * T_ * HD];

__device__ __forceinline__ float fast_exp(float x) {
    float y = x * 1.4426950408889634f;
    float n = rintf(y);
    float f = y - n;
    float p = 1.3333558146e-3f;
    p = fmaf(p, f, 9.6181291076e-3f);
    p = fmaf(p, f, 5.5504108664e-2f);
    p = fmaf(p, f, 2.4022650696e-1f);
    p = fmaf(p, f, 6.9314718056e-1f);
    p = fmaf(p, f, 1.0f);
    return p * __int_as_float(((int)n + 127) << 23);
}

// ---- warp MMA helpers ----
__device__ __forceinline__ u32 s2u(const void* p) {
    u32 a;
    asm("{ .reg .u64 t; cvta.to.shared.u64 t, %1; cvt.u32.u64 %0, t; }"
        : "=r"(a) : "l"(p));
    return a;
}
__device__ __forceinline__ void ldsm4(u32* r, u32 addr) {
    asm volatile("ldmatrix.sync.aligned.m8n8.x4.shared.b16 {%0,%1,%2,%3}, [%4];"
                 : "=r"(r[0]), "=r"(r[1]), "=r"(r[2]), "=r"(r[3]) : "r"(addr));
}
__device__ __forceinline__ void mma16816(float* d, const u32* a, const u32* b) {
    asm volatile(
        "mma.sync.aligned.m16n8k16.row.col.f32.bf16.bf16.f32 "
        "{%0,%1,%2,%3}, {%4,%5,%6,%7}, {%8,%9}, {%0,%1,%2,%3};"
        : "+f"(d[0]), "+f"(d[1]), "+f"(d[2]), "+f"(d[3])
        : "r"(a[0]), "r"(a[1]), "r"(a[2]), "r"(a[3]), "r"(b[0]), "r"(b[1]));
}
__device__ __forceinline__ void mma16816h(float* d, const u32* a, const u32* b) {
    asm volatile(
        "mma.sync.aligned.m16n8k16.row.col.f32.f16.f16.f32 "
        "{%0,%1,%2,%3}, {%4,%5,%6,%7}, {%8,%9}, {%0,%1,%2,%3};"
        : "+f"(d[0]), "+f"(d[1]), "+f"(d[2]), "+f"(d[3])
        : "r"(a[0]), "r"(a[1]), "r"(a[2]), "r"(a[3]), "r"(b[0]), "r"(b[1]));
}
__device__ __forceinline__ void bfsplit(float v, __nv_bfloat16& h, __nv_bfloat16& l) {
    h = __float2bfloat16(v);
    l = __float2bfloat16(v - __bfloat162float(h));
}

// ---------------------------------------------------------------------------
// Pass 0: transpose+split W into [n=192][k=1024] bf16 hi/lo
// ---------------------------------------------------------------------------
__global__ __launch_bounds__(256) void wsplit_kernel(
    const float* __restrict__ Wq, const float* __restrict__ Wk,
    const float* __restrict__ Wv) {
    int i = blockIdx.x * 256 + threadIdx.x;
    int n = i >> 10, k = i & 1023;
    const float* W = (n < 64) ? Wq : (n < 128) ? Wk : Wv;
    float v = W[k * HD + (n & 63)];
    __nv_bfloat16 h, l;
    bfsplit(v, h, l);
    g_wth[i] = h;
    g_wtl[i] = l;
}

// ---------------------------------------------------------------------------
// Pass 1: proj via mma.sync bf16x3 with fused x staging.
// Epilogue: q/8 -> fp16 hi/lo; k -> fp16 single; v -> fp32.
// ---------------------------------------------------------------------------
#define PXH 0
#define PXL (128 * 144)
#define PWH (2 * 128 * 144)
#define PWL (PWH + 64 * 144)
#define SMP_TOTAL (PWL + 64 * 144)

__global__ __launch_bounds__(256) void proj_mma_kernel(const float* __restrict__ x) {
    extern __shared__ __align__(16) char smem[];
    int ntile = blockIdx.x, m0 = blockIdx.y << 7;
    int t = threadIdx.x, wid = t >> 5, lane = t & 31;
    int qw = wid >> 1, hw = wid & 1;
    u32 sb = s2u(smem);

    float acc[2][4][4] = {};
#pragma unroll 1
    for (int kc = 0; kc < 16; kc++) {
        int k0 = kc << 6;
        __syncthreads();
#pragma unroll
        for (int rep = 0; rep < 8; rep++) {
            int li = rep * 256 + t;
            int row = li >> 4, c4 = li & 15;
            float4 v = *(const float4*)&x[(size_t)(m0 + row) * CE + k0 + c4 * 4];
            __nv_bfloat16 h0, h1, h2, h3, l0, l1, l2, l3;
            bfsplit(v.x, h0, l0); bfsplit(v.y, h1, l1);
            bfsplit(v.z, h2, l2); bfsplit(v.w, h3, l3);
            *(ushort4*)(smem + PXH + row * 144 + c4 * 8) =
                make_ushort4(__bfloat16_as_ushort(h0), __bfloat16_as_ushort(h1),
                             __bfloat16_as_ushort(h2), __bfloat16_as_ushort(h3));
            *(ushort4*)(smem + PXL + row * 144 + c4 * 8) =
                make_ushort4(__bfloat16_as_ushort(l0), __bfloat16_as_ushort(l1),
                             __bfloat16_as_ushort(l2), __bfloat16_as_ushort(l3));
        }
#pragma unroll
        for (int rep = 0; rep < 2; rep++) {
            int li = rep * 256 + t;
            int row = li >> 3, c16 = li & 7;
            size_t gsrc = (size_t)(ntile * 64 + row) * CE + k0 + c16 * 8;
            *(uint4*)(smem + PWH + row * 144 + c16 * 16) =
                *(const uint4*)&g_wth[gsrc];
            *(uint4*)(smem + PWL + row * 144 + c16 * 16) =
                *(const uint4*)&g_wtl[gsrc];
        }
        __syncthreads();

#pragma unroll
        for (int kk = 0; kk < 4; kk++) {
            u32 ah[2][4], al[2][4];
#pragma unroll
            for (int tq = 0; tq < 2; tq++) {
                u32 aoff = (u32)((qw * 32 + tq * 16 + (lane & 15)) * 144 +
                                 (kk * 16 + ((lane >> 4) << 3)) * 2);
                ldsm4(ah[tq], sb + PXH + aoff);
                ldsm4(al[tq], sb + PXL + aoff);
            }
            u32 bh[2][4], bl[2][4];
#pragma unroll
            for (int ng = 0; ng < 2; ng++) {
                u32 roff = (u32)((hw * 32 + ng * 16 + (lane & 7) +
                                  ((lane & 16) ? 8 : 0)) * 144 +
                                 (kk * 16 + ((lane & 8) ? 8 : 0)) * 2);
                ldsm4(bh[ng], sb + PWH + roff);
                ldsm4(bl[ng], sb + PWL + roff);
            }
#pragma unroll
            for (int tq = 0; tq < 2; tq++)
#pragma unroll
                for (int nt = 0; nt < 4; nt++) {
                    int ng = nt >> 1, hf = (nt & 1) << 1;
                    mma16816(acc[tq][nt], ah[tq], bh[ng] + hf);
                    mma16816(acc[tq][nt], ah[tq], bl[ng] + hf);
                    mma16816(acc[tq][nt], al[tq], bh[ng] + hf);
                }
        }
    }

    int g = lane >> 2, tp = (lane & 3) << 1;
#pragma unroll
    for (int tq = 0; tq < 2; tq++) {
        int mA = m0 + qw * 32 + tq * 16 + g;
        int mB = mA + 8;
#pragma unroll
        for (int nt = 0; nt < 4; nt++) {
            int h = hw * 32 + nt * 8 + tp;
            float v0 = acc[tq][nt][0], v1 = acc[tq][nt][1];
            float v2 = acc[tq][nt][2], v3 = acc[tq][nt][3];
            if (ntile == 2) {
                *(float2*)&g_v[(size_t)mA * HD + h] = make_float2(v0, v1);
                *(float2*)&g_v[(size_t)mB * HD + h] = make_float2(v2, v3);
            } else if (ntile == 1) {
                *(__half2*)&g_kf[(size_t)mA * HD + h] = __floats2half2_rn(v0, v1);
                *(__half2*)&g_kf[(size_t)mB * HD + h] = __floats2half2_rn(v2, v3);
            } else {
                v0 *= SCALE; v1 *= SCALE; v2 *= SCALE; v3 *= SCALE;
                __half2 hA = __floats2half2_rn(v0, v1);
                __half2 hB = __floats2half2_rn(v2, v3);
                __half2 lA = __floats2half2_rn(
                    v0 - __half2float(hA.x), v1 - __half2float(hA.y));
                __half2 lB = __floats2half2_rn(
                    v2 - __half2float(hB.x), v3 - __half2float(hB.y));
                *(__half2*)&g_qh2[(size_t)mA * HD + h] = hA;
                *(__half2*)&g_qh2[(size_t)mB * HD + h] = hB;
                *(__half2*)&g_ql2[(size_t)mA * HD + h] = lA;
                *(__half2*)&g_ql2[(size_t)mB * HD + h] = lB;
            }
        }
    }
}

// ---------------------------------------------------------------------------
// Pass 2: score via f16 mma 2-pass (Qh·K + Ql·K). E -> one fp16 plane;
// d sums use fp16-rounded E (consistent-d). Coalesced smem-staged E stores.
// ---------------------------------------------------------------------------
#define OQH 0
#define OQL (128 * 144)
#define OKF (2 * 128 * 144)
#define OBUF (3 * 128 * 144)
#define SMM_TOTAL (OBUF + 4 * 128 * 4)   // 57344
#define EPITCH 272

__global__ __launch_bounds__(256) void score_mma_kernel() {
    extern __shared__ __align__(16) char smem[];
    int b = blockIdx.y;
    int ti = blockIdx.x;
    int qt = (int)((sqrtf(8.f * (float)ti + 1.f) - 1.f) * 0.5f);
    while ((qt + 1) * (qt + 2) / 2 <= ti) qt++;
    while (qt * (qt + 1) / 2 > ti) qt--;
    int kt = ti - qt * (qt + 1) / 2;
    int q0 = qt << 7, k0 = kt << 7;
    int t = threadIdx.x, wid = t >> 5, lane = t & 31;

    {
        const __half* gsrc[3] = {
            g_qh2 + (size_t)(b * T_ + q0) * HD,
            g_ql2 + (size_t)(b * T_ + q0) * HD,
            g_kf + (size_t)(b * T_ + k0) * HD};
        const int obase[3] = {OQH, OQL, OKF};
#pragma unroll
        for (int rep = 0; rep < 2; rep++) {
            int li = rep * 256 + t;
            if (li < 384) {
                int a = li >> 7, row = li & 127;
                const uint4* s = (const uint4*)(gsrc[a] + (size_t)row * HD);
                uint4* d = (uint4*)(smem + obase[a] + row * 144);
#pragma unroll
                for (int c = 0; c < 8; c++) d[c] = s[c];
            }
        }
    }
    __syncthreads();

    int qw = wid >> 1, kw = wid & 1;
    u32 sb = s2u(smem);
    float acc[2][8][4] = {};

#pragma unroll
    for (int kk = 0; kk < 4; kk++) {
        u32 ah[2][4], al[2][4];
#pragma unroll
        for (int tq = 0; tq < 2; tq++) {
            u32 aoff = (u32)((qw * 32 + tq * 16 + (lane & 15)) * 144 +
                             (kk * 16 + ((lane >> 4) << 3)) * 2);
            ldsm4(ah[tq], sb + OQH + aoff);
            ldsm4(al[tq], sb + OQL + aoff);
        }
        u32 bf[4][4];
#pragma unroll
        for (int ng = 0; ng < 4; ng++) {
            u32 roff = (u32)((kw * 64 + ng * 16 + (lane & 7) +
                              ((lane & 16) ? 8 : 0)) * 144 +
                             (kk * 16 + ((lane & 8) ? 8 : 0)) * 2);
            ldsm4(bf[ng], sb + OKF + roff);
        }
#pragma unroll
        for (int tq = 0; tq < 2; tq++)
#pragma unroll
            for (int ng = 0; ng < 4; ng++)
#pragma unroll
                for (int hf = 0; hf < 2; hf++) {
                    float* d = acc[tq][ng * 2 + hf];
                    mma16816h(d, ah[tq], bf[ng] + hf * 2);
                    mma16816h(d, al[tq], bf[ng] + hf * 2);
                }
    }

    __syncthreads();   // staging reads done; reuse smem for E tile

    char* efs = smem;                    // 128 x EPITCH (fp16 plane)
    int g = lane >> 2, tp = (lane & 3) << 1;
    bool diag = (kt == qt);
    float cs[8][2] = {};
#pragma unroll
    for (int tq = 0; tq < 2; tq++) {
        int rA = qw * 32 + tq * 16 + g;
        int rB = rA + 8;
#pragma unroll
        for (int nt = 0; nt < 8; nt++) {
            int col = kw * 64 + nt * 8 + tp;
            float e0 = fast_exp(acc[tq][nt][0]);
            float e1 = fast_exp(acc[tq][nt][1]);
            float e2 = fast_exp(acc[tq][nt][2]);
            float e3 = fast_exp(acc[tq][nt][3]);
            if (diag) {
                if (q0 + rA < k0 + col) e0 = 0.f;
                if (q0 + rA < k0 + col + 1) e1 = 0.f;
                if (q0 + rB < k0 + col) e2 = 0.f;
                if (q0 + rB < k0 + col + 1) e3 = 0.f;
            }
            __half2 hA = __floats2half2_rn(e0, e1);
            __half2 hB = __floats2half2_rn(e2, e3);
            *(__half2*)(efs + rA * EPITCH + col * 2) = hA;
            *(__half2*)(efs + rB * EPITCH + col * 2) = hB;
            cs[nt][0] += __half2float(hA.x) + __half2float(hB.x);
            cs[nt][1] += __half2float(hA.y) + __half2float(hB.y);
        }
    }
#pragma unroll
    for (int nt = 0; nt < 8; nt++)
#pragma unroll
        for (int j = 0; j < 2; j++) {
            float v = cs[nt][j];
            v += __shfl_xor_sync(0xffffffffu, v, 4);
            v += __shfl_xor_sync(0xffffffffu, v, 8);
            v += __shfl_xor_sync(0xffffffffu, v, 16);
            cs[nt][j] = v;
        }
    float* buf = (float*)(smem + OBUF);
    if (lane < 4) {
#pragma unroll
        for (int nt = 0; nt < 8; nt++) {
            buf[qw * 128 + kw * 64 + nt * 8 + ((lane & 3) << 1) + 0] = cs[nt][0];
            buf[qw * 128 + kw * 64 + nt * 8 + ((lane & 3) << 1) + 1] = cs[nt][1];
        }
    }
    __syncthreads();

    size_t gbase = (size_t)b * T_ * T_ + (size_t)q0 * T_ + k0;
#pragma unroll
    for (int rep = 0; rep < 8; rep++) {
        int li = rep * 256 + t;
        int row = li >> 4, c16 = li & 15;
        *(uint4*)&g_ef[gbase + (size_t)row * T_ + c16 * 8] =
            *(const uint4*)(efs + row * EPITCH + c16 * 16);
    }
    if (t < 128) {
        float s = buf[t] + buf[128 + t] + buf[256 + t] + buf[384 + t];
        g_dp[(size_t)((b << 5) + qt) * T_ + k0 + t] = s;
    }
}

// ---------------------------------------------------------------------------
// Pass 3: d[k] -> reciprocal
// ---------------------------------------------------------------------------
__global__ void dinv_kernel() {
    int i = blockIdx.x * 256 + threadIdx.x;
    int b = i >> 12, k = i & 4095;
    float s = 0.f;
    for (int qt = (k >> 7); qt < 32; qt++)
        s += g_dp[(size_t)((b << 5) + qt) * T_ + k];
    g_dinv[i] = 1.0f / s;
}

// ---------------------------------------------------------------------------
// Pass 3b: Vt = (V*dinv)^T single fp16 plane, [b][h][k]
// ---------------------------------------------------------------------------
__global__ __launch_bounds__(256) void vprep_kernel() {
    __shared__ __align__(16) float Vt[64][68];
    int k0 = blockIdx.x << 6, b = blockIdx.y;
    int t = threadIdx.x;
    {
        int k = t >> 2, hseg = (t & 3) << 4;
        float dinv = g_dinv[(b << 12) + k0 + k];
        const float* src = &g_v[(size_t)(b * T_ + k0 + k) * HD + hseg];
#pragma unroll
        for (int u = 0; u < 4; u++) {
            float4 v = *(const float4*)&src[u * 4];
            Vt[hseg + u * 4 + 0][k] = v.x * dinv;
            Vt[hseg + u * 4 + 1][k] = v.y * dinv;
            Vt[hseg + u * 4 + 2][k] = v.z * dinv;
            Vt[hseg + u * 4 + 3][k] = v.w * dinv;
        }
    }
    __syncthreads();
    {
        int h = t >> 2, kseg = (t & 3) << 4;
        size_t dst = (size_t)(b * HD + h) * T_ + k0 + kseg;
#pragma unroll
        for (int u = 0; u < 4; u++) {
            __half2 p0 = __floats2half2_rn(Vt[h][kseg + u * 4 + 0],
                                           Vt[h][kseg + u * 4 + 1]);
            __half2 p1 = __floats2half2_rn(Vt[h][kseg + u * 4 + 2],
                                           Vt[h][kseg + u * 4 + 3]);
            *(__half2*)&g_vtf[dst + u * 4 + 0] = p0;
            *(__half2*)&g_vtf[dst + u * 4 + 2] = p1;
        }
    }
}

// ---------------------------------------------------------------------------
// Pass 4: out via f16 mma single pass: O = Ef @ Vtf
// ---------------------------------------------------------------------------
#define OEF 0
#define OVF (128 * 144)
#define SMO_TOTAL (OVF + 64 * 144)   // 27648

__global__ __launch_bounds__(256) void out_mma_kernel() {
    extern __shared__ __align__(16) char smem[];
    int qt = blockIdx.x, s = blockIdx.y, b = blockIdx.z;
    int q0 = qt << 7;
    int nch = 2 * qt + 2;
    int lo = (s * nch) >> 2, hi = ((s + 1) * nch) >> 2;
    int t = threadIdx.x, wid = t >> 5, lane = t & 31;
    int qw = wid >> 1, hw = wid & 1;
    u32 sb = s2u(smem);

    float acc[2][4][4] = {};
    for (int c = lo; c < hi; c++) {
        int k0 = c << 6;
        __syncthreads();
#pragma unroll
        for (int rep = 0; rep < 4; rep++) {
            int li = rep * 256 + t;
            int row = li >> 3, c16 = li & 7;
            *(uint4*)(smem + OEF + row * 144 + c16 * 16) = *(const uint4*)
                &g_ef[((size_t)(b * T_ + q0 + row)) * T_ + k0 + c16 * 8];
        }
#pragma unroll
        for (int rep = 0; rep < 2; rep++) {
            int li = rep * 256 + t;
            int row = li >> 3, c16 = li & 7;
            *(uint4*)(smem + OVF + row * 144 + c16 * 16) = *(const uint4*)
                &g_vtf[(size_t)(b * HD + row) * T_ + k0 + c16 * 8];
        }
        __syncthreads();

#pragma unroll
        for (int kk = 0; kk < 4; kk++) {
            u32 af[2][4];
#pragma unroll
            for (int tq = 0; tq < 2; tq++) {
                u32 aoff = (u32)((qw * 32 + tq * 16 + (lane & 15)) * 144 +
                                 (kk * 16 + ((lane >> 4) << 3)) * 2);
                ldsm4(af[tq], sb + OEF + aoff);
            }
            u32 bf[2][4];
#pragma unroll
            for (int ng = 0; ng < 2; ng++) {
                u32 roff = (u32)((hw * 32 + ng * 16 + (lane & 7) +
                                  ((lane & 16) ? 8 : 0)) * 144 +
                                 (kk * 16 + ((lane & 8) ? 8 : 0)) * 2);
                ldsm4(bf[ng], sb + OVF + roff);
            }
#pragma unroll
            for (int tq = 0; tq < 2; tq++)
#pragma unroll
                for (int nt = 0; nt < 4; nt++)
                    mma16816h(acc[tq][nt], af[tq], bf[nt >> 1] + (nt & 1) * 2);
        }
    }

    int g = lane >> 2, tp = (lane & 3) << 1;
#pragma unroll
    for (int tq = 0; tq < 2; tq++) {
        int qrA = q0 + qw * 32 + tq * 16 + g;
#pragma unroll
        for (int nt = 0; nt < 4; nt++) {
            int h = hw * 32 + nt * 8 + tp;
            size_t base = (size_t)((s * B_ + b) * T_);
            *(float2*)&g_op[(base + qrA) * HD + h] =
                make_float2(acc[tq][nt][0], acc[tq][nt][1]);
            *(float2*)&g_op[(base + qrA + 8) * HD + h] =
                make_float2(acc[tq][nt][2], acc[tq][nt][3]);
        }
    }
}

// ---------------------------------------------------------------------------
// Pass 5: sum 4 split partials
// ---------------------------------------------------------------------------
__global__ void reduce_kernel(float* __restrict__ out) {
    const int N4 = B_ * T_ * HD / 4;
    int i = blockIdx.x * 256 + threadIdx.x;
    const float4* p = (const float4*)g_op;
    float4 a = p[i], b = p[i + N4], c = p[i + 2 * N4], d = p[i + 3 * N4];
    ((float4*)out)[i] = make_float4(a.x + b.x + c.x + d.x,
                                    a.y + b.y + c.y + d.y,
                                    a.z + b.z + c.z + d.z,
                                    a.w + b.w + c.w + d.w);
}

// ---------------------------------------------------------------------------
// inputs: x, Wk, Wq, Wv ; output fp32 [8,4096,64]
// ---------------------------------------------------------------------------
extern "C" void kernel_launch(void* const* d_in, const int* in_sizes, int n_in,
                              void* d_out, int out_size) {
    const float* x  = (const float*)d_in[0];
    const float* Wk = (const float*)d_in[1];
    const float* Wq = (const float*)d_in[2];
    const float* Wv = (const float*)d_in[3];
    float* out = (float*)d_out;

    cudaFuncSetAttribute(proj_mma_kernel,
        cudaFuncAttributeMaxDynamicSharedMemorySize, SMP_TOTAL);
    cudaFuncSetAttribute(score_mma_kernel,
        cudaFuncAttributeMaxDynamicSharedMemorySize, SMM_TOTAL);
    cudaFuncSetAttribute(out_mma_kernel,
        cudaFuncAttributeMaxDynamicSharedMemorySize, SMO_TOTAL);

    wsplit_kernel<<<768, 256>>>(Wq, Wk, Wv);
    proj_mma_kernel<<<dim3(3, 256), 256, SMP_TOTAL>>>(x);
    score_mma_kernel<<<dim3(528, 8), 256, SMM_TOTAL>>>();
    dinv_kernel<<<128, 256>>>();
    vprep_kernel<<<dim3(64, 8), 256>>>();
    out_mma_kernel<<<dim3(32, 4, 8), 256, SMO_TOTAL>>>();
    reduce_kernel<<<2048, 256>>>(out);
}

// round 14
// speedup vs baseline: 5.2735x; 1.1547x over previous
#include <cuda_runtime.h>
#include <cuda_fp16.h>
#include <cstdint>

#define B_ 8
#define T_ 4096
#define CE 1024
#define HD 64
#define SCALE 0.125f

typedef unsigned long long u64;
typedef unsigned int u32;

// ---- device scratch (allocation-free) ----
__device__ __align__(16) float g_v[B_ * T_ * HD];
__device__ __align__(16) __half g_wtf[3 * HD * CE];         // W^T fp16 [n][k]
__device__ __align__(16) __half g_qf[B_ * T_ * HD];         // q/8 fp16
__device__ __align__(16) __half g_kf[B_ * T_ * HD];         // k fp16
__device__ __align__(16) __half g_ef[(size_t)B_ * T_ * T_]; // E fp16
__device__ __align__(16) __half g_vtf[B_ * HD * T_];        // (V*dinv)^T fp16
__device__ __align__(16) float g_dp[B_ * 32 * T_];
__device__ __align__(16) float g_op[4 * B_ * T_ * HD];

__device__ __forceinline__ float fast_exp(float x) {
    float y = x * 1.4426950408889634f;
    float n = rintf(y);
    float f = y - n;
    float p = 1.3333558146e-3f;
    p = fmaf(p, f, 9.6181291076e-3f);
    p = fmaf(p, f, 5.5504108664e-2f);
    p = fmaf(p, f, 2.4022650696e-1f);
    p = fmaf(p, f, 6.9314718056e-1f);
    p = fmaf(p, f, 1.0f);
    return p * __int_as_float(((int)n + 127) << 23);
}

// ---- warp MMA helpers ----
__device__ __forceinline__ u32 s2u(const void* p) {
    u32 a;
    asm("{ .reg .u64 t; cvta.to.shared.u64 t, %1; cvt.u32.u64 %0, t; }"
        : "=r"(a) : "l"(p));
    return a;
}
__device__ __forceinline__ void ldsm4(u32* r, u32 addr) {
    asm volatile("ldmatrix.sync.aligned.m8n8.x4.shared.b16 {%0,%1,%2,%3}, [%4];"
                 : "=r"(r[0]), "=r"(r[1]), "=r"(r[2]), "=r"(r[3]) : "r"(addr));
}
__device__ __forceinline__ void mma16816h(float* d, const u32* a, const u32* b) {
    asm volatile(
        "mma.sync.aligned.m16n8k16.row.col.f32.f16.f16.f32 "
        "{%0,%1,%2,%3}, {%4,%5,%6,%7}, {%8,%9}, {%0,%1,%2,%3};"
        : "+f"(d[0]), "+f"(d[1]), "+f"(d[2]), "+f"(d[3])
        : "r"(a[0]), "r"(a[1]), "r"(a[2]), "r"(a[3]), "r"(b[0]), "r"(b[1]));
}

// ---------------------------------------------------------------------------
// Pass 0: transpose W into [n=192][k=1024] fp16
// ---------------------------------------------------------------------------
__global__ __launch_bounds__(256) void wsplit_kernel(
    const float* __restrict__ Wq, const float* __restrict__ Wk,
    const float* __restrict__ Wv) {
    int i = blockIdx.x * 256 + threadIdx.x;
    int n = i >> 10, k = i & 1023;
    const float* W = (n < 64) ? Wq : (n < 128) ? Wk : Wv;
    g_wtf[i] = __float2half_rn(W[k * HD + (n & 63)]);
}

// ---------------------------------------------------------------------------
// Pass 1: proj via f16 mma 2-pass (Xh·W + Xl·W), fused x fp32->fp16 hi/lo
// staging. grid (3 ntiles, 256 mtiles).
// Epilogue: q/8 -> fp16; k -> fp16; v -> fp32.
// ---------------------------------------------------------------------------
#define PXH 0
#define PXL (128 * 144)
#define PWF (2 * 128 * 144)
#define SMP_TOTAL (PWF + 64 * 144)   // 46080

__global__ __launch_bounds__(256) void proj_mma_kernel(const float* __restrict__ x) {
    extern __shared__ __align__(16) char smem[];
    int ntile = blockIdx.x, m0 = blockIdx.y << 7;
    int t = threadIdx.x, wid = t >> 5, lane = t & 31;
    int qw = wid >> 1, hw = wid & 1;
    u32 sb = s2u(smem);

    float acc[2][4][4] = {};
#pragma unroll 1
    for (int kc = 0; kc < 16; kc++) {
        int k0 = kc << 6;
        __syncthreads();
        // stage x chunk with inline fp32 -> fp16 hi/lo split
#pragma unroll
        for (int rep = 0; rep < 8; rep++) {
            int li = rep * 256 + t;          // 128 rows x 16 float4
            int row = li >> 4, c4 = li & 15;
            float4 v = *(const float4*)&x[(size_t)(m0 + row) * CE + k0 + c4 * 4];
            __half2 h01 = __floats2half2_rn(v.x, v.y);
            __half2 h23 = __floats2half2_rn(v.z, v.w);
            __half2 l01 = __floats2half2_rn(v.x - __half2float(h01.x),
                                            v.y - __half2float(h01.y));
            __half2 l23 = __floats2half2_rn(v.z - __half2float(h23.x),
                                            v.w - __half2float(h23.y));
            *(__half2*)(smem + PXH + row * 144 + c4 * 8) = h01;
            *(__half2*)(smem + PXH + row * 144 + c4 * 8 + 4) = h23;
            *(__half2*)(smem + PXL + row * 144 + c4 * 8) = l01;
            *(__half2*)(smem + PXL + row * 144 + c4 * 8 + 4) = l23;
        }
        // stage W^T chunk: 64 n-rows x 64 k fp16
        {
            int li = t;
            if (li < 512) {
                int row = li >> 3, c16 = li & 7;
                *(uint4*)(smem + PWF + row * 144 + c16 * 16) = *(const uint4*)
                    &g_wtf[(size_t)(ntile * 64 + row) * CE + k0 + c16 * 8];
            } else {
                int li2 = li - 256;   // covers rows 32..63
                int row = li2 >> 3, c16 = li2 & 7;
                if (row >= 32) {}     // (handled below)
            }
        }
        // simpler: 512 vec loads with 256 threads, 2 reps
#pragma unroll
        for (int rep = 0; rep < 2; rep++) {
            int li = rep * 256 + t;
            int row = li >> 3, c16 = li & 7;
            *(uint4*)(smem + PWF + row * 144 + c16 * 16) = *(const uint4*)
                &g_wtf[(size_t)(ntile * 64 + row) * CE + k0 + c16 * 8];
        }
        __syncthreads();

#pragma unroll
        for (int kk = 0; kk < 4; kk++) {
            u32 ah[2][4], al[2][4];
#pragma unroll
            for (int tq = 0; tq < 2; tq++) {
                u32 aoff = (u32)((qw * 32 + tq * 16 + (lane & 15)) * 144 +
                                 (kk * 16 + ((lane >> 4) << 3)) * 2);
                ldsm4(ah[tq], sb + PXH + aoff);
                ldsm4(al[tq], sb + PXL + aoff);
            }
            u32 bf[2][4];
#pragma unroll
            for (int ng = 0; ng < 2; ng++) {
                u32 roff = (u32)((hw * 32 + ng * 16 + (lane & 7) +
                                  ((lane & 16) ? 8 : 0)) * 144 +
                                 (kk * 16 + ((lane & 8) ? 8 : 0)) * 2);
                ldsm4(bf[ng], sb + PWF + roff);
            }
#pragma unroll
            for (int tq = 0; tq < 2; tq++)
#pragma unroll
                for (int nt = 0; nt < 4; nt++) {
                    const u32* bb = bf[nt >> 1] + (nt & 1) * 2;
                    mma16816h(acc[tq][nt], ah[tq], bb);
                    mma16816h(acc[tq][nt], al[tq], bb);
                }
        }
    }

    int g = lane >> 2, tp = (lane & 3) << 1;
#pragma unroll
    for (int tq = 0; tq < 2; tq++) {
        int mA = m0 + qw * 32 + tq * 16 + g;
        int mB = mA + 8;
#pragma unroll
        for (int nt = 0; nt < 4; nt++) {
            int h = hw * 32 + nt * 8 + tp;
            float v0 = acc[tq][nt][0], v1 = acc[tq][nt][1];
            float v2 = acc[tq][nt][2], v3 = acc[tq][nt][3];
            if (ntile == 2) {
                *(float2*)&g_v[(size_t)mA * HD + h] = make_float2(v0, v1);
                *(float2*)&g_v[(size_t)mB * HD + h] = make_float2(v2, v3);
            } else {
                __half* dst = (ntile == 0) ? g_qf : g_kf;
                if (ntile == 0) {
                    v0 *= SCALE; v1 *= SCALE; v2 *= SCALE; v3 *= SCALE;
                }
                *(__half2*)&dst[(size_t)mA * HD + h] = __floats2half2_rn(v0, v1);
                *(__half2*)&dst[(size_t)mB * HD + h] = __floats2half2_rn(v2, v3);
            }
        }
    }
}

// ---------------------------------------------------------------------------
// Pass 2: score via f16 mma single pass (Qf·Kf). E -> one fp16 plane;
// d sums use fp16-rounded E (consistent-d). Coalesced smem-staged E stores.
// ---------------------------------------------------------------------------
#define OQF 0
#define OKF (128 * 144)
#define OBUF (2 * 128 * 144)
#define SMM_TOTAL (OBUF + 4 * 128 * 4)   // 38912
#define EPITCH 272

__global__ __launch_bounds__(256) void score_mma_kernel() {
    extern __shared__ __align__(16) char smem[];
    int b = blockIdx.y;
    int ti = blockIdx.x;
    int qt = (int)((sqrtf(8.f * (float)ti + 1.f) - 1.f) * 0.5f);
    while ((qt + 1) * (qt + 2) / 2 <= ti) qt++;
    while (qt * (qt + 1) / 2 > ti) qt--;
    int kt = ti - qt * (qt + 1) / 2;
    int q0 = qt << 7, k0 = kt << 7;
    int t = threadIdx.x, wid = t >> 5, lane = t & 31;

    {   // stage Qf + Kf: 256 rows x 8 uint4 = 256 threads x 8
        int a = t >> 7, row = t & 127;
        const __half* src = (a == 0) ? g_qf + (size_t)(b * T_ + q0) * HD
                                     : g_kf + (size_t)(b * T_ + k0) * HD;
        const uint4* s = (const uint4*)(src + (size_t)row * HD);
        uint4* d = (uint4*)(smem + (a == 0 ? OQF : OKF) + row * 144);
#pragma unroll
        for (int c = 0; c < 8; c++) d[c] = s[c];
    }
    __syncthreads();

    int qw = wid >> 1, kw = wid & 1;
    u32 sb = s2u(smem);
    float acc[2][8][4] = {};

#pragma unroll
    for (int kk = 0; kk < 4; kk++) {
        u32 af[2][4];
#pragma unroll
        for (int tq = 0; tq < 2; tq++) {
            u32 aoff = (u32)((qw * 32 + tq * 16 + (lane & 15)) * 144 +
                             (kk * 16 + ((lane >> 4) << 3)) * 2);
            ldsm4(af[tq], sb + OQF + aoff);
        }
        u32 bf[4][4];
#pragma unroll
        for (int ng = 0; ng < 4; ng++) {
            u32 roff = (u32)((kw * 64 + ng * 16 + (lane & 7) +
                              ((lane & 16) ? 8 : 0)) * 144 +
                             (kk * 16 + ((lane & 8) ? 8 : 0)) * 2);
            ldsm4(bf[ng], sb + OKF + roff);
        }
#pragma unroll
        for (int tq = 0; tq < 2; tq++)
#pragma unroll
            for (int ng = 0; ng < 4; ng++)
#pragma unroll
                for (int hf = 0; hf < 2; hf++)
                    mma16816h(acc[tq][ng * 2 + hf], af[tq], bf[ng] + hf * 2);
    }

    __syncthreads();   // staging reads done; reuse smem for E tile

    char* efs = smem;                    // 128 x EPITCH (fp16 plane)
    int g = lane >> 2, tp = (lane & 3) << 1;
    bool diag = (kt == qt);
    float cs[8][2] = {};
#pragma unroll
    for (int tq = 0; tq < 2; tq++) {
        int rA = qw * 32 + tq * 16 + g;
        int rB = rA + 8;
#pragma unroll
        for (int nt = 0; nt < 8; nt++) {
            int col = kw * 64 + nt * 8 + tp;
            float e0 = fast_exp(acc[tq][nt][0]);
            float e1 = fast_exp(acc[tq][nt][1]);
            float e2 = fast_exp(acc[tq][nt][2]);
            float e3 = fast_exp(acc[tq][nt][3]);
            if (diag) {
                if (q0 + rA < k0 + col) e0 = 0.f;
                if (q0 + rA < k0 + col + 1) e1 = 0.f;
                if (q0 + rB < k0 + col) e2 = 0.f;
                if (q0 + rB < k0 + col + 1) e3 = 0.f;
            }
            __half2 hA = __floats2half2_rn(e0, e1);
            __half2 hB = __floats2half2_rn(e2, e3);
            *(__half2*)(efs + rA * EPITCH + col * 2) = hA;
            *(__half2*)(efs + rB * EPITCH + col * 2) = hB;
            cs[nt][0] += __half2float(hA.x) + __half2float(hB.x);
            cs[nt][1] += __half2float(hA.y) + __half2float(hB.y);
        }
    }
#pragma unroll
    for (int nt = 0; nt < 8; nt++)
#pragma unroll
        for (int j = 0; j < 2; j++) {
            float v = cs[nt][j];
            v += __shfl_xor_sync(0xffffffffu, v, 4);
            v += __shfl_xor_sync(0xffffffffu, v, 8);
            v += __shfl_xor_sync(0xffffffffu, v, 16);
            cs[nt][j] = v;
        }
    float* buf = (float*)(smem + OBUF);
    if (lane < 4) {
#pragma unroll
        for (int nt = 0; nt < 8; nt++) {
            buf[qw * 128 + kw * 64 + nt * 8 + ((lane & 3) << 1) + 0] = cs[nt][0];
            buf[qw * 128 + kw * 64 + nt * 8 + ((lane & 3) << 1) + 1] = cs[nt][1];
        }
    }
    __syncthreads();

    size_t gbase = (size_t)b * T_ * T_ + (size_t)q0 * T_ + k0;
#pragma unroll
    for (int rep = 0; rep < 8; rep++) {
        int li = rep * 256 + t;
        int row = li >> 4, c16 = li & 15;
        *(uint4*)&g_ef[gbase + (size_t)row * T_ + c16 * 8] =
            *(const uint4*)(efs + row * EPITCH + c16 * 16);
    }
    if (t < 128) {
        float s = buf[t] + buf[128 + t] + buf[256 + t] + buf[384 + t];
        g_dp[(size_t)((b << 5) + qt) * T_ + k0 + t] = s;
    }
}

// ---------------------------------------------------------------------------
// Pass 3: vprep with FUSED dinv: Vt = (V/d)^T fp16, [b][h][k]
// ---------------------------------------------------------------------------
__global__ __launch_bounds__(256) void vprep_kernel() {
    __shared__ __align__(16) float Vt[64][68];
    __shared__ float dinv_s[64];
    int k0 = blockIdx.x << 6, b = blockIdx.y;
    int t = threadIdx.x;

    if (t < 64) {   // fused dinv for this block's 64 columns
        int k = k0 + t;
        float s = 0.f;
        for (int qt = (k >> 7); qt < 32; qt++)
            s += g_dp[(size_t)((b << 5) + qt) * T_ + k];
        dinv_s[t] = 1.0f / s;
    }
    __syncthreads();
    {
        int k = t >> 2, hseg = (t & 3) << 4;
        float dinv = dinv_s[k];
        const float* src = &g_v[(size_t)(b * T_ + k0 + k) * HD + hseg];
#pragma unroll
        for (int u = 0; u < 4; u++) {
            float4 v = *(const float4*)&src[u * 4];
            Vt[hseg + u * 4 + 0][k] = v.x * dinv;
            Vt[hseg + u * 4 + 1][k] = v.y * dinv;
            Vt[hseg + u * 4 + 2][k] = v.z * dinv;
            Vt[hseg + u * 4 + 3][k] = v.w * dinv;
        }
    }
    __syncthreads();
    {
        int h = t >> 2, kseg = (t & 3) << 4;
        size_t dst = (size_t)(b * HD + h) * T_ + k0 + kseg;
#pragma unroll
        for (int u = 0; u < 4; u++) {
            __half2 p0 = __floats2half2_rn(Vt[h][kseg + u * 4 + 0],
                                           Vt[h][kseg + u * 4 + 1]);
            __half2 p1 = __floats2half2_rn(Vt[h][kseg + u * 4 + 2],
                                           Vt[h][kseg + u * 4 + 3]);
            *(__half2*)&g_vtf[dst + u * 4 + 0] = p0;
            *(__half2*)&g_vtf[dst + u * 4 + 2] = p1;
        }
    }
}

// ---------------------------------------------------------------------------
// Pass 4: out via f16 mma single pass: O = Ef @ Vtf
// ---------------------------------------------------------------------------
#define OEF 0
#define OVF (128 * 144)
#define SMO_TOTAL (OVF + 64 * 144)   // 27648

__global__ __launch_bounds__(256) void out_mma_kernel() {
    extern __shared__ __align__(16) char smem[];
    int qt = blockIdx.x, s = blockIdx.y, b = blockIdx.z;
    int q0 = qt << 7;
    int nch = 2 * qt + 2;
    int lo = (s * nch) >> 2, hi = ((s + 1) * nch) >> 2;
    int t = threadIdx.x, wid = t >> 5, lane = t & 31;
    int qw = wid >> 1, hw = wid & 1;
    u32 sb = s2u(smem);

    float acc[2][4][4] = {};
    for (int c = lo; c < hi; c++) {
        int k0 = c << 6;
        __syncthreads();
#pragma unroll
        for (int rep = 0; rep < 4; rep++) {
            int li = rep * 256 + t;
            int row = li >> 3, c16 = li & 7;
            *(uint4*)(smem + OEF + row * 144 + c16 * 16) = *(const uint4*)
                &g_ef[((size_t)(b * T_ + q0 + row)) * T_ + k0 + c16 * 8];
        }
#pragma unroll
        for (int rep = 0; rep < 2; rep++) {
            int li = rep * 256 + t;
            int row = li >> 3, c16 = li & 7;
            *(uint4*)(smem + OVF + row * 144 + c16 * 16) = *(const uint4*)
                &g_vtf[(size_t)(b * HD + row) * T_ + k0 + c16 * 8];
        }
        __syncthreads();

#pragma unroll
        for (int kk = 0; kk < 4; kk++) {
            u32 af[2][4];
#pragma unroll
            for (int tq = 0; tq < 2; tq++) {
                u32 aoff = (u32)((qw * 32 + tq * 16 + (lane & 15)) * 144 +
                                 (kk * 16 + ((lane >> 4) << 3)) * 2);
                ldsm4(af[tq], sb + OEF + aoff);
            }
            u32 bf[2][4];
#pragma unroll
            for (int ng = 0; ng < 2; ng++) {
                u32 roff = (u32)((hw * 32 + ng * 16 + (lane & 7) +
                                  ((lane & 16) ? 8 : 0)) * 144 +
                                 (kk * 16 + ((lane & 8) ? 8 : 0)) * 2);
                ldsm4(bf[ng], sb + OVF + roff);
            }
#pragma unroll
            for (int tq = 0; tq < 2; tq++)
#pragma unroll
                for (int nt = 0; nt < 4; nt++)
                    mma16816h(acc[tq][nt], af[tq], bf[nt >> 1] + (nt & 1) * 2);
        }
    }

    int g = lane >> 2, tp = (lane & 3) << 1;
#pragma unroll
    for (int tq = 0; tq < 2; tq++) {
        int qrA = q0 + qw * 32 + tq * 16 + g;
#pragma unroll
        for (int nt = 0; nt < 4; nt++) {
            int h = hw * 32 + nt * 8 + tp;
            size_t base = (size_t)((s * B_ + b) * T_);
            *(float2*)&g_op[(base + qrA) * HD + h] =
                make_float2(acc[tq][nt][0], acc[tq][nt][1]);
            *(float2*)&g_op[(base + qrA + 8) * HD + h] =
                make_float2(acc[tq][nt][2], acc[tq][nt][3]);
        }
    }
}

// ---------------------------------------------------------------------------
// Pass 5: sum 4 split partials
// ---------------------------------------------------------------------------
__global__ void reduce_kernel(float* __restrict__ out) {
    const int N4 = B_ * T_ * HD / 4;
    int i = blockIdx.x * 256 + threadIdx.x;
    const float4* p = (const float4*)g_op;
    float4 a = p[i], b = p[i + N4], c = p[i + 2 * N4], d = p[i + 3 * N4];
    ((float4*)out)[i] = make_float4(a.x + b.x + c.x + d.x,
                                    a.y + b.y + c.y + d.y,
                                    a.z + b.z + c.z + d.z,
                                    a.w + b.w + c.w + d.w);
}

// ---------------------------------------------------------------------------
// inputs: x, Wk, Wq, Wv ; output fp32 [8,4096,64]
// ---------------------------------------------------------------------------
extern "C" void kernel_launch(void* const* d_in, const int* in_sizes, int n_in,
                              void* d_out, int out_size) {
    const float* x  = (const float*)d_in[0];
    const float* Wk = (const float*)d_in[1];
    const float* Wq = (const float*)d_in[2];
    const float* Wv = (const float*)d_in[3];
    float* out = (float*)d_out;

    cudaFuncSetAttribute(proj_mma_kernel,
        cudaFuncAttributeMaxDynamicSharedMemorySize, SMP_TOTAL);
    cudaFuncSetAttribute(score_mma_kernel,
        cudaFuncAttributeMaxDynamicSharedMemorySize, SMM_TOTAL);
    cudaFuncSetAttribute(out_mma_kernel,
        cudaFuncAttributeMaxDynamicSharedMemorySize, SMO_TOTAL);

    wsplit_kernel<<<768, 256>>>(Wq, Wk, Wv);
    proj_mma_kernel<<<dim3(3, 256), 256, SMP_TOTAL>>>(x);
    score_mma_kernel<<<dim3(528, 8), 256, SMM_TOTAL>>>();
    vprep_kernel<<<dim3(64, 8), 256>>>();
    out_mma_kernel<<<dim3(32, 4, 8), 256, SMO_TOTAL>>>();
    reduce_kernel<<<2048, 256>>>(out);
}